// round 1
// baseline (speedup 1.0000x reference)
#include <cuda_runtime.h>
#include <math.h>

#define NN 50000
#define EE 1600000
#define HH 128
#define BB 64
#define TT 4
#define GG 10
#define TAB 4096

// scratch (static device globals — no runtime allocation)
static __device__ float g_table[2 * TAB * HH];   // W*C lookup per interaction
static __device__ float g_t[EE];                 // interpolation coordinate per edge
static __device__ float g_h[NN * HH];
static __device__ float g_xj[NN * HH];
static __device__ float g_agg[NN * HH];
static __device__ float g_pooled[BB * HH];

__device__ __forceinline__ float sspf(float x) {
    // softplus(x) - log(2), numerically stable
    float ax = fabsf(x);
    return fmaxf(x, 0.0f) + log1pf(__expf(-ax)) - 0.6931471805599453f;
}

// ---------------------------------------------------------------------------
// Build filter table: table[inter][row][h] = (ssp(rbf(d)@W1+b1)@W2+b2)[h] * C(d)
// grid = (TAB, 2), block = 128
// ---------------------------------------------------------------------------
__global__ void build_table_kernel(const float* __restrict__ w1, const float* __restrict__ b1,
                                   const float* __restrict__ w2, const float* __restrict__ b2) {
    int row = blockIdx.x;
    int inter = blockIdx.y;
    int tid = threadIdx.x;
    const float D_MAX = 8.6603f;   // slightly above 5*sqrt(3)
    float d = row * (D_MAX / (float)(TAB - 1));

    __shared__ float hid[HH];
    const float* w1i = w1 + (size_t)inter * GG * HH;
    const float* b1i = b1 + (size_t)inter * HH;
    const float* w2i = w2 + (size_t)inter * HH * HH;
    const float* b2i = b2 + (size_t)inter * HH;

    const float step = 10.0f / 9.0f;               // linspace(0,10,10) spacing
    const float coeff = -0.5f / (step * step);

    float acc = b1i[tid];
    #pragma unroll
    for (int g = 0; g < GG; g++) {
        float diff = d - (float)g * step;
        float r = expf(coeff * diff * diff);
        acc += r * w1i[g * HH + tid];
    }
    hid[tid] = sspf(acc);
    __syncthreads();

    float acc2 = b2i[tid];
    for (int k = 0; k < HH; k++)
        acc2 = fmaf(hid[k], w2i[k * HH + tid], acc2);

    float C = 0.5f * (cosf(d * 3.14159265358979f / 10.0f) + 1.0f);
    g_table[((size_t)inter * TAB + row) * HH + tid] = acc2 * C;
}

// ---------------------------------------------------------------------------
// Per-edge distance -> table coordinate
// ---------------------------------------------------------------------------
__global__ void edge_prep_kernel(const int* __restrict__ ei, const float* __restrict__ pos) {
    int e = blockIdx.x * blockDim.x + threadIdx.x;
    if (e >= EE) return;
    int s = ei[e];
    int d = ei[EE + e];
    float dx = pos[s * 3 + 0] - pos[d * 3 + 0];
    float dy = pos[s * 3 + 1] - pos[d * 3 + 1];
    float dz = pos[s * 3 + 2] - pos[d * 3 + 2];
    float dist = sqrtf(dx * dx + dy * dy + dz * dz);
    const float INV_STEP = (float)(TAB - 1) / 8.6603f;
    g_t[e] = dist * INV_STEP;
}

// ---------------------------------------------------------------------------
// Embedding gather: h[n] = emb[z[n]]
// ---------------------------------------------------------------------------
__global__ void embed_kernel(const int* __restrict__ z, const float* __restrict__ emb) {
    int idx = blockIdx.x * blockDim.x + threadIdx.x;  // over NN * 32 float4s
    if (idx >= NN * (HH / 4)) return;
    int n = idx >> 5;
    int c = idx & 31;
    ((float4*)g_h)[idx] = ((const float4*)emb)[(size_t)z[n] * (HH / 4) + c];
}

// ---------------------------------------------------------------------------
// Zero fill (n4 = count in float4 units)
// ---------------------------------------------------------------------------
__global__ void zero_kernel(float* __restrict__ p, int n4) {
    int i = blockIdx.x * blockDim.x + threadIdx.x;
    if (i < n4) ((float4*)p)[i] = make_float4(0.f, 0.f, 0.f, 0.f);
}

// ---------------------------------------------------------------------------
// Edge convolution: agg[dst] += xj[src] * lerp(table[inter], t)
// One warp per edge; lane l handles cols [4l, 4l+4)
// ---------------------------------------------------------------------------
__global__ void __launch_bounds__(256) edge_conv_kernel(const int* __restrict__ ei, int inter) {
    int warp = blockIdx.x * (blockDim.x >> 5) + (threadIdx.x >> 5);
    if (warp >= EE) return;
    int lane = threadIdx.x & 31;

    int s = __ldg(ei + warp);
    int d = __ldg(ei + EE + warp);
    float t = g_t[warp];
    int i0 = (int)t;
    i0 = min(i0, TAB - 2);
    float f = t - (float)i0;

    const float4* xr = (const float4*)(g_xj + (size_t)s * HH);
    float4 x = xr[lane];
    const float4* tr = (const float4*)(g_table + ((size_t)inter * TAB + i0) * HH);
    float4 w0 = tr[lane];
    float4 w1 = tr[lane + 32];   // next table row (contiguous)

    float4 v;
    v.x = x.x * fmaf(w1.x - w0.x, f, w0.x);
    v.y = x.y * fmaf(w1.y - w0.y, f, w0.y);
    v.z = x.z * fmaf(w1.z - w0.z, f, w0.z);
    v.w = x.w * fmaf(w1.w - w0.w, f, w0.w);

    float* ap = g_agg + (size_t)d * HH + lane * 4;
    asm volatile("red.global.add.v4.f32 [%0], {%1,%2,%3,%4};"
                 :: "l"(ap), "f"(v.x), "f"(v.y), "f"(v.z), "f"(v.w) : "memory");
}

// ---------------------------------------------------------------------------
// Register-tiled fp32 GEMM: out[N,NCOL] = epi(A[N,KDIM] @ W[KDIM,NCOL])
// block: (NCOL/8)*16 threads; tile 64 rows x NCOL cols; thread tile 4x8
// epilogue flags: BIAS, ACT(ssp), RESID(out += acc), POOL(atomic to pooled)
// ---------------------------------------------------------------------------
template <int KDIM, int NCOL, bool BIAS, bool ACT, bool RESID, bool POOL>
__global__ void __launch_bounds__((NCOL / 8) * 16)
gemm_kernel(const float* __restrict__ A, const float* __restrict__ W,
            const float* __restrict__ bias, float* __restrict__ out,
            const int* __restrict__ batch) {
    constexpr int KC = 32;
    constexpr int ROWS = 64;
    constexpr int TX = NCOL / 8;
    constexpr int NTHR = TX * 16;

    __shared__ float As[KC][ROWS + 4];   // transposed A tile, padded (68 floats stride)
    __shared__ float Ws[KC][NCOL];

    int tid = threadIdx.x;
    int tx = tid % TX;
    int ty = tid / TX;
    int row0 = blockIdx.x * ROWS;
    int c0 = tx * 8;
    int r0 = ty * 4;

    float acc[4][8];
    #pragma unroll
    for (int i = 0; i < 4; i++)
        #pragma unroll
        for (int j = 0; j < 8; j++) acc[i][j] = 0.f;

    for (int k0 = 0; k0 < KDIM; k0 += KC) {
        // stage A (transpose into As[k][row])
        #pragma unroll
        for (int i = tid; i < ROWS * (KC / 4); i += NTHR) {
            int row = i / (KC / 4);
            int kq = i % (KC / 4);
            float4 v = make_float4(0.f, 0.f, 0.f, 0.f);
            if (row0 + row < NN)
                v = *(const float4*)(A + (size_t)(row0 + row) * KDIM + k0 + kq * 4);
            As[kq * 4 + 0][row] = v.x;
            As[kq * 4 + 1][row] = v.y;
            As[kq * 4 + 2][row] = v.z;
            As[kq * 4 + 3][row] = v.w;
        }
        // stage W (straight copy)
        #pragma unroll
        for (int i = tid; i < KC * (NCOL / 4); i += NTHR)
            ((float4*)&Ws[0][0])[i] = ((const float4*)(W + (size_t)k0 * NCOL))[i];
        __syncthreads();

        #pragma unroll
        for (int kk = 0; kk < KC; kk++) {
            float4 a  = *(const float4*)&As[kk][r0];
            float4 b0 = *(const float4*)&Ws[kk][c0];
            float4 b1 = *(const float4*)&Ws[kk][c0 + 4];
            float av[4] = {a.x, a.y, a.z, a.w};
            float bv[8] = {b0.x, b0.y, b0.z, b0.w, b1.x, b1.y, b1.z, b1.w};
            #pragma unroll
            for (int i = 0; i < 4; i++)
                #pragma unroll
                for (int j = 0; j < 8; j++)
                    acc[i][j] = fmaf(av[i], bv[j], acc[i][j]);
        }
        __syncthreads();
    }

    // epilogue
    #pragma unroll
    for (int i = 0; i < 4; i++) {
        int row = row0 + r0 + i;
        if (row >= NN) continue;
        float vals[8];
        #pragma unroll
        for (int j = 0; j < 8; j++) {
            float v = acc[i][j];
            if (BIAS) v += bias[c0 + j];
            if (ACT) v = sspf(v);
            vals[j] = v;
        }
        if (POOL) {
            int b = batch[row];
            float* p = g_pooled + (size_t)b * NCOL + c0;
            asm volatile("red.global.add.v4.f32 [%0], {%1,%2,%3,%4};"
                         :: "l"(p), "f"(vals[0]), "f"(vals[1]), "f"(vals[2]), "f"(vals[3]) : "memory");
            asm volatile("red.global.add.v4.f32 [%0], {%1,%2,%3,%4};"
                         :: "l"(p + 4), "f"(vals[4]), "f"(vals[5]), "f"(vals[6]), "f"(vals[7]) : "memory");
        } else {
            float* o = out + (size_t)row * NCOL + c0;
            if (RESID) {
                float4 h0 = *(float4*)o;
                float4 h1 = *(float4*)(o + 4);
                vals[0] += h0.x; vals[1] += h0.y; vals[2] += h0.z; vals[3] += h0.w;
                vals[4] += h1.x; vals[5] += h1.y; vals[6] += h1.z; vals[7] += h1.w;
            }
            *(float4*)o       = make_float4(vals[0], vals[1], vals[2], vals[3]);
            *(float4*)(o + 4) = make_float4(vals[4], vals[5], vals[6], vals[7]);
        }
    }
}

// ---------------------------------------------------------------------------
// Final tiny GEMM: out[B,T] = pooled[B,H] @ pred_w[H,T] + pred_b
// single block, 256 threads (64 graphs x 4 targets)
// ---------------------------------------------------------------------------
__global__ void final_kernel(const float* __restrict__ pw, const float* __restrict__ pb,
                             float* __restrict__ out) {
    int tid = threadIdx.x;
    int b = tid >> 2;
    int t = tid & 3;
    float acc = pb[t];
    for (int k = 0; k < HH; k++)
        acc = fmaf(g_pooled[b * HH + k], pw[k * TT + t], acc);
    out[b * TT + t] = acc;
}

// ---------------------------------------------------------------------------
extern "C" void kernel_launch(void* const* d_in, const int* in_sizes, int n_in,
                              void* d_out, int out_size) {
    const int*   z       = (const int*)d_in[0];
    const float* pos     = (const float*)d_in[1];
    const int*   batch   = (const int*)d_in[2];
    const int*   ei      = (const int*)d_in[3];
    const float* emb     = (const float*)d_in[4];
    const float* mlp_w1  = (const float*)d_in[5];
    const float* mlp_b1  = (const float*)d_in[6];
    const float* mlp_w2  = (const float*)d_in[7];
    const float* mlp_b2  = (const float*)d_in[8];
    const float* lin1_w  = (const float*)d_in[9];
    const float* lin2_w  = (const float*)d_in[10];
    const float* lin2_b  = (const float*)d_in[11];
    const float* lin_w   = (const float*)d_in[12];
    const float* lin_b   = (const float*)d_in[13];
    const float* out1_w  = (const float*)d_in[14];
    const float* out1_b  = (const float*)d_in[15];
    const float* out2_w  = (const float*)d_in[16];
    const float* out2_b  = (const float*)d_in[17];
    const float* pred_w  = (const float*)d_in[18];
    const float* pred_b  = (const float*)d_in[19];
    float* out = (float*)d_out;

    float *p_h, *p_xj, *p_agg, *p_pooled;
    cudaGetSymbolAddress((void**)&p_h, g_h);
    cudaGetSymbolAddress((void**)&p_xj, g_xj);
    cudaGetSymbolAddress((void**)&p_agg, g_agg);
    cudaGetSymbolAddress((void**)&p_pooled, g_pooled);

    dim3 tb(TAB, 2);
    build_table_kernel<<<tb, HH>>>(mlp_w1, mlp_b1, mlp_w2, mlp_b2);
    edge_prep_kernel<<<(EE + 255) / 256, 256>>>(ei, pos);
    embed_kernel<<<(NN * 32 + 255) / 256, 256>>>(z, emb);

    int gblocks = (NN + 63) / 64;
    for (int i = 0; i < 2; i++) {
        zero_kernel<<<(NN * 32 + 255) / 256, 256>>>(p_agg, NN * 32);
        // xj = h @ lin1
        gemm_kernel<128, 128, false, false, false, false><<<gblocks, 256>>>(
            p_h, lin1_w + (size_t)i * HH * HH, nullptr, p_xj, nullptr);
        // agg[dst] += xj[src] * W(d)
        edge_conv_kernel<<<(EE + 7) / 8, 256>>>(ei, i);
        // tmp = ssp(agg @ lin2 + b2)   (reuse g_xj)
        gemm_kernel<128, 128, true, true, false, false><<<gblocks, 256>>>(
            p_agg, lin2_w + (size_t)i * HH * HH, lin2_b + (size_t)i * HH, p_xj, nullptr);
        // h += tmp @ lin + b
        gemm_kernel<128, 128, true, false, true, false><<<gblocks, 256>>>(
            p_xj, lin_w + (size_t)i * HH * HH, lin_b + (size_t)i * HH, p_h, nullptr);
    }

    zero_kernel<<<(BB * 32 + 255) / 256, 256>>>(p_pooled, BB * 32);
    // t1 = ssp(h @ out1 + b1)  [N,64]   (reuse g_agg)
    gemm_kernel<128, 64, true, true, false, false><<<gblocks, 128>>>(
        p_h, out1_w, out1_b, p_agg, nullptr);
    // pooled[batch[n]] += t1 @ out2 + b2  (atomic epilogue, no [N,H] store)
    gemm_kernel<64, 128, true, false, false, true><<<gblocks, 256>>>(
        p_agg, out2_w, out2_b, nullptr, batch);
    // out = pooled @ pred_w + pred_b
    final_kernel<<<1, 256>>>(pred_w, pred_b, out);
}

// round 2
// speedup vs baseline: 1.4108x; 1.4108x over previous
#include <cuda_runtime.h>
#include <cuda_bf16.h>
#include <math.h>

#define NN 50000
#define EE 1600000
#define HH 128
#define BB 64
#define TT 4
#define GG 10
#define TAB 384
#define D_MAX 8.6603f

// scratch (static device globals — no runtime allocation)
static __device__ float g_table[2 * TAB * HH];        // W*C lookup per interaction
static __device__ float g_t[EE];                      // interpolation coordinate per edge
static __device__ float g_h[NN * HH];
static __device__ float g_tmp[NN * HH];
static __device__ __nv_bfloat16 g_xjb[NN * HH];       // bf16 gather operand
static __device__ float g_agg[NN * HH];
static __device__ float g_pooled[BB * HH];

__device__ __forceinline__ float sspf(float x) {
    float ax = fabsf(x);
    return fmaxf(x, 0.0f) + log1pf(__expf(-ax)) - 0.6931471805599453f;
}

// packed-f32x2 helpers (Blackwell dual-FP32 pipe; only reachable via PTX)
__device__ __forceinline__ unsigned long long pack2(float lo, float hi) {
    unsigned long long r;
    asm("mov.b64 %0, {%1, %2};" : "=l"(r) : "f"(lo), "f"(hi));
    return r;
}
__device__ __forceinline__ void unpack2(unsigned long long v, float& lo, float& hi) {
    asm("mov.b64 {%0, %1}, %2;" : "=f"(lo), "=f"(hi) : "l"(v));
}
__device__ __forceinline__ void ffma2(unsigned long long& d, unsigned long long a,
                                      unsigned long long b) {
    asm("fma.rn.f32x2 %0, %1, %2, %0;" : "+l"(d) : "l"(a), "l"(b));
}

// ---------------------------------------------------------------------------
// Build filter table: table[inter][row][h] = (ssp(rbf(d)@W1+b1)@W2+b2)[h] * C(d)
// grid = (TAB, 2), block = 128
// ---------------------------------------------------------------------------
__global__ void build_table_kernel(const float* __restrict__ w1, const float* __restrict__ b1,
                                   const float* __restrict__ w2, const float* __restrict__ b2) {
    int row = blockIdx.x;
    int inter = blockIdx.y;
    int tid = threadIdx.x;
    float d = row * (D_MAX / (float)(TAB - 1));

    __shared__ float hid[HH];
    const float* w1i = w1 + (size_t)inter * GG * HH;
    const float* b1i = b1 + (size_t)inter * HH;
    const float* w2i = w2 + (size_t)inter * HH * HH;
    const float* b2i = b2 + (size_t)inter * HH;

    const float step = 10.0f / 9.0f;
    const float coeff = -0.5f / (step * step);

    float acc = b1i[tid];
    #pragma unroll
    for (int g = 0; g < GG; g++) {
        float diff = d - (float)g * step;
        float r = expf(coeff * diff * diff);
        acc += r * w1i[g * HH + tid];
    }
    hid[tid] = sspf(acc);
    __syncthreads();

    float acc2 = b2i[tid];
    for (int k = 0; k < HH; k++)
        acc2 = fmaf(hid[k], w2i[k * HH + tid], acc2);

    float C = 0.5f * (cosf(d * 3.14159265358979f / 10.0f) + 1.0f);
    g_table[((size_t)inter * TAB + row) * HH + tid] = acc2 * C;
}

// ---------------------------------------------------------------------------
// Per-edge distance -> table coordinate
// ---------------------------------------------------------------------------
__global__ void edge_prep_kernel(const int* __restrict__ ei, const float* __restrict__ pos) {
    int e = blockIdx.x * blockDim.x + threadIdx.x;
    if (e >= EE) return;
    int s = ei[e];
    int d = ei[EE + e];
    float dx = pos[s * 3 + 0] - pos[d * 3 + 0];
    float dy = pos[s * 3 + 1] - pos[d * 3 + 1];
    float dz = pos[s * 3 + 2] - pos[d * 3 + 2];
    float dist = sqrtf(dx * dx + dy * dy + dz * dz);
    const float INV_STEP = (float)(TAB - 1) / D_MAX;
    g_t[e] = dist * INV_STEP;
}

// ---------------------------------------------------------------------------
// Embedding gather: h[n] = emb[z[n]]
// ---------------------------------------------------------------------------
__global__ void embed_kernel(const int* __restrict__ z, const float* __restrict__ emb) {
    int idx = blockIdx.x * blockDim.x + threadIdx.x;
    if (idx >= NN * (HH / 4)) return;
    int n = idx >> 5;
    int c = idx & 31;
    ((float4*)g_h)[idx] = ((const float4*)emb)[(size_t)z[n] * (HH / 4) + c];
}

__global__ void zero_kernel(float* __restrict__ p, int n4) {
    int i = blockIdx.x * blockDim.x + threadIdx.x;
    if (i < n4) ((float4*)p)[i] = make_float4(0.f, 0.f, 0.f, 0.f);
}

// ---------------------------------------------------------------------------
// Edge convolution, persistent, smem-resident table:
//   agg[dst] += bf16(xj[src]) * lerp(table[inter], t)
// 1 block/SM, 1024 threads, 196KB dynamic smem. One warp per edge;
// indices/t are loaded coalesced 32-at-a-time and shfl-broadcast.
// ---------------------------------------------------------------------------
__global__ void __launch_bounds__(1024) edge_conv_kernel(const int* __restrict__ ei, int inter) {
    extern __shared__ float tab[];
    const float4* src_tab = (const float4*)(g_table + (size_t)inter * TAB * HH);
    for (int i = threadIdx.x; i < TAB * HH / 4; i += 1024)
        ((float4*)tab)[i] = src_tab[i];
    __syncthreads();

    int lane = threadIdx.x & 31;
    int gwarp = blockIdx.x * 32 + (threadIdx.x >> 5);
    int nwarp = gridDim.x * 32;

    for (int base = gwarp * 32; base < EE; base += nwarp * 32) {
        int e = base + lane;
        int s_l = __ldg(ei + e);
        int d_l = __ldg(ei + EE + e);
        float t_l = __ldg(&g_t[e]);
        #pragma unroll 4
        for (int j = 0; j < 32; j++) {
            int s   = __shfl_sync(0xffffffffu, s_l, j);
            int d   = __shfl_sync(0xffffffffu, d_l, j);
            float t = __shfl_sync(0xffffffffu, t_l, j);
            int i0 = min((int)t, TAB - 2);
            float f = t - (float)i0;

            uint2 xw = *(const uint2*)(g_xjb + (size_t)s * HH + lane * 4);
            __nv_bfloat162 x01 = *reinterpret_cast<__nv_bfloat162*>(&xw.x);
            __nv_bfloat162 x23 = *reinterpret_cast<__nv_bfloat162*>(&xw.y);

            const float* t0 = tab + i0 * HH + lane * 4;
            float4 w0 = *(const float4*)t0;
            float4 w1 = *(const float4*)(t0 + HH);

            float4 v;
            v.x = __bfloat162float(x01.x) * fmaf(w1.x - w0.x, f, w0.x);
            v.y = __bfloat162float(x01.y) * fmaf(w1.y - w0.y, f, w0.y);
            v.z = __bfloat162float(x23.x) * fmaf(w1.z - w0.z, f, w0.z);
            v.w = __bfloat162float(x23.y) * fmaf(w1.w - w0.w, f, w0.w);

            float* ap = g_agg + (size_t)d * HH + lane * 4;
            asm volatile("red.global.add.v4.f32 [%0], {%1,%2,%3,%4};"
                         :: "l"(ap), "f"(v.x), "f"(v.y), "f"(v.z), "f"(v.w) : "memory");
        }
    }
}

// ---------------------------------------------------------------------------
// Row epilogue helper
// ---------------------------------------------------------------------------
template <int NCOL, bool BIAS, bool ACT, bool RESID, bool POOL, bool OBF16>
__device__ __forceinline__ void epi_row(int row, int c0, float* vals,
                                        const float* __restrict__ bias, void* outv,
                                        const int* __restrict__ batch) {
    if (row >= NN) return;
    #pragma unroll
    for (int j = 0; j < 8; j++) {
        float v = vals[j];
        if (BIAS) v += bias[c0 + j];
        if (ACT) v = sspf(v);
        vals[j] = v;
    }
    if (POOL) {
        int b = batch[row];
        float* p = g_pooled + (size_t)b * NCOL + c0;
        asm volatile("red.global.add.v4.f32 [%0], {%1,%2,%3,%4};"
                     :: "l"(p), "f"(vals[0]), "f"(vals[1]), "f"(vals[2]), "f"(vals[3]) : "memory");
        asm volatile("red.global.add.v4.f32 [%0], {%1,%2,%3,%4};"
                     :: "l"(p + 4), "f"(vals[4]), "f"(vals[5]), "f"(vals[6]), "f"(vals[7]) : "memory");
    } else if (OBF16) {
        __nv_bfloat16* ob = (__nv_bfloat16*)outv + (size_t)row * NCOL + c0;
        __nv_bfloat162 p[4];
        #pragma unroll
        for (int j = 0; j < 4; j++)
            p[j] = __nv_bfloat162(__float2bfloat16(vals[2 * j]), __float2bfloat16(vals[2 * j + 1]));
        *(uint4*)ob = *reinterpret_cast<uint4*>(p);
    } else {
        float* o = (float*)outv + (size_t)row * NCOL + c0;
        if (RESID) {
            float4 h0 = *(float4*)o;
            float4 h1 = *(float4*)(o + 4);
            vals[0] += h0.x; vals[1] += h0.y; vals[2] += h0.z; vals[3] += h0.w;
            vals[4] += h1.x; vals[5] += h1.y; vals[6] += h1.z; vals[7] += h1.w;
        }
        *(float4*)o       = make_float4(vals[0], vals[1], vals[2], vals[3]);
        *(float4*)(o + 4) = make_float4(vals[4], vals[5], vals[6], vals[7]);
    }
}

// ---------------------------------------------------------------------------
// fp32 GEMM with packed f32x2 FMA: out[N,NCOL] = epi(A[N,KDIM] @ W[KDIM,NCOL])
// block tile 128 x NCOL, thread tile 8x8 (acc pairs along rows).
// ---------------------------------------------------------------------------
template <int KDIM, int NCOL, bool BIAS, bool ACT, bool RESID, bool POOL, bool OBF16>
__global__ void __launch_bounds__((NCOL / 8) * 16)
gemm_kernel(const float* __restrict__ A, const float* __restrict__ W,
            const float* __restrict__ bias, void* outv, const int* __restrict__ batch) {
    constexpr int KC = 32;
    constexpr int ROWS = 128;
    constexpr int TX = NCOL / 8;
    constexpr int NTHR = TX * 16;
    constexpr int ASTRIDE = ROWS + 4;

    __shared__ float As[KC][ASTRIDE];   // transposed A tile
    __shared__ float Ws[KC][NCOL];

    int tid = threadIdx.x;
    int tx = tid % TX;
    int ty = tid / TX;
    int row0 = blockIdx.x * ROWS;
    int c0 = tx * 8;

    unsigned long long acc[4][8];   // [row-pair][col]
    #pragma unroll
    for (int i = 0; i < 4; i++)
        #pragma unroll
        for (int j = 0; j < 8; j++) acc[i][j] = 0ULL;

    for (int k0 = 0; k0 < KDIM; k0 += KC) {
        // stage A transposed
        #pragma unroll
        for (int i = tid; i < ROWS * (KC / 4); i += NTHR) {
            int row = i / (KC / 4);
            int kq = i % (KC / 4);
            float4 v = make_float4(0.f, 0.f, 0.f, 0.f);
            if (row0 + row < NN)
                v = *(const float4*)(A + (size_t)(row0 + row) * KDIM + k0 + kq * 4);
            As[kq * 4 + 0][row] = v.x;
            As[kq * 4 + 1][row] = v.y;
            As[kq * 4 + 2][row] = v.z;
            As[kq * 4 + 3][row] = v.w;
        }
        // stage W
        #pragma unroll
        for (int i = tid; i < KC * (NCOL / 4); i += NTHR)
            ((float4*)&Ws[0][0])[i] = ((const float4*)(W + (size_t)k0 * NCOL))[i];
        __syncthreads();

        #pragma unroll 16
        for (int kk = 0; kk < KC; kk++) {
            float4 a0 = *(const float4*)&As[kk][ty * 8];
            float4 a1 = *(const float4*)&As[kk][ty * 8 + 4];
            float4 b0 = *(const float4*)&Ws[kk][c0];
            float4 b1 = *(const float4*)&Ws[kk][c0 + 4];
            unsigned long long ap[4];
            ap[0] = *reinterpret_cast<unsigned long long*>(&a0.x);
            ap[1] = *reinterpret_cast<unsigned long long*>(&a0.z);
            ap[2] = *reinterpret_cast<unsigned long long*>(&a1.x);
            ap[3] = *reinterpret_cast<unsigned long long*>(&a1.z);
            float bv[8] = {b0.x, b0.y, b0.z, b0.w, b1.x, b1.y, b1.z, b1.w};
            #pragma unroll
            for (int j = 0; j < 8; j++) {
                unsigned long long bb = pack2(bv[j], bv[j]);
                #pragma unroll
                for (int i = 0; i < 4; i++)
                    ffma2(acc[i][j], ap[i], bb);
            }
        }
        __syncthreads();
    }

    // epilogue: unpack row pairs
    #pragma unroll
    for (int i2 = 0; i2 < 4; i2++) {
        float v0[8], v1[8];
        #pragma unroll
        for (int j = 0; j < 8; j++) unpack2(acc[i2][j], v0[j], v1[j]);
        int r = row0 + ty * 8 + 2 * i2;
        epi_row<NCOL, BIAS, ACT, RESID, POOL, OBF16>(r, c0, v0, bias, outv, batch);
        epi_row<NCOL, BIAS, ACT, RESID, POOL, OBF16>(r + 1, c0, v1, bias, outv, batch);
    }
}

// ---------------------------------------------------------------------------
// Final tiny GEMM: out[B,T] = pooled[B,H] @ pred_w[H,T] + pred_b
// ---------------------------------------------------------------------------
__global__ void final_kernel(const float* __restrict__ pw, const float* __restrict__ pb,
                             float* __restrict__ out) {
    int tid = threadIdx.x;
    int b = tid >> 2;
    int t = tid & 3;
    float acc = pb[t];
    for (int k = 0; k < HH; k++)
        acc = fmaf(g_pooled[b * HH + k], pw[k * TT + t], acc);
    out[b * TT + t] = acc;
}

// ---------------------------------------------------------------------------
extern "C" void kernel_launch(void* const* d_in, const int* in_sizes, int n_in,
                              void* d_out, int out_size) {
    const int*   z       = (const int*)d_in[0];
    const float* pos     = (const float*)d_in[1];
    const int*   batch   = (const int*)d_in[2];
    const int*   ei      = (const int*)d_in[3];
    const float* emb     = (const float*)d_in[4];
    const float* mlp_w1  = (const float*)d_in[5];
    const float* mlp_b1  = (const float*)d_in[6];
    const float* mlp_w2  = (const float*)d_in[7];
    const float* mlp_b2  = (const float*)d_in[8];
    const float* lin1_w  = (const float*)d_in[9];
    const float* lin2_w  = (const float*)d_in[10];
    const float* lin2_b  = (const float*)d_in[11];
    const float* lin_w   = (const float*)d_in[12];
    const float* lin_b   = (const float*)d_in[13];
    const float* out1_w  = (const float*)d_in[14];
    const float* out1_b  = (const float*)d_in[15];
    const float* out2_w  = (const float*)d_in[16];
    const float* out2_b  = (const float*)d_in[17];
    const float* pred_w  = (const float*)d_in[18];
    const float* pred_b  = (const float*)d_in[19];
    float* out = (float*)d_out;

    float *p_h, *p_tmp, *p_agg, *p_pooled;
    void* p_xjb;
    cudaGetSymbolAddress((void**)&p_h, g_h);
    cudaGetSymbolAddress((void**)&p_tmp, g_tmp);
    cudaGetSymbolAddress(&p_xjb, g_xjb);
    cudaGetSymbolAddress((void**)&p_agg, g_agg);
    cudaGetSymbolAddress((void**)&p_pooled, g_pooled);

    int dev = 0, smCount = 148;
    cudaGetDevice(&dev);
    cudaDeviceGetAttribute(&smCount, cudaDevAttrMultiProcessorCount, dev);

    const int TAB_SMEM = TAB * HH * (int)sizeof(float);   // 196608
    cudaFuncSetAttribute(edge_conv_kernel, cudaFuncAttributeMaxDynamicSharedMemorySize, TAB_SMEM);

    dim3 tb(TAB, 2);
    build_table_kernel<<<tb, HH>>>(mlp_w1, mlp_b1, mlp_w2, mlp_b2);
    edge_prep_kernel<<<(EE + 255) / 256, 256>>>(ei, pos);
    embed_kernel<<<(NN * 32 + 255) / 256, 256>>>(z, emb);

    int gblocks = (NN + 127) / 128;
    for (int i = 0; i < 2; i++) {
        zero_kernel<<<(NN * 32 + 255) / 256, 256>>>(p_agg, NN * 32);
        // xj = h @ lin1  -> bf16
        gemm_kernel<128, 128, false, false, false, false, true><<<gblocks, 256>>>(
            p_h, lin1_w + (size_t)i * HH * HH, nullptr, p_xjb, nullptr);
        // agg[dst] += xj[src] * W(d)
        edge_conv_kernel<<<smCount, 1024, TAB_SMEM>>>(ei, i);
        // tmp = ssp(agg @ lin2 + b2)
        gemm_kernel<128, 128, true, true, false, false, false><<<gblocks, 256>>>(
            p_agg, lin2_w + (size_t)i * HH * HH, lin2_b + (size_t)i * HH, p_tmp, nullptr);
        // h += tmp @ lin + b
        gemm_kernel<128, 128, true, false, true, false, false><<<gblocks, 256>>>(
            p_tmp, lin_w + (size_t)i * HH * HH, lin_b + (size_t)i * HH, p_h, nullptr);
    }

    zero_kernel<<<(BB * 32 + 255) / 256, 256>>>(p_pooled, BB * 32);
    // t1 = ssp(h @ out1 + b1)  [N,64]
    gemm_kernel<128, 64, true, true, false, false, false><<<gblocks, 128>>>(
        p_h, out1_w, out1_b, p_tmp, nullptr);
    // pooled[batch[n]] += t1 @ out2 + b2
    gemm_kernel<64, 128, true, false, false, true, false><<<gblocks, 256>>>(
        p_tmp, out2_w, out2_b, nullptr, batch);
    // out = pooled @ pred_w + pred_b
    final_kernel<<<1, 256>>>(pred_w, pred_b, out);
}

// round 3
// speedup vs baseline: 1.5681x; 1.1115x over previous
#include <cuda_runtime.h>
#include <cuda_bf16.h>
#include <math.h>

#define NN 50000
#define EE 1600000
#define HH 128
#define BB 64
#define TT 4
#define GG 10
#define TAB 384
#define D_MAX 8.6603f
#define SCAN_B 1024
#define NBLK ((NN + SCAN_B - 1) / SCAN_B)

// scratch (static device globals — no runtime allocation)
static __device__ float g_table[2 * TAB * HH];
static __device__ float g_h[NN * HH];
static __device__ float g_tmp[NN * HH];
static __device__ __nv_bfloat16 g_xjb[NN * HH];
static __device__ float g_agg[NN * HH];
static __device__ float g_pooled[BB * HH];
// CSR (dst-major)
static __device__ int  g_deg[NN];
static __device__ int  g_ptr[NN + 1];
static __device__ int  g_work[NN];
static __device__ int  g_bsum[NBLK];
static __device__ int2 g_csr[EE];        // {src | i0<<16, f(bits)}

__device__ __forceinline__ float sspf(float x) {
    float ax = fabsf(x);
    return fmaxf(x, 0.0f) + log1pf(__expf(-ax)) - 0.6931471805599453f;
}

// packed-f32x2 helpers (Blackwell dual-FP32 pipe)
__device__ __forceinline__ unsigned long long pack2(float lo, float hi) {
    unsigned long long r;
    asm("mov.b64 %0, {%1, %2};" : "=l"(r) : "f"(lo), "f"(hi));
    return r;
}
__device__ __forceinline__ void unpack2(unsigned long long v, float& lo, float& hi) {
    asm("mov.b64 {%0, %1}, %2;" : "=f"(lo), "=f"(hi) : "l"(v));
}
__device__ __forceinline__ void ffma2(unsigned long long& d, unsigned long long a,
                                      unsigned long long b) {
    asm("fma.rn.f32x2 %0, %1, %2, %0;" : "+l"(d) : "l"(a), "l"(b));
}

// ---------------------------------------------------------------------------
// Build filter table
// ---------------------------------------------------------------------------
__global__ void build_table_kernel(const float* __restrict__ w1, const float* __restrict__ b1,
                                   const float* __restrict__ w2, const float* __restrict__ b2) {
    int row = blockIdx.x;
    int inter = blockIdx.y;
    int tid = threadIdx.x;
    float d = row * (D_MAX / (float)(TAB - 1));

    __shared__ float hid[HH];
    const float* w1i = w1 + (size_t)inter * GG * HH;
    const float* b1i = b1 + (size_t)inter * HH;
    const float* w2i = w2 + (size_t)inter * HH * HH;
    const float* b2i = b2 + (size_t)inter * HH;

    const float step = 10.0f / 9.0f;
    const float coeff = -0.5f / (step * step);

    float acc = b1i[tid];
    #pragma unroll
    for (int g = 0; g < GG; g++) {
        float diff = d - (float)g * step;
        float r = expf(coeff * diff * diff);
        acc += r * w1i[g * HH + tid];
    }
    hid[tid] = sspf(acc);
    __syncthreads();

    float acc2 = b2i[tid];
    for (int k = 0; k < HH; k++)
        acc2 = fmaf(hid[k], w2i[k * HH + tid], acc2);

    float C = 0.5f * (cosf(d * 3.14159265358979f / 10.0f) + 1.0f);
    g_table[((size_t)inter * TAB + row) * HH + tid] = acc2 * C;
}

// ---------------------------------------------------------------------------
// CSR construction
// ---------------------------------------------------------------------------
__global__ void zero_int_kernel(int* __restrict__ p, int n) {
    int i = blockIdx.x * blockDim.x + threadIdx.x;
    if (i < n) p[i] = 0;
}

__global__ void hist_kernel(const int* __restrict__ ei) {
    int e = blockIdx.x * blockDim.x + threadIdx.x;
    if (e >= EE) return;
    atomicAdd(&g_deg[ei[EE + e]], 1);
}

__global__ void scan1_kernel() {   // per-block sums of deg
    __shared__ int sm[SCAN_B];
    int idx = blockIdx.x * SCAN_B + threadIdx.x;
    int v = (idx < NN) ? g_deg[idx] : 0;
    sm[threadIdx.x] = v;
    __syncthreads();
    for (int off = SCAN_B / 2; off > 0; off >>= 1) {
        if (threadIdx.x < off) sm[threadIdx.x] += sm[threadIdx.x + off];
        __syncthreads();
    }
    if (threadIdx.x == 0) g_bsum[blockIdx.x] = sm[0];
}

__global__ void scan2_kernel() {   // exclusive scan of block sums (tiny)
    if (threadIdx.x == 0) {
        int run = 0;
        for (int b = 0; b < NBLK; b++) {
            int v = g_bsum[b];
            g_bsum[b] = run;
            run += v;
        }
    }
}

__global__ void scan3_kernel() {   // exclusive scan within block + offset
    __shared__ int sm[SCAN_B];
    int idx = blockIdx.x * SCAN_B + threadIdx.x;
    int v = (idx < NN) ? g_deg[idx] : 0;
    sm[threadIdx.x] = v;
    __syncthreads();
    // Hillis-Steele inclusive scan
    for (int off = 1; off < SCAN_B; off <<= 1) {
        int add = (threadIdx.x >= off) ? sm[threadIdx.x - off] : 0;
        __syncthreads();
        sm[threadIdx.x] += add;
        __syncthreads();
    }
    if (idx < NN) {
        int excl = g_bsum[blockIdx.x] + sm[threadIdx.x] - v;
        g_ptr[idx] = excl;
        g_work[idx] = excl;
        if (idx == NN - 1) g_ptr[NN] = g_bsum[blockIdx.x] + sm[threadIdx.x];
    }
}

__global__ void fill_kernel(const int* __restrict__ ei, const float* __restrict__ pos) {
    int e = blockIdx.x * blockDim.x + threadIdx.x;
    if (e >= EE) return;
    int s = ei[e];
    int d = ei[EE + e];
    float dx = pos[s * 3 + 0] - pos[d * 3 + 0];
    float dy = pos[s * 3 + 1] - pos[d * 3 + 1];
    float dz = pos[s * 3 + 2] - pos[d * 3 + 2];
    float dist = sqrtf(dx * dx + dy * dy + dz * dz);
    const float INV_STEP = (float)(TAB - 1) / D_MAX;
    float t = dist * INV_STEP;
    int i0 = min((int)t, TAB - 2);
    float f = t - (float)i0;
    int slot = atomicAdd(&g_work[d], 1);
    g_csr[slot] = make_int2(s | (i0 << 16), __float_as_int(f));
}

// ---------------------------------------------------------------------------
// Embedding gather
// ---------------------------------------------------------------------------
__global__ void embed_kernel(const int* __restrict__ z, const float* __restrict__ emb) {
    int idx = blockIdx.x * blockDim.x + threadIdx.x;
    if (idx >= NN * (HH / 4)) return;
    int n = idx >> 5;
    int c = idx & 31;
    ((float4*)g_h)[idx] = ((const float4*)emb)[(size_t)z[n] * (HH / 4) + c];
}

__global__ void zero_kernel(float* __restrict__ p, int n4) {
    int i = blockIdx.x * blockDim.x + threadIdx.x;
    if (i < n4) ((float4*)p)[i] = make_float4(0.f, 0.f, 0.f, 0.f);
}

// ---------------------------------------------------------------------------
// CSR edge aggregation (gather-only, no atomics):
//   agg[n] = sum_{e in edges(n)} bf16(xj[src_e]) * lerp(table, i0_e, f_e)
// Persistent: 1 block/SM, 1024 thr, table in 196KB smem. One warp per node.
// ---------------------------------------------------------------------------
__global__ void __launch_bounds__(1024) edge_conv_csr_kernel(int inter) {
    extern __shared__ float tab[];
    const float4* src_tab = (const float4*)(g_table + (size_t)inter * TAB * HH);
    for (int i = threadIdx.x; i < TAB * HH / 4; i += 1024)
        ((float4*)tab)[i] = src_tab[i];
    __syncthreads();

    int lane = threadIdx.x & 31;
    int gwarp = blockIdx.x * 32 + (threadIdx.x >> 5);
    int nwarp = gridDim.x * 32;

    for (int node = gwarp; node < NN; node += nwarp) {
        int beg = __ldg(&g_ptr[node]);
        int end = __ldg(&g_ptr[node + 1]);

        float4 acc = make_float4(0.f, 0.f, 0.f, 0.f);

        for (int base = beg; base < end; base += 32) {
            int k = base + lane;
            int2 c = (k < end) ? __ldg(&g_csr[k]) : make_int2(0, 0);
            int cnt = min(32, end - base);
            for (int j = 0; j < cnt; j++) {
                int cx  = __shfl_sync(0xffffffffu, c.x, j);
                int cyi = __shfl_sync(0xffffffffu, c.y, j);
                int s  = cx & 0xffff;
                int i0 = cx >> 16;
                float f = __int_as_float(cyi);

                uint2 xw = *(const uint2*)(g_xjb + (size_t)s * HH + lane * 4);
                __nv_bfloat162 x01 = *reinterpret_cast<__nv_bfloat162*>(&xw.x);
                __nv_bfloat162 x23 = *reinterpret_cast<__nv_bfloat162*>(&xw.y);

                const float* t0 = tab + i0 * HH + lane * 4;
                float4 w0 = *(const float4*)t0;
                float4 w1 = *(const float4*)(t0 + HH);

                acc.x = fmaf(__bfloat162float(x01.x), fmaf(w1.x - w0.x, f, w0.x), acc.x);
                acc.y = fmaf(__bfloat162float(x01.y), fmaf(w1.y - w0.y, f, w0.y), acc.y);
                acc.z = fmaf(__bfloat162float(x23.x), fmaf(w1.z - w0.z, f, w0.z), acc.z);
                acc.w = fmaf(__bfloat162float(x23.y), fmaf(w1.w - w0.w, f, w0.w), acc.w);
            }
        }
        *(float4*)(g_agg + (size_t)node * HH + lane * 4) = acc;
    }
}

// ---------------------------------------------------------------------------
// Row epilogue helper
// ---------------------------------------------------------------------------
template <int NCOL, bool BIAS, bool ACT, bool RESID, bool POOL, bool OBF16>
__device__ __forceinline__ void epi_row(int row, int c0, float* vals,
                                        const float* __restrict__ bias, void* outv,
                                        const int* __restrict__ batch) {
    if (row >= NN) return;
    #pragma unroll
    for (int j = 0; j < 8; j++) {
        float v = vals[j];
        if (BIAS) v += bias[c0 + j];
        if (ACT) v = sspf(v);
        vals[j] = v;
    }
    if (POOL) {
        int b = batch[row];
        float* p = g_pooled + (size_t)b * NCOL + c0;
        asm volatile("red.global.add.v4.f32 [%0], {%1,%2,%3,%4};"
                     :: "l"(p), "f"(vals[0]), "f"(vals[1]), "f"(vals[2]), "f"(vals[3]) : "memory");
        asm volatile("red.global.add.v4.f32 [%0], {%1,%2,%3,%4};"
                     :: "l"(p + 4), "f"(vals[4]), "f"(vals[5]), "f"(vals[6]), "f"(vals[7]) : "memory");
    } else if (OBF16) {
        __nv_bfloat16* ob = (__nv_bfloat16*)outv + (size_t)row * NCOL + c0;
        __nv_bfloat162 p[4];
        #pragma unroll
        for (int j = 0; j < 4; j++)
            p[j] = __nv_bfloat162(__float2bfloat16(vals[2 * j]), __float2bfloat16(vals[2 * j + 1]));
        *(uint4*)ob = *reinterpret_cast<uint4*>(p);
    } else {
        float* o = (float*)outv + (size_t)row * NCOL + c0;
        if (RESID) {
            float4 h0 = *(float4*)o;
            float4 h1 = *(float4*)(o + 4);
            vals[0] += h0.x; vals[1] += h0.y; vals[2] += h0.z; vals[3] += h0.w;
            vals[4] += h1.x; vals[5] += h1.y; vals[6] += h1.z; vals[7] += h1.w;
        }
        *(float4*)o       = make_float4(vals[0], vals[1], vals[2], vals[3]);
        *(float4*)(o + 4) = make_float4(vals[4], vals[5], vals[6], vals[7]);
    }
}

// ---------------------------------------------------------------------------
// fp32 GEMM with packed f32x2 FMA
// ---------------------------------------------------------------------------
template <int KDIM, int NCOL, bool BIAS, bool ACT, bool RESID, bool POOL, bool OBF16>
__global__ void __launch_bounds__((NCOL / 8) * 16)
gemm_kernel(const float* __restrict__ A, const float* __restrict__ W,
            const float* __restrict__ bias, void* outv, const int* __restrict__ batch) {
    constexpr int KC = 32;
    constexpr int ROWS = 128;
    constexpr int TX = NCOL / 8;
    constexpr int NTHR = TX * 16;
    constexpr int ASTRIDE = ROWS + 4;

    __shared__ float As[KC][ASTRIDE];
    __shared__ float Ws[KC][NCOL];

    int tid = threadIdx.x;
    int tx = tid % TX;
    int ty = tid / TX;
    int row0 = blockIdx.x * ROWS;
    int c0 = tx * 8;

    unsigned long long acc[4][8];
    #pragma unroll
    for (int i = 0; i < 4; i++)
        #pragma unroll
        for (int j = 0; j < 8; j++) acc[i][j] = 0ULL;

    for (int k0 = 0; k0 < KDIM; k0 += KC) {
        #pragma unroll
        for (int i = tid; i < ROWS * (KC / 4); i += NTHR) {
            int row = i / (KC / 4);
            int kq = i % (KC / 4);
            float4 v = make_float4(0.f, 0.f, 0.f, 0.f);
            if (row0 + row < NN)
                v = *(const float4*)(A + (size_t)(row0 + row) * KDIM + k0 + kq * 4);
            As[kq * 4 + 0][row] = v.x;
            As[kq * 4 + 1][row] = v.y;
            As[kq * 4 + 2][row] = v.z;
            As[kq * 4 + 3][row] = v.w;
        }
        #pragma unroll
        for (int i = tid; i < KC * (NCOL / 4); i += NTHR)
            ((float4*)&Ws[0][0])[i] = ((const float4*)(W + (size_t)k0 * NCOL))[i];
        __syncthreads();

        #pragma unroll 16
        for (int kk = 0; kk < KC; kk++) {
            float4 a0 = *(const float4*)&As[kk][ty * 8];
            float4 a1 = *(const float4*)&As[kk][ty * 8 + 4];
            float4 b0 = *(const float4*)&Ws[kk][c0];
            float4 b1 = *(const float4*)&Ws[kk][c0 + 4];
            unsigned long long ap[4];
            ap[0] = *reinterpret_cast<unsigned long long*>(&a0.x);
            ap[1] = *reinterpret_cast<unsigned long long*>(&a0.z);
            ap[2] = *reinterpret_cast<unsigned long long*>(&a1.x);
            ap[3] = *reinterpret_cast<unsigned long long*>(&a1.z);
            float bv[8] = {b0.x, b0.y, b0.z, b0.w, b1.x, b1.y, b1.z, b1.w};
            #pragma unroll
            for (int j = 0; j < 8; j++) {
                unsigned long long bb = pack2(bv[j], bv[j]);
                #pragma unroll
                for (int i = 0; i < 4; i++)
                    ffma2(acc[i][j], ap[i], bb);
            }
        }
        __syncthreads();
    }

    #pragma unroll
    for (int i2 = 0; i2 < 4; i2++) {
        float v0[8], v1[8];
        #pragma unroll
        for (int j = 0; j < 8; j++) unpack2(acc[i2][j], v0[j], v1[j]);
        int r = row0 + ty * 8 + 2 * i2;
        epi_row<NCOL, BIAS, ACT, RESID, POOL, OBF16>(r, c0, v0, bias, outv, batch);
        epi_row<NCOL, BIAS, ACT, RESID, POOL, OBF16>(r + 1, c0, v1, bias, outv, batch);
    }
}

// ---------------------------------------------------------------------------
// Final tiny GEMM
// ---------------------------------------------------------------------------
__global__ void final_kernel(const float* __restrict__ pw, const float* __restrict__ pb,
                             float* __restrict__ out) {
    int tid = threadIdx.x;
    int b = tid >> 2;
    int t = tid & 3;
    float acc = pb[t];
    for (int k = 0; k < HH; k++)
        acc = fmaf(g_pooled[b * HH + k], pw[k * TT + t], acc);
    out[b * TT + t] = acc;
}

// ---------------------------------------------------------------------------
extern "C" void kernel_launch(void* const* d_in, const int* in_sizes, int n_in,
                              void* d_out, int out_size) {
    const int*   z       = (const int*)d_in[0];
    const float* pos     = (const float*)d_in[1];
    const int*   batch   = (const int*)d_in[2];
    const int*   ei      = (const int*)d_in[3];
    const float* emb     = (const float*)d_in[4];
    const float* mlp_w1  = (const float*)d_in[5];
    const float* mlp_b1  = (const float*)d_in[6];
    const float* mlp_w2  = (const float*)d_in[7];
    const float* mlp_b2  = (const float*)d_in[8];
    const float* lin1_w  = (const float*)d_in[9];
    const float* lin2_w  = (const float*)d_in[10];
    const float* lin2_b  = (const float*)d_in[11];
    const float* lin_w   = (const float*)d_in[12];
    const float* lin_b   = (const float*)d_in[13];
    const float* out1_w  = (const float*)d_in[14];
    const float* out1_b  = (const float*)d_in[15];
    const float* out2_w  = (const float*)d_in[16];
    const float* out2_b  = (const float*)d_in[17];
    const float* pred_w  = (const float*)d_in[18];
    const float* pred_b  = (const float*)d_in[19];
    float* out = (float*)d_out;

    float *p_h, *p_tmp, *p_agg, *p_pooled;
    void* p_xjb;
    int* p_deg;
    cudaGetSymbolAddress((void**)&p_h, g_h);
    cudaGetSymbolAddress((void**)&p_tmp, g_tmp);
    cudaGetSymbolAddress(&p_xjb, g_xjb);
    cudaGetSymbolAddress((void**)&p_agg, g_agg);
    cudaGetSymbolAddress((void**)&p_pooled, g_pooled);
    cudaGetSymbolAddress((void**)&p_deg, g_deg);

    int dev = 0, smCount = 148;
    cudaGetDevice(&dev);
    cudaDeviceGetAttribute(&smCount, cudaDevAttrMultiProcessorCount, dev);

    const int TAB_SMEM = TAB * HH * (int)sizeof(float);
    cudaFuncSetAttribute(edge_conv_csr_kernel, cudaFuncAttributeMaxDynamicSharedMemorySize, TAB_SMEM);

    // table + CSR build + embedding
    dim3 tb(TAB, 2);
    build_table_kernel<<<tb, HH>>>(mlp_w1, mlp_b1, mlp_w2, mlp_b2);
    zero_int_kernel<<<(NN + 255) / 256, 256>>>(p_deg, NN);
    hist_kernel<<<(EE + 255) / 256, 256>>>(ei);
    scan1_kernel<<<NBLK, SCAN_B>>>();
    scan2_kernel<<<1, 32>>>();
    scan3_kernel<<<NBLK, SCAN_B>>>();
    fill_kernel<<<(EE + 255) / 256, 256>>>(ei, pos);
    embed_kernel<<<(NN * 32 + 255) / 256, 256>>>(z, emb);

    int gblocks = (NN + 127) / 128;
    for (int i = 0; i < 2; i++) {
        // xj = h @ lin1 -> bf16
        gemm_kernel<128, 128, false, false, false, false, true><<<gblocks, 256>>>(
            p_h, lin1_w + (size_t)i * HH * HH, nullptr, p_xjb, nullptr);
        // agg[n] = sum over incident edges (gather-only)
        edge_conv_csr_kernel<<<smCount, 1024, TAB_SMEM>>>(i);
        // tmp = ssp(agg @ lin2 + b2)
        gemm_kernel<128, 128, true, true, false, false, false><<<gblocks, 256>>>(
            p_agg, lin2_w + (size_t)i * HH * HH, lin2_b + (size_t)i * HH, p_tmp, nullptr);
        // h += tmp @ lin + b
        gemm_kernel<128, 128, true, false, true, false, false><<<gblocks, 256>>>(
            p_tmp, lin_w + (size_t)i * HH * HH, lin_b + (size_t)i * HH, p_h, nullptr);
    }

    zero_kernel<<<(BB * 32 + 255) / 256, 256>>>(p_pooled, BB * 32);
    gemm_kernel<128, 64, true, true, false, false, false><<<gblocks, 128>>>(
        p_h, out1_w, out1_b, p_tmp, nullptr);
    gemm_kernel<64, 128, true, false, false, true, false><<<gblocks, 256>>>(
        p_tmp, out2_w, out2_b, nullptr, batch);
    final_kernel<<<1, 256>>>(pred_w, pred_b, out);
}

// round 6
// speedup vs baseline: 2.0236x; 1.2905x over previous
#include <cuda_runtime.h>
#include <cuda_bf16.h>
#include <stdint.h>
#include <math.h>

#define NN 50000
#define EE 1600000
#define HH 128
#define BB 64
#define TT 4
#define GG 10
#define TAB 384
#define D_MAX 8.6603f
#define SCAN_B 1024
#define NBLK ((NN + SCAN_B - 1) / SCAN_B)

// scratch (static device globals — no runtime allocation)
static __device__ float g_table[2 * TAB * HH];
static __device__ float g_h[NN * HH];
static __device__ float g_tmp[NN * HH];
static __device__ __nv_bfloat16 g_xjb[NN * HH];
static __device__ float g_agg[NN * HH];
static __device__ float g_pooled[BB * HH];
static __device__ __nv_bfloat16 g_wt_hi[7 * 16384];   // transposed bf16 weights (high part)
static __device__ __nv_bfloat16 g_wt_lo[7 * 16384];   // residual (low part)
// CSR (dst-major)
static __device__ int  g_deg[NN];
static __device__ int  g_ptr[NN + 1];
static __device__ int  g_work[NN];
static __device__ int  g_bsum[NBLK];
static __device__ int2 g_csr[EE];        // {src | i0<<16, f(bits)}

// transposed-weight offsets (elements)
#define WT_LIN1(i)  ((size_t)(i) * 16384)
#define WT_LIN2(i)  ((size_t)(32768) + (size_t)(i) * 16384)
#define WT_LIN(i)   ((size_t)(65536) + (size_t)(i) * 16384)
#define WT_OUT1     ((size_t)98304)
#define WT_OUT2     ((size_t)106496)

__device__ __forceinline__ float sspf(float x) {
    float ax = fabsf(x);
    return fmaxf(x, 0.0f) + log1pf(__expf(-ax)) - 0.6931471805599453f;
}

#define SWZ(off) ((off) ^ (((off) >> 3) & 0x70))

__device__ __forceinline__ unsigned smem_u32(const void* p) {
    return (unsigned)__cvta_generic_to_shared(p);
}
__device__ __forceinline__ void ldsm_x4(unsigned* r, unsigned addr) {
    asm volatile("ldmatrix.sync.aligned.m8n8.x4.shared.b16 {%0,%1,%2,%3}, [%4];"
                 : "=r"(r[0]), "=r"(r[1]), "=r"(r[2]), "=r"(r[3]) : "r"(addr));
}
__device__ __forceinline__ void ldsm_x2(unsigned* r, unsigned addr) {
    asm volatile("ldmatrix.sync.aligned.m8n8.x2.shared.b16 {%0,%1}, [%2];"
                 : "=r"(r[0]), "=r"(r[1]) : "r"(addr));
}
__device__ __forceinline__ void mma_bf16(float* d, const unsigned* a, const unsigned* b) {
    asm volatile("mma.sync.aligned.m16n8k16.row.col.f32.bf16.bf16.f32 "
                 "{%0,%1,%2,%3}, {%4,%5,%6,%7}, {%8,%9}, {%0,%1,%2,%3};"
                 : "+f"(d[0]), "+f"(d[1]), "+f"(d[2]), "+f"(d[3])
                 : "r"(a[0]), "r"(a[1]), "r"(a[2]), "r"(a[3]), "r"(b[0]), "r"(b[1]));
}

// split x into bf16 hi + bf16 lo (residual)
__device__ __forceinline__ void split_bf16(float x, __nv_bfloat16& hi, __nv_bfloat16& lo) {
    hi = __float2bfloat16(x);
    lo = __float2bfloat16(x - __bfloat162float(hi));
}

// ---------------------------------------------------------------------------
// Build filter table
// ---------------------------------------------------------------------------
__global__ void build_table_kernel(const float* __restrict__ w1, const float* __restrict__ b1,
                                   const float* __restrict__ w2, const float* __restrict__ b2) {
    int row = blockIdx.x;
    int inter = blockIdx.y;
    int tid = threadIdx.x;
    float d = row * (D_MAX / (float)(TAB - 1));

    __shared__ float hid[HH];
    const float* w1i = w1 + (size_t)inter * GG * HH;
    const float* b1i = b1 + (size_t)inter * HH;
    const float* w2i = w2 + (size_t)inter * HH * HH;
    const float* b2i = b2 + (size_t)inter * HH;

    const float step = 10.0f / 9.0f;
    const float coeff = -0.5f / (step * step);

    float acc = b1i[tid];
    #pragma unroll
    for (int g = 0; g < GG; g++) {
        float diff = d - (float)g * step;
        float r = expf(coeff * diff * diff);
        acc += r * w1i[g * HH + tid];
    }
    hid[tid] = sspf(acc);
    __syncthreads();

    float acc2 = b2i[tid];
    for (int k = 0; k < HH; k++)
        acc2 = fmaf(hid[k], w2i[k * HH + tid], acc2);

    float C = 0.5f * (cosf(d * 3.14159265358979f / 10.0f) + 1.0f);
    g_table[((size_t)inter * TAB + row) * HH + tid] = acc2 * C;
}

// ---------------------------------------------------------------------------
// Weight transpose + split-bf16 convert: dst[n*K+k] = split(src[k*N+n])
// ---------------------------------------------------------------------------
__global__ void transpose_w_kernel(const float* __restrict__ src,
                                   __nv_bfloat16* __restrict__ dst_hi,
                                   __nv_bfloat16* __restrict__ dst_lo,
                                   int K, int N) {
    int i = blockIdx.x * blockDim.x + threadIdx.x;
    if (i >= K * N) return;
    int k = i / N, n = i % N;
    __nv_bfloat16 hi, lo;
    split_bf16(src[i], hi, lo);
    dst_hi[(size_t)n * K + k] = hi;
    dst_lo[(size_t)n * K + k] = lo;
}

// ---------------------------------------------------------------------------
// CSR construction
// ---------------------------------------------------------------------------
__global__ void zero_int_kernel(int* __restrict__ p, int n) {
    int i = blockIdx.x * blockDim.x + threadIdx.x;
    if (i < n) p[i] = 0;
}

__global__ void hist_kernel(const int* __restrict__ ei) {
    int e = blockIdx.x * blockDim.x + threadIdx.x;
    if (e >= EE) return;
    atomicAdd(&g_deg[ei[EE + e]], 1);
}

__global__ void scan1_kernel() {
    __shared__ int sm[SCAN_B];
    int idx = blockIdx.x * SCAN_B + threadIdx.x;
    int v = (idx < NN) ? g_deg[idx] : 0;
    sm[threadIdx.x] = v;
    __syncthreads();
    for (int off = SCAN_B / 2; off > 0; off >>= 1) {
        if (threadIdx.x < off) sm[threadIdx.x] += sm[threadIdx.x + off];
        __syncthreads();
    }
    if (threadIdx.x == 0) g_bsum[blockIdx.x] = sm[0];
}

__global__ void scan2_kernel() {
    if (threadIdx.x == 0) {
        int run = 0;
        for (int b = 0; b < NBLK; b++) {
            int v = g_bsum[b];
            g_bsum[b] = run;
            run += v;
        }
    }
}

__global__ void scan3_kernel() {
    __shared__ int sm[SCAN_B];
    int idx = blockIdx.x * SCAN_B + threadIdx.x;
    int v = (idx < NN) ? g_deg[idx] : 0;
    sm[threadIdx.x] = v;
    __syncthreads();
    for (int off = 1; off < SCAN_B; off <<= 1) {
        int add = (threadIdx.x >= off) ? sm[threadIdx.x - off] : 0;
        __syncthreads();
        sm[threadIdx.x] += add;
        __syncthreads();
    }
    if (idx < NN) {
        int excl = g_bsum[blockIdx.x] + sm[threadIdx.x] - v;
        g_ptr[idx] = excl;
        g_work[idx] = excl;
        if (idx == NN - 1) g_ptr[NN] = g_bsum[blockIdx.x] + sm[threadIdx.x];
    }
}

__global__ void fill_kernel(const int* __restrict__ ei, const float* __restrict__ pos) {
    int e = blockIdx.x * blockDim.x + threadIdx.x;
    if (e >= EE) return;
    int s = ei[e];
    int d = ei[EE + e];
    float dx = pos[s * 3 + 0] - pos[d * 3 + 0];
    float dy = pos[s * 3 + 1] - pos[d * 3 + 1];
    float dz = pos[s * 3 + 2] - pos[d * 3 + 2];
    float dist = sqrtf(dx * dx + dy * dy + dz * dz);
    const float INV_STEP = (float)(TAB - 1) / D_MAX;
    float t = dist * INV_STEP;
    int i0 = min((int)t, TAB - 2);
    float f = t - (float)i0;
    int slot = atomicAdd(&g_work[d], 1);
    g_csr[slot] = make_int2(s | (i0 << 16), __float_as_int(f));
}

// ---------------------------------------------------------------------------
// Embedding gather
// ---------------------------------------------------------------------------
__global__ void embed_kernel(const int* __restrict__ z, const float* __restrict__ emb) {
    int idx = blockIdx.x * blockDim.x + threadIdx.x;
    if (idx >= NN * (HH / 4)) return;
    int n = idx >> 5;
    int c = idx & 31;
    ((float4*)g_h)[idx] = ((const float4*)emb)[(size_t)z[n] * (HH / 4) + c];
}

__global__ void zero_kernel(float* __restrict__ p, int n4) {
    int i = blockIdx.x * blockDim.x + threadIdx.x;
    if (i < n4) ((float4*)p)[i] = make_float4(0.f, 0.f, 0.f, 0.f);
}

// ---------------------------------------------------------------------------
// CSR edge aggregation (gather-only), fp32 table in smem (196KB) — round-3 validated
// ---------------------------------------------------------------------------
__global__ void __launch_bounds__(1024) edge_conv_csr_kernel(int inter) {
    extern __shared__ float tab[];
    const float4* src_tab = (const float4*)(g_table + (size_t)inter * TAB * HH);
    for (int i = threadIdx.x; i < TAB * HH / 4; i += 1024)
        ((float4*)tab)[i] = src_tab[i];
    __syncthreads();

    int lane = threadIdx.x & 31;
    int gwarp = blockIdx.x * 32 + (threadIdx.x >> 5);
    int nwarp = gridDim.x * 32;

    for (int node = gwarp; node < NN; node += nwarp) {
        int beg = __ldg(&g_ptr[node]);
        int end = __ldg(&g_ptr[node + 1]);

        float4 acc = make_float4(0.f, 0.f, 0.f, 0.f);

        for (int base = beg; base < end; base += 32) {
            int k = base + lane;
            int2 c = (k < end) ? __ldg(&g_csr[k]) : make_int2(0, 0);
            int cnt = min(32, end - base);
            for (int j = 0; j < cnt; j++) {
                int cx  = __shfl_sync(0xffffffffu, c.x, j);
                int cyi = __shfl_sync(0xffffffffu, c.y, j);
                int s  = cx & 0xffff;
                int i0 = cx >> 16;
                float f = __int_as_float(cyi);

                uint2 xw = *(const uint2*)(g_xjb + (size_t)s * HH + lane * 4);
                __nv_bfloat162 x01 = *reinterpret_cast<__nv_bfloat162*>(&xw.x);
                __nv_bfloat162 x23 = *reinterpret_cast<__nv_bfloat162*>(&xw.y);

                const float* t0 = tab + i0 * HH + lane * 4;
                float4 w0 = *(const float4*)t0;
                float4 w1 = *(const float4*)(t0 + HH);

                acc.x = fmaf(__bfloat162float(x01.x), fmaf(w1.x - w0.x, f, w0.x), acc.x);
                acc.y = fmaf(__bfloat162float(x01.y), fmaf(w1.y - w0.y, f, w0.y), acc.y);
                acc.z = fmaf(__bfloat162float(x23.x), fmaf(w1.z - w0.z, f, w0.z), acc.z);
                acc.w = fmaf(__bfloat162float(x23.y), fmaf(w1.w - w0.w, f, w0.w), acc.w);
            }
        }
        *(float4*)(g_agg + (size_t)node * HH + lane * 4) = acc;
    }
}

// ---------------------------------------------------------------------------
// Pair epilogue
// ---------------------------------------------------------------------------
template <int NCOL, bool BIAS, bool ACT, bool RESID, bool POOL, bool OBF16>
__device__ __forceinline__ void epi2(int row, int col, float v0, float v1,
                                     const float* __restrict__ bias, void* outv,
                                     const int* __restrict__ batch) {
    if (row >= NN) return;
    if (BIAS) { v0 += bias[col]; v1 += bias[col + 1]; }
    if (ACT)  { v0 = sspf(v0); v1 = sspf(v1); }
    if (POOL) {
        int b = batch[row];
        float* p = g_pooled + (size_t)b * NCOL + col;
        asm volatile("red.global.add.v2.f32 [%0], {%1,%2};" :: "l"(p), "f"(v0), "f"(v1) : "memory");
    } else if (OBF16) {
        __nv_bfloat162 pk = __floats2bfloat162_rn(v0, v1);
        *(unsigned*)((__nv_bfloat16*)outv + (size_t)row * NCOL + col) = *(unsigned*)&pk;
    } else {
        float* o = (float*)outv + (size_t)row * NCOL + col;
        if (RESID) {
            float2 h = *(float2*)o;
            v0 += h.x; v1 += h.y;
        }
        *(float2*)o = make_float2(v0, v1);
    }
}

// ---------------------------------------------------------------------------
// Split-bf16 tensor-core GEMM (3-term emulation, near-fp32 accuracy):
//   out = epi(A @ Wt^T),  A fp32 -> (hi,lo) bf16;  W pre-split (hi,lo)
//   acc = A_hi*W_hi + A_lo*W_hi + A_hi*W_lo
// block 128 x NCOL tile, 256 threads = 8 warps (4 M x 2 N)
// dynamic smem: As_hi, As_lo [128*KC], Bs_hi, Bs_lo [NCOL*KC] bf16
// ---------------------------------------------------------------------------
template <int KDIM, int NCOL, bool BIAS, bool ACT, bool RESID, bool POOL, bool OBF16>
__global__ void __launch_bounds__(256)
mma_gemm_kernel(const float* __restrict__ A,
                const __nv_bfloat16* __restrict__ Wt_hi,
                const __nv_bfloat16* __restrict__ Wt_lo,
                const float* __restrict__ bias, void* outv, const int* __restrict__ batch) {
    constexpr int KC = 64;
    constexpr int WN = NCOL / 2;
    constexpr int NT = WN / 8;
    constexpr int A_BYTES = 128 * KC * 2;
    constexpr int B_BYTES = NCOL * KC * 2;

    extern __shared__ char dynsm[];
    char* As_hi = dynsm;
    char* As_lo = dynsm + A_BYTES;
    char* Bs_hi = dynsm + 2 * A_BYTES;
    char* Bs_lo = dynsm + 2 * A_BYTES + B_BYTES;

    int tid = threadIdx.x;
    int warp = tid >> 5, lane = tid & 31;
    int wm = warp & 3, wn = warp >> 2;
    int row0 = blockIdx.x * 128;

    float acc[2][NT][4];
    #pragma unroll
    for (int mt = 0; mt < 2; mt++)
        #pragma unroll
        for (int nt = 0; nt < NT; nt++)
            #pragma unroll
            for (int q = 0; q < 4; q++) acc[mt][nt][q] = 0.f;

    unsigned ah_base = smem_u32(As_hi);
    unsigned al_base = smem_u32(As_lo);
    unsigned bh_base = smem_u32(Bs_hi);
    unsigned bl_base = smem_u32(Bs_lo);

    for (int k0 = 0; k0 < KDIM; k0 += KC) {
        // stage A (fp32 -> split bf16, SW128 swizzled 128B rows)
        #pragma unroll
        for (int i = tid; i < 128 * 8; i += 256) {
            int r = i >> 3, ch = i & 7;
            int grow = row0 + r;
            float v[8] = {0.f, 0.f, 0.f, 0.f, 0.f, 0.f, 0.f, 0.f};
            if (grow < NN) {
                const float* gp = A + (size_t)grow * KDIM + k0 + ch * 8;
                float4 f0 = *(const float4*)gp;
                float4 f1 = *(const float4*)(gp + 4);
                v[0] = f0.x; v[1] = f0.y; v[2] = f0.z; v[3] = f0.w;
                v[4] = f1.x; v[5] = f1.y; v[6] = f1.z; v[7] = f1.w;
            }
            __nv_bfloat16 hi[8], lo[8];
            #pragma unroll
            for (int q = 0; q < 8; q++) split_bf16(v[q], hi[q], lo[q]);
            int off = SWZ(r * 128 + ch * 16);
            *(uint4*)(As_hi + off) = *(uint4*)hi;
            *(uint4*)(As_lo + off) = *(uint4*)lo;
        }
        // stage B (pre-split bf16 [NCOL][KDIM])
        #pragma unroll
        for (int i = tid; i < NCOL * 8; i += 256) {
            int r = i >> 3, ch = i & 7;
            size_t gidx = (size_t)r * KDIM + k0 + ch * 8;
            int off = SWZ(r * 128 + ch * 16);
            *(uint4*)(Bs_hi + off) = *(const uint4*)(Wt_hi + gidx);
            *(uint4*)(Bs_lo + off) = *(const uint4*)(Wt_lo + gidx);
        }
        __syncthreads();

        #pragma unroll
        for (int ks = 0; ks < KC / 16; ks++) {
            unsigned ah[2][4], al[2][4];
            #pragma unroll
            for (int mt = 0; mt < 2; mt++) {
                int r = wm * 32 + mt * 16 + (lane & 15);
                int off = SWZ(r * 128 + ks * 32 + (lane >> 4) * 16);
                ldsm_x4(ah[mt], ah_base + off);
                ldsm_x4(al[mt], al_base + off);
            }
            #pragma unroll
            for (int nt = 0; nt < NT; nt++) {
                unsigned bh[2], bl[2];
                int l = lane & 15;
                int r = wn * WN + nt * 8 + (l & 7);
                int off = SWZ(r * 128 + ks * 32 + ((l >> 3) & 1) * 16);
                ldsm_x2(bh, bh_base + off);
                ldsm_x2(bl, bl_base + off);
                #pragma unroll
                for (int mt = 0; mt < 2; mt++) {
                    mma_bf16(acc[mt][nt], ah[mt], bh);
                    mma_bf16(acc[mt][nt], al[mt], bh);
                    mma_bf16(acc[mt][nt], ah[mt], bl);
                }
            }
        }
        __syncthreads();
    }

    // epilogue
    #pragma unroll
    for (int mt = 0; mt < 2; mt++) {
        #pragma unroll
        for (int nt = 0; nt < NT; nt++) {
            int r = row0 + wm * 32 + mt * 16 + (lane >> 2);
            int c = wn * WN + nt * 8 + (lane & 3) * 2;
            epi2<NCOL, BIAS, ACT, RESID, POOL, OBF16>(r, c, acc[mt][nt][0], acc[mt][nt][1], bias, outv, batch);
            epi2<NCOL, BIAS, ACT, RESID, POOL, OBF16>(r + 8, c, acc[mt][nt][2], acc[mt][nt][3], bias, outv, batch);
        }
    }
}

// ---------------------------------------------------------------------------
// Final tiny GEMM
// ---------------------------------------------------------------------------
__global__ void final_kernel(const float* __restrict__ pw, const float* __restrict__ pb,
                             float* __restrict__ out) {
    int tid = threadIdx.x;
    int b = tid >> 2;
    int t = tid & 3;
    float acc = pb[t];
    for (int k = 0; k < HH; k++)
        acc = fmaf(g_pooled[b * HH + k], pw[k * TT + t], acc);
    out[b * TT + t] = acc;
}

// ---------------------------------------------------------------------------
extern "C" void kernel_launch(void* const* d_in, const int* in_sizes, int n_in,
                              void* d_out, int out_size) {
    const int*   z       = (const int*)d_in[0];
    const float* pos     = (const float*)d_in[1];
    const int*   batch   = (const int*)d_in[2];
    const int*   ei      = (const int*)d_in[3];
    const float* emb     = (const float*)d_in[4];
    const float* mlp_w1  = (const float*)d_in[5];
    const float* mlp_b1  = (const float*)d_in[6];
    const float* mlp_w2  = (const float*)d_in[7];
    const float* mlp_b2  = (const float*)d_in[8];
    const float* lin1_w  = (const float*)d_in[9];
    const float* lin2_w  = (const float*)d_in[10];
    const float* lin2_b  = (const float*)d_in[11];
    const float* lin_w   = (const float*)d_in[12];
    const float* lin_b   = (const float*)d_in[13];
    const float* out1_w  = (const float*)d_in[14];
    const float* out1_b  = (const float*)d_in[15];
    const float* out2_w  = (const float*)d_in[16];
    const float* out2_b  = (const float*)d_in[17];
    const float* pred_w  = (const float*)d_in[18];
    const float* pred_b  = (const float*)d_in[19];
    float* out = (float*)d_out;

    float *p_h, *p_tmp, *p_agg, *p_pooled;
    void* p_xjb;
    int* p_deg;
    __nv_bfloat16 *p_wh, *p_wl;
    cudaGetSymbolAddress((void**)&p_h, g_h);
    cudaGetSymbolAddress((void**)&p_tmp, g_tmp);
    cudaGetSymbolAddress(&p_xjb, g_xjb);
    cudaGetSymbolAddress((void**)&p_agg, g_agg);
    cudaGetSymbolAddress((void**)&p_pooled, g_pooled);
    cudaGetSymbolAddress((void**)&p_deg, g_deg);
    cudaGetSymbolAddress((void**)&p_wh, g_wt_hi);
    cudaGetSymbolAddress((void**)&p_wl, g_wt_lo);

    int dev = 0, smCount = 148;
    cudaGetDevice(&dev);
    cudaDeviceGetAttribute(&smCount, cudaDevAttrMultiProcessorCount, dev);

    const int TAB_SMEM = TAB * HH * (int)sizeof(float);   // 196608
    cudaFuncSetAttribute(edge_conv_csr_kernel, cudaFuncAttributeMaxDynamicSharedMemorySize, TAB_SMEM);

    // dynamic smem sizes for GEMM variants: 2*A + 2*B bf16 tiles, KC=64
    const int SM128 = (2 * 128 * 64 + 2 * 128 * 64) * 2;   // 65536
    const int SM64  = (2 * 128 * 64 + 2 * 64 * 64) * 2;    // 49152
    cudaFuncSetAttribute(mma_gemm_kernel<128, 128, false, false, false, false, true>,
                         cudaFuncAttributeMaxDynamicSharedMemorySize, SM128);
    cudaFuncSetAttribute(mma_gemm_kernel<128, 128, true, true, false, false, false>,
                         cudaFuncAttributeMaxDynamicSharedMemorySize, SM128);
    cudaFuncSetAttribute(mma_gemm_kernel<128, 128, true, false, true, false, false>,
                         cudaFuncAttributeMaxDynamicSharedMemorySize, SM128);
    cudaFuncSetAttribute(mma_gemm_kernel<128, 64, true, true, false, false, false>,
                         cudaFuncAttributeMaxDynamicSharedMemorySize, SM64);
    cudaFuncSetAttribute(mma_gemm_kernel<64, 128, true, false, false, true, false>,
                         cudaFuncAttributeMaxDynamicSharedMemorySize, SM128);

    // table + weight transpose/split + CSR build + embedding
    dim3 tb(TAB, 2);
    build_table_kernel<<<tb, HH>>>(mlp_w1, mlp_b1, mlp_w2, mlp_b2);
    for (int i = 0; i < 2; i++) {
        transpose_w_kernel<<<64, 256>>>(lin1_w + (size_t)i * 16384, p_wh + WT_LIN1(i), p_wl + WT_LIN1(i), 128, 128);
        transpose_w_kernel<<<64, 256>>>(lin2_w + (size_t)i * 16384, p_wh + WT_LIN2(i), p_wl + WT_LIN2(i), 128, 128);
        transpose_w_kernel<<<64, 256>>>(lin_w  + (size_t)i * 16384, p_wh + WT_LIN(i),  p_wl + WT_LIN(i),  128, 128);
    }
    transpose_w_kernel<<<32, 256>>>(out1_w, p_wh + WT_OUT1, p_wl + WT_OUT1, 128, 64);
    transpose_w_kernel<<<32, 256>>>(out2_w, p_wh + WT_OUT2, p_wl + WT_OUT2, 64, 128);

    zero_int_kernel<<<(NN + 255) / 256, 256>>>(p_deg, NN);
    hist_kernel<<<(EE + 255) / 256, 256>>>(ei);
    scan1_kernel<<<NBLK, SCAN_B>>>();
    scan2_kernel<<<1, 32>>>();
    scan3_kernel<<<NBLK, SCAN_B>>>();
    fill_kernel<<<(EE + 255) / 256, 256>>>(ei, pos);
    embed_kernel<<<(NN * 32 + 255) / 256, 256>>>(z, emb);

    int gblocks = (NN + 127) / 128;
    for (int i = 0; i < 2; i++) {
        // xj = h @ lin1 -> bf16
        mma_gemm_kernel<128, 128, false, false, false, false, true><<<gblocks, 256, SM128>>>(
            p_h, p_wh + WT_LIN1(i), p_wl + WT_LIN1(i), nullptr, p_xjb, nullptr);
        // agg[n] = gather-sum over incident edges
        edge_conv_csr_kernel<<<smCount, 1024, TAB_SMEM>>>(i);
        // tmp = ssp(agg @ lin2 + b2)
        mma_gemm_kernel<128, 128, true, true, false, false, false><<<gblocks, 256, SM128>>>(
            p_agg, p_wh + WT_LIN2(i), p_wl + WT_LIN2(i), lin2_b + (size_t)i * HH, p_tmp, nullptr);
        // h += tmp @ lin + b
        mma_gemm_kernel<128, 128, true, false, true, false, false><<<gblocks, 256, SM128>>>(
            p_tmp, p_wh + WT_LIN(i), p_wl + WT_LIN(i), lin_b + (size_t)i * HH, p_h, nullptr);
    }

    zero_kernel<<<(BB * 32 + 255) / 256, 256>>>(p_pooled, BB * 32);
    // t1 = ssp(h @ out1 + b1)  [N,64]
    mma_gemm_kernel<128, 64, true, true, false, false, false><<<gblocks, 256, SM64>>>(
        p_h, p_wh + WT_OUT1, p_wl + WT_OUT1, out1_b, p_tmp, nullptr);
    // pooled[batch[n]] += t1 @ out2 + b2
    mma_gemm_kernel<64, 128, true, false, false, true, false><<<gblocks, 256, SM128>>>(
        p_tmp, p_wh + WT_OUT2, p_wl + WT_OUT2, out2_b, nullptr, batch);
    final_kernel<<<1, 256>>>(pred_w, pred_b, out);
}

// round 7
// speedup vs baseline: 2.2773x; 1.1253x over previous
#include <cuda_runtime.h>
#include <cuda_bf16.h>
#include <stdint.h>
#include <math.h>

#define NN 50000
#define EE 1600000
#define HH 128
#define BB 64
#define TT 4
#define GG 10
#define TAB 384
#define D_MAX 8.6603f
#define SCAN_B 1024
#define NBLK ((NN + SCAN_B - 1) / SCAN_B)

// scratch (static device globals — no runtime allocation)
static __device__ float g_table[2 * TAB * HH];
static __device__ float g_h[NN * HH];
static __device__ __nv_bfloat16 g_xjb[NN * HH];
static __device__ float g_agg[NN * HH];
static __device__ float g_pooled[BB * HH];
static __device__ __nv_bfloat16 g_wt_hi[7 * 16384];
static __device__ __nv_bfloat16 g_wt_lo[7 * 16384];
// CSR (dst-major)
static __device__ int  g_deg[NN];
static __device__ int  g_ptr[NN + 1];
static __device__ int  g_work[NN];
static __device__ int  g_bsum[NBLK];
static __device__ int2 g_csr[EE];        // {src | i0<<16, f(bits)}

#define WT_LIN1(i)  ((size_t)(i) * 16384)
#define WT_LIN2(i)  ((size_t)(32768) + (size_t)(i) * 16384)
#define WT_LIN(i)   ((size_t)(65536) + (size_t)(i) * 16384)
#define WT_OUT1     ((size_t)98304)
#define WT_OUT2     ((size_t)106496)

__device__ __forceinline__ float sspf(float x) {
    float ax = fabsf(x);
    return fmaxf(x, 0.0f) + log1pf(__expf(-ax)) - 0.6931471805599453f;
}

#define SWZ(off) ((off) ^ (((off) >> 3) & 0x70))

__device__ __forceinline__ unsigned smem_u32(const void* p) {
    return (unsigned)__cvta_generic_to_shared(p);
}
__device__ __forceinline__ void ldsm_x4(unsigned* r, unsigned addr) {
    asm volatile("ldmatrix.sync.aligned.m8n8.x4.shared.b16 {%0,%1,%2,%3}, [%4];"
                 : "=r"(r[0]), "=r"(r[1]), "=r"(r[2]), "=r"(r[3]) : "r"(addr));
}
__device__ __forceinline__ void ldsm_x2(unsigned* r, unsigned addr) {
    asm volatile("ldmatrix.sync.aligned.m8n8.x2.shared.b16 {%0,%1}, [%2];"
                 : "=r"(r[0]), "=r"(r[1]) : "r"(addr));
}
__device__ __forceinline__ void mma_bf16(float* d, const unsigned* a, const unsigned* b) {
    asm volatile("mma.sync.aligned.m16n8k16.row.col.f32.bf16.bf16.f32 "
                 "{%0,%1,%2,%3}, {%4,%5,%6,%7}, {%8,%9}, {%0,%1,%2,%3};"
                 : "+f"(d[0]), "+f"(d[1]), "+f"(d[2]), "+f"(d[3])
                 : "r"(a[0]), "r"(a[1]), "r"(a[2]), "r"(a[3]), "r"(b[0]), "r"(b[1]));
}

__device__ __forceinline__ void split_bf16(float x, __nv_bfloat16& hi, __nv_bfloat16& lo) {
    hi = __float2bfloat16(x);
    lo = __float2bfloat16(x - __bfloat162float(hi));
}

// ---------------------------------------------------------------------------
// Build filter table
// ---------------------------------------------------------------------------
__global__ void build_table_kernel(const float* __restrict__ w1, const float* __restrict__ b1,
                                   const float* __restrict__ w2, const float* __restrict__ b2) {
    int row = blockIdx.x;
    int inter = blockIdx.y;
    int tid = threadIdx.x;
    float d = row * (D_MAX / (float)(TAB - 1));

    __shared__ float hid[HH];
    const float* w1i = w1 + (size_t)inter * GG * HH;
    const float* b1i = b1 + (size_t)inter * HH;
    const float* w2i = w2 + (size_t)inter * HH * HH;
    const float* b2i = b2 + (size_t)inter * HH;

    const float step = 10.0f / 9.0f;
    const float coeff = -0.5f / (step * step);

    float acc = b1i[tid];
    #pragma unroll
    for (int g = 0; g < GG; g++) {
        float diff = d - (float)g * step;
        float r = expf(coeff * diff * diff);
        acc += r * w1i[g * HH + tid];
    }
    hid[tid] = sspf(acc);
    __syncthreads();

    float acc2 = b2i[tid];
    for (int k = 0; k < HH; k++)
        acc2 = fmaf(hid[k], w2i[k * HH + tid], acc2);

    float C = 0.5f * (cosf(d * 3.14159265358979f / 10.0f) + 1.0f);
    g_table[((size_t)inter * TAB + row) * HH + tid] = acc2 * C;
}

// ---------------------------------------------------------------------------
// Merged weight transpose + split-bf16: 8 matrices in one launch (grid.y)
// ---------------------------------------------------------------------------
__global__ void transpose_all_kernel(const float* __restrict__ lin1_w,
                                     const float* __restrict__ lin2_w,
                                     const float* __restrict__ lin_w,
                                     const float* __restrict__ out1_w,
                                     const float* __restrict__ out2_w,
                                     __nv_bfloat16* __restrict__ wh,
                                     __nv_bfloat16* __restrict__ wl) {
    int m = blockIdx.y;
    const float* src;
    size_t off;
    int K, N;
    switch (m) {
        case 0: src = lin1_w;          off = WT_LIN1(0); K = 128; N = 128; break;
        case 1: src = lin1_w + 16384;  off = WT_LIN1(1); K = 128; N = 128; break;
        case 2: src = lin2_w;          off = WT_LIN2(0); K = 128; N = 128; break;
        case 3: src = lin2_w + 16384;  off = WT_LIN2(1); K = 128; N = 128; break;
        case 4: src = lin_w;           off = WT_LIN(0);  K = 128; N = 128; break;
        case 5: src = lin_w + 16384;   off = WT_LIN(1);  K = 128; N = 128; break;
        case 6: src = out1_w;          off = WT_OUT1;    K = 128; N = 64;  break;
        default: src = out2_w;         off = WT_OUT2;    K = 64;  N = 128; break;
    }
    int i = blockIdx.x * blockDim.x + threadIdx.x;
    if (i >= K * N) return;
    int k = i / N, n = i % N;
    __nv_bfloat16 hi, lo;
    split_bf16(src[i], hi, lo);
    wh[off + (size_t)n * K + k] = hi;
    wl[off + (size_t)n * K + k] = lo;
}

// ---------------------------------------------------------------------------
// Fused prep: embedding gather + zero deg + zero pooled
// ---------------------------------------------------------------------------
__global__ void prep_kernel(const int* __restrict__ z, const float* __restrict__ emb) {
    int idx = blockIdx.x * blockDim.x + threadIdx.x;
    if (idx < NN * (HH / 4)) {
        int n = idx >> 5;
        int c = idx & 31;
        ((float4*)g_h)[idx] = ((const float4*)emb)[(size_t)z[n] * (HH / 4) + c];
    }
    if (idx < NN) g_deg[idx] = 0;
    if (idx < BB * HH) g_pooled[idx] = 0.f;
}

// ---------------------------------------------------------------------------
// CSR construction
// ---------------------------------------------------------------------------
__global__ void hist_kernel(const int* __restrict__ ei) {
    int e = blockIdx.x * blockDim.x + threadIdx.x;
    if (e >= EE) return;
    atomicAdd(&g_deg[ei[EE + e]], 1);
}

__global__ void scan1_kernel() {
    __shared__ int sm[SCAN_B];
    int idx = blockIdx.x * SCAN_B + threadIdx.x;
    int v = (idx < NN) ? g_deg[idx] : 0;
    sm[threadIdx.x] = v;
    __syncthreads();
    for (int off = SCAN_B / 2; off > 0; off >>= 1) {
        if (threadIdx.x < off) sm[threadIdx.x] += sm[threadIdx.x + off];
        __syncthreads();
    }
    if (threadIdx.x == 0) g_bsum[blockIdx.x] = sm[0];
}

__global__ void scan3_kernel() {   // intra-block scan + inline cross-block offset
    __shared__ int sm[SCAN_B];
    __shared__ int blockoff;
    int idx = blockIdx.x * SCAN_B + threadIdx.x;
    int v = (idx < NN) ? g_deg[idx] : 0;
    sm[threadIdx.x] = v;
    if (threadIdx.x == 0) {
        int run = 0;
        for (int b = 0; b < blockIdx.x; b++) run += g_bsum[b];
        blockoff = run;
    }
    __syncthreads();
    for (int off = 1; off < SCAN_B; off <<= 1) {
        int add = (threadIdx.x >= off) ? sm[threadIdx.x - off] : 0;
        __syncthreads();
        sm[threadIdx.x] += add;
        __syncthreads();
    }
    if (idx < NN) {
        int excl = blockoff + sm[threadIdx.x] - v;
        g_ptr[idx] = excl;
        g_work[idx] = excl;
        if (idx == NN - 1) g_ptr[NN] = blockoff + sm[threadIdx.x];
    }
}

__global__ void fill_kernel(const int* __restrict__ ei, const float* __restrict__ pos) {
    int e = blockIdx.x * blockDim.x + threadIdx.x;
    if (e >= EE) return;
    int s = ei[e];
    int d = ei[EE + e];
    float dx = pos[s * 3 + 0] - pos[d * 3 + 0];
    float dy = pos[s * 3 + 1] - pos[d * 3 + 1];
    float dz = pos[s * 3 + 2] - pos[d * 3 + 2];
    float dist = sqrtf(dx * dx + dy * dy + dz * dz);
    const float INV_STEP = (float)(TAB - 1) / D_MAX;
    float t = dist * INV_STEP;
    int i0 = min((int)t, TAB - 2);
    float f = t - (float)i0;
    int slot = atomicAdd(&g_work[d], 1);
    g_csr[slot] = make_int2(s | (i0 << 16), __float_as_int(f));
}

// ---------------------------------------------------------------------------
// CSR edge aggregation (gather-only), fp32 table in smem (196KB)
// ---------------------------------------------------------------------------
#define EDGE_BODY(J) {                                                              \
    int cx  = __shfl_sync(0xffffffffu, c.x, (J));                                   \
    int cyi = __shfl_sync(0xffffffffu, c.y, (J));                                   \
    int s  = cx & 0xffff;                                                           \
    int i0 = cx >> 16;                                                              \
    float f = __int_as_float(cyi);                                                  \
    uint2 xw = *(const uint2*)(g_xjb + (size_t)s * HH + lane * 4);                  \
    __nv_bfloat162 x01 = *reinterpret_cast<__nv_bfloat162*>(&xw.x);                 \
    __nv_bfloat162 x23 = *reinterpret_cast<__nv_bfloat162*>(&xw.y);                 \
    const float* t0 = tab + i0 * HH + lane * 4;                                     \
    float4 w0 = *(const float4*)t0;                                                 \
    float4 w1 = *(const float4*)(t0 + HH);                                          \
    acc.x = fmaf(__bfloat162float(x01.x), fmaf(w1.x - w0.x, f, w0.x), acc.x);       \
    acc.y = fmaf(__bfloat162float(x01.y), fmaf(w1.y - w0.y, f, w0.y), acc.y);       \
    acc.z = fmaf(__bfloat162float(x23.x), fmaf(w1.z - w0.z, f, w0.z), acc.z);       \
    acc.w = fmaf(__bfloat162float(x23.y), fmaf(w1.w - w0.w, f, w0.w), acc.w);       \
}

__global__ void __launch_bounds__(1024) edge_conv_csr_kernel(int inter) {
    extern __shared__ float tab[];
    const float4* src_tab = (const float4*)(g_table + (size_t)inter * TAB * HH);
    for (int i = threadIdx.x; i < TAB * HH / 4; i += 1024)
        ((float4*)tab)[i] = src_tab[i];
    __syncthreads();

    int lane = threadIdx.x & 31;
    int gwarp = blockIdx.x * 32 + (threadIdx.x >> 5);
    int nwarp = gridDim.x * 32;

    for (int node = gwarp; node < NN; node += nwarp) {
        int beg = __ldg(&g_ptr[node]);
        int end = __ldg(&g_ptr[node + 1]);

        float4 acc = make_float4(0.f, 0.f, 0.f, 0.f);
        int base = beg;
        // full chunks of 32 (unrolled for ILP)
        for (; base + 32 <= end; base += 32) {
            int2 c = __ldg(&g_csr[base + lane]);
            #pragma unroll 8
            for (int j = 0; j < 32; j++) EDGE_BODY(j);
        }
        // tail
        if (base < end) {
            int k = base + lane;
            int2 c = (k < end) ? __ldg(&g_csr[k]) : make_int2(0, 0);
            int cnt = end - base;
            for (int j = 0; j < cnt; j++) EDGE_BODY(j);
        }
        *(float4*)(g_agg + (size_t)node * HH + lane * 4) = acc;
    }
}

// ---------------------------------------------------------------------------
// Pair epilogue
// ---------------------------------------------------------------------------
template <int NCOL, bool BIAS, bool ACT, bool RESID, bool POOL, bool OBF16>
__device__ __forceinline__ void epi2(int row, int col, float v0, float v1,
                                     const float* __restrict__ bias, void* outv,
                                     const int* __restrict__ batch) {
    if (row >= NN) return;
    if (BIAS) { v0 += bias[col]; v1 += bias[col + 1]; }
    if (ACT)  { v0 = sspf(v0); v1 = sspf(v1); }
    if (POOL) {
        int b = batch[row];
        float* p = g_pooled + (size_t)b * NCOL + col;
        asm volatile("red.global.add.v2.f32 [%0], {%1,%2};" :: "l"(p), "f"(v0), "f"(v1) : "memory");
    } else if (OBF16) {
        __nv_bfloat162 pk = __floats2bfloat162_rn(v0, v1);
        *(unsigned*)((__nv_bfloat16*)outv + (size_t)row * NCOL + col) = *(unsigned*)&pk;
    } else {
        float* o = (float*)outv + (size_t)row * NCOL + col;
        if (RESID) {
            float2 h = *(float2*)o;
            v0 += h.x; v1 += h.y;
        }
        *(float2*)o = make_float2(v0, v1);
    }
}

// ---------------------------------------------------------------------------
// Split-bf16 tensor-core GEMM (3-term emulation) — standalone (for lin1 -> xjb)
// ---------------------------------------------------------------------------
template <int KDIM, int NCOL, bool BIAS, bool ACT, bool RESID, bool POOL, bool OBF16>
__global__ void __launch_bounds__(256)
mma_gemm_kernel(const float* __restrict__ A,
                const __nv_bfloat16* __restrict__ Wt_hi,
                const __nv_bfloat16* __restrict__ Wt_lo,
                const float* __restrict__ bias, void* outv, const int* __restrict__ batch) {
    constexpr int KC = 64;
    constexpr int WN = NCOL / 2;
    constexpr int NT = WN / 8;
    constexpr int A_BYTES = 128 * KC * 2;
    constexpr int B_BYTES = NCOL * KC * 2;

    extern __shared__ char dynsm[];
    char* As_hi = dynsm;
    char* As_lo = dynsm + A_BYTES;
    char* Bs_hi = dynsm + 2 * A_BYTES;
    char* Bs_lo = dynsm + 2 * A_BYTES + B_BYTES;

    int tid = threadIdx.x;
    int warp = tid >> 5, lane = tid & 31;
    int wm = warp & 3, wn = warp >> 2;
    int row0 = blockIdx.x * 128;

    float acc[2][NT][4];
    #pragma unroll
    for (int mt = 0; mt < 2; mt++)
        #pragma unroll
        for (int nt = 0; nt < NT; nt++)
            #pragma unroll
            for (int q = 0; q < 4; q++) acc[mt][nt][q] = 0.f;

    unsigned ah_base = smem_u32(As_hi);
    unsigned al_base = smem_u32(As_lo);
    unsigned bh_base = smem_u32(Bs_hi);
    unsigned bl_base = smem_u32(Bs_lo);

    for (int k0 = 0; k0 < KDIM; k0 += KC) {
        #pragma unroll
        for (int i = tid; i < 128 * 8; i += 256) {
            int r = i >> 3, ch = i & 7;
            int grow = row0 + r;
            float v[8] = {0.f, 0.f, 0.f, 0.f, 0.f, 0.f, 0.f, 0.f};
            if (grow < NN) {
                const float* gp = A + (size_t)grow * KDIM + k0 + ch * 8;
                float4 f0 = *(const float4*)gp;
                float4 f1 = *(const float4*)(gp + 4);
                v[0] = f0.x; v[1] = f0.y; v[2] = f0.z; v[3] = f0.w;
                v[4] = f1.x; v[5] = f1.y; v[6] = f1.z; v[7] = f1.w;
            }
            __nv_bfloat16 hi[8], lo[8];
            #pragma unroll
            for (int q = 0; q < 8; q++) split_bf16(v[q], hi[q], lo[q]);
            int off = SWZ(r * 128 + ch * 16);
            *(uint4*)(As_hi + off) = *(uint4*)hi;
            *(uint4*)(As_lo + off) = *(uint4*)lo;
        }
        #pragma unroll
        for (int i = tid; i < NCOL * 8; i += 256) {
            int r = i >> 3, ch = i & 7;
            size_t gidx = (size_t)r * KDIM + k0 + ch * 8;
            int off = SWZ(r * 128 + ch * 16);
            *(uint4*)(Bs_hi + off) = *(const uint4*)(Wt_hi + gidx);
            *(uint4*)(Bs_lo + off) = *(const uint4*)(Wt_lo + gidx);
        }
        __syncthreads();

        #pragma unroll
        for (int ks = 0; ks < KC / 16; ks++) {
            unsigned ah[2][4], al[2][4];
            #pragma unroll
            for (int mt = 0; mt < 2; mt++) {
                int r = wm * 32 + mt * 16 + (lane & 15);
                int off = SWZ(r * 128 + ks * 32 + (lane >> 4) * 16);
                ldsm_x4(ah[mt], ah_base + off);
                ldsm_x4(al[mt], al_base + off);
            }
            #pragma unroll
            for (int nt = 0; nt < NT; nt++) {
                unsigned bh[2], bl[2];
                int l = lane & 15;
                int r = wn * WN + nt * 8 + (l & 7);
                int off = SWZ(r * 128 + ks * 32 + ((l >> 3) & 1) * 16);
                ldsm_x2(bh, bh_base + off);
                ldsm_x2(bl, bl_base + off);
                #pragma unroll
                for (int mt = 0; mt < 2; mt++) {
                    mma_bf16(acc[mt][nt], ah[mt], bh);
                    mma_bf16(acc[mt][nt], al[mt], bh);
                    mma_bf16(acc[mt][nt], ah[mt], bl);
                }
            }
        }
        __syncthreads();
    }

    #pragma unroll
    for (int mt = 0; mt < 2; mt++) {
        #pragma unroll
        for (int nt = 0; nt < NT; nt++) {
            int r = row0 + wm * 32 + mt * 16 + (lane >> 2);
            int c = wn * WN + nt * 8 + (lane & 3) * 2;
            epi2<NCOL, BIAS, ACT, RESID, POOL, OBF16>(r, c, acc[mt][nt][0], acc[mt][nt][1], bias, outv, batch);
            epi2<NCOL, BIAS, ACT, RESID, POOL, OBF16>(r + 8, c, acc[mt][nt][2], acc[mt][nt][3], bias, outv, batch);
        }
    }
}

// ---------------------------------------------------------------------------
// Fused two-GEMM chain (row-local): T = ssp(A@W1 + b1); out2 = T@W2 + b2
//   POOL2=false: outh[r] += (T@W2 + b2)   (residual h update)
//   POOL2=true : pooled[batch[r]] += (T@W2 + b2)
// T kept in smem as split-bf16, 128B-row swizzled panels of 64 K each.
// ---------------------------------------------------------------------------
template <int K1, int N1, int N2, bool POOL2>
__global__ void __launch_bounds__(256)
fused2_kernel(const float* __restrict__ A,
              const __nv_bfloat16* __restrict__ W1h, const __nv_bfloat16* __restrict__ W1l,
              const float* __restrict__ b1,
              const __nv_bfloat16* __restrict__ W2h, const __nv_bfloat16* __restrict__ W2l,
              const float* __restrict__ b2,
              float* __restrict__ outh, const int* __restrict__ batch) {
    constexpr int WN1 = N1 / 2, NT1 = WN1 / 8;
    constexpr int WN2 = N2 / 2, NT2 = WN2 / 8;
    constexpr int A_B = 128 * 64 * 2;                       // 16384
    constexpr int B_B = (N1 > N2 ? N1 : N2) * 64 * 2;
    constexpr int T_B = 128 * N1 * 2;
    constexpr int PANEL = 128 * 64 * 2;                     // 16384 per 64-K panel

    extern __shared__ char dynsm[];
    char* As_hi = dynsm;
    char* As_lo = dynsm + A_B;
    char* Bs_hi = dynsm + 2 * A_B;
    char* Bs_lo = dynsm + 2 * A_B + B_B;
    char* Ts_hi = dynsm + 2 * A_B + 2 * B_B;
    char* Ts_lo = dynsm + 2 * A_B + 2 * B_B + T_B;

    int tid = threadIdx.x;
    int warp = tid >> 5, lane = tid & 31;
    int wm = warp & 3, wn = warp >> 2;
    int row0 = blockIdx.x * 128;

    unsigned ah_base = smem_u32(As_hi);
    unsigned al_base = smem_u32(As_lo);
    unsigned bh_base = smem_u32(Bs_hi);
    unsigned bl_base = smem_u32(Bs_lo);
    unsigned th_base = smem_u32(Ts_hi);
    unsigned tl_base = smem_u32(Ts_lo);

    // ---------------- stage 1: acc1 = A @ W1 ----------------
    float acc1[2][NT1][4];
    #pragma unroll
    for (int mt = 0; mt < 2; mt++)
        #pragma unroll
        for (int nt = 0; nt < NT1; nt++)
            #pragma unroll
            for (int q = 0; q < 4; q++) acc1[mt][nt][q] = 0.f;

    for (int k0 = 0; k0 < K1; k0 += 64) {
        #pragma unroll
        for (int i = tid; i < 128 * 8; i += 256) {
            int r = i >> 3, ch = i & 7;
            int grow = row0 + r;
            float v[8] = {0.f, 0.f, 0.f, 0.f, 0.f, 0.f, 0.f, 0.f};
            if (grow < NN) {
                const float* gp = A + (size_t)grow * K1 + k0 + ch * 8;
                float4 f0 = *(const float4*)gp;
                float4 f1 = *(const float4*)(gp + 4);
                v[0] = f0.x; v[1] = f0.y; v[2] = f0.z; v[3] = f0.w;
                v[4] = f1.x; v[5] = f1.y; v[6] = f1.z; v[7] = f1.w;
            }
            __nv_bfloat16 hi[8], lo[8];
            #pragma unroll
            for (int q = 0; q < 8; q++) split_bf16(v[q], hi[q], lo[q]);
            int off = SWZ(r * 128 + ch * 16);
            *(uint4*)(As_hi + off) = *(uint4*)hi;
            *(uint4*)(As_lo + off) = *(uint4*)lo;
        }
        #pragma unroll
        for (int i = tid; i < N1 * 8; i += 256) {
            int r = i >> 3, ch = i & 7;
            size_t gidx = (size_t)r * K1 + k0 + ch * 8;
            int off = SWZ(r * 128 + ch * 16);
            *(uint4*)(Bs_hi + off) = *(const uint4*)(W1h + gidx);
            *(uint4*)(Bs_lo + off) = *(const uint4*)(W1l + gidx);
        }
        __syncthreads();

        #pragma unroll
        for (int ks = 0; ks < 4; ks++) {
            unsigned ah[2][4], al[2][4];
            #pragma unroll
            for (int mt = 0; mt < 2; mt++) {
                int r = wm * 32 + mt * 16 + (lane & 15);
                int off = SWZ(r * 128 + ks * 32 + (lane >> 4) * 16);
                ldsm_x4(ah[mt], ah_base + off);
                ldsm_x4(al[mt], al_base + off);
            }
            #pragma unroll
            for (int nt = 0; nt < NT1; nt++) {
                unsigned bh[2], bl[2];
                int l = lane & 15;
                int r = wn * WN1 + nt * 8 + (l & 7);
                int off = SWZ(r * 128 + ks * 32 + ((l >> 3) & 1) * 16);
                ldsm_x2(bh, bh_base + off);
                ldsm_x2(bl, bl_base + off);
                #pragma unroll
                for (int mt = 0; mt < 2; mt++) {
                    mma_bf16(acc1[mt][nt], ah[mt], bh);
                    mma_bf16(acc1[mt][nt], al[mt], bh);
                    mma_bf16(acc1[mt][nt], ah[mt], bl);
                }
            }
        }
        __syncthreads();
    }

    // epilogue 1: T = ssp(acc1 + b1) -> split-bf16 into Ts panels
    #pragma unroll
    for (int mt = 0; mt < 2; mt++) {
        #pragma unroll
        for (int nt = 0; nt < NT1; nt++) {
            int c = wn * WN1 + nt * 8 + (lane & 3) * 2;
            int panel_off = (c >> 6) * PANEL;
            int kk2 = (c & 63) * 2;
            #pragma unroll
            for (int half = 0; half < 2; half++) {
                int rl = wm * 32 + mt * 16 + (lane >> 2) + half * 8;
                float v0 = sspf(acc1[mt][nt][half * 2 + 0] + b1[c]);
                float v1 = sspf(acc1[mt][nt][half * 2 + 1] + b1[c + 1]);
                __nv_bfloat16 h0, l0, h1, l1;
                split_bf16(v0, h0, l0);
                split_bf16(v1, h1, l1);
                __nv_bfloat16 hp[2] = {h0, h1}, lp[2] = {l0, l1};
                int off = panel_off + SWZ(rl * 128 + kk2);
                *(unsigned*)(Ts_hi + off) = *(unsigned*)hp;
                *(unsigned*)(Ts_lo + off) = *(unsigned*)lp;
            }
        }
    }
    __syncthreads();

    // ---------------- stage 2: out = T @ W2 ----------------
    float acc2[2][NT2][4];
    #pragma unroll
    for (int mt = 0; mt < 2; mt++)
        #pragma unroll
        for (int nt = 0; nt < NT2; nt++)
            #pragma unroll
            for (int q = 0; q < 4; q++) acc2[mt][nt][q] = 0.f;

    for (int k0 = 0; k0 < N1; k0 += 64) {
        #pragma unroll
        for (int i = tid; i < N2 * 8; i += 256) {
            int r = i >> 3, ch = i & 7;
            size_t gidx = (size_t)r * N1 + k0 + ch * 8;
            int off = SWZ(r * 128 + ch * 16);
            *(uint4*)(Bs_hi + off) = *(const uint4*)(W2h + gidx);
            *(uint4*)(Bs_lo + off) = *(const uint4*)(W2l + gidx);
        }
        __syncthreads();

        int panel_off = (k0 >> 6) * PANEL;
        #pragma unroll
        for (int ks = 0; ks < 4; ks++) {
            unsigned ah[2][4], al[2][4];
            #pragma unroll
            for (int mt = 0; mt < 2; mt++) {
                int r = wm * 32 + mt * 16 + (lane & 15);
                int off = panel_off + SWZ(r * 128 + ks * 32 + (lane >> 4) * 16);
                ldsm_x4(ah[mt], th_base + off);
                ldsm_x4(al[mt], tl_base + off);
            }
            #pragma unroll
            for (int nt = 0; nt < NT2; nt++) {
                unsigned bh[2], bl[2];
                int l = lane & 15;
                int r = wn * WN2 + nt * 8 + (l & 7);
                int off = SWZ(r * 128 + ks * 32 + ((l >> 3) & 1) * 16);
                ldsm_x2(bh, bh_base + off);
                ldsm_x2(bl, bl_base + off);
                #pragma unroll
                for (int mt = 0; mt < 2; mt++) {
                    mma_bf16(acc2[mt][nt], ah[mt], bh);
                    mma_bf16(acc2[mt][nt], al[mt], bh);
                    mma_bf16(acc2[mt][nt], ah[mt], bl);
                }
            }
        }
        __syncthreads();
    }

    // epilogue 2
    #pragma unroll
    for (int mt = 0; mt < 2; mt++) {
        #pragma unroll
        for (int nt = 0; nt < NT2; nt++) {
            int r = row0 + wm * 32 + mt * 16 + (lane >> 2);
            int c = wn * WN2 + nt * 8 + (lane & 3) * 2;
            epi2<N2, true, false, !POOL2, POOL2, false>(r, c, acc2[mt][nt][0], acc2[mt][nt][1], b2, outh, batch);
            epi2<N2, true, false, !POOL2, POOL2, false>(r + 8, c, acc2[mt][nt][2], acc2[mt][nt][3], b2, outh, batch);
        }
    }
}

// ---------------------------------------------------------------------------
// Final tiny GEMM
// ---------------------------------------------------------------------------
__global__ void final_kernel(const float* __restrict__ pw, const float* __restrict__ pb,
                             float* __restrict__ out) {
    int tid = threadIdx.x;
    int b = tid >> 2;
    int t = tid & 3;
    float acc = pb[t];
    for (int k = 0; k < HH; k++)
        acc = fmaf(g_pooled[b * HH + k], pw[k * TT + t], acc);
    out[b * TT + t] = acc;
}

// ---------------------------------------------------------------------------
extern "C" void kernel_launch(void* const* d_in, const int* in_sizes, int n_in,
                              void* d_out, int out_size) {
    const int*   z       = (const int*)d_in[0];
    const float* pos     = (const float*)d_in[1];
    const int*   batch   = (const int*)d_in[2];
    const int*   ei      = (const int*)d_in[3];
    const float* emb     = (const float*)d_in[4];
    const float* mlp_w1  = (const float*)d_in[5];
    const float* mlp_b1  = (const float*)d_in[6];
    const float* mlp_w2  = (const float*)d_in[7];
    const float* mlp_b2  = (const float*)d_in[8];
    const float* lin1_w  = (const float*)d_in[9];
    const float* lin2_w  = (const float*)d_in[10];
    const float* lin2_b  = (const float*)d_in[11];
    const float* lin_w   = (const float*)d_in[12];
    const float* lin_b   = (const float*)d_in[13];
    const float* out1_w  = (const float*)d_in[14];
    const float* out1_b  = (const float*)d_in[15];
    const float* out2_w  = (const float*)d_in[16];
    const float* out2_b  = (const float*)d_in[17];
    const float* pred_w  = (const float*)d_in[18];
    const float* pred_b  = (const float*)d_in[19];
    float* out = (float*)d_out;

    float *p_h, *p_agg;
    void* p_xjb;
    __nv_bfloat16 *p_wh, *p_wl;
    cudaGetSymbolAddress((void**)&p_h, g_h);
    cudaGetSymbolAddress(&p_xjb, g_xjb);
    cudaGetSymbolAddress((void**)&p_agg, g_agg);
    cudaGetSymbolAddress((void**)&p_wh, g_wt_hi);
    cudaGetSymbolAddress((void**)&p_wl, g_wt_lo);

    int dev = 0, smCount = 148;
    cudaGetDevice(&dev);
    cudaDeviceGetAttribute(&smCount, cudaDevAttrMultiProcessorCount, dev);

    const int TAB_SMEM = TAB * HH * (int)sizeof(float);   // 196608
    cudaFuncSetAttribute(edge_conv_csr_kernel, cudaFuncAttributeMaxDynamicSharedMemorySize, TAB_SMEM);

    const int SM_LIN1 = (2 * 128 * 64 + 2 * 128 * 64) * 2;                  // 65536
    const int SM_FA   = 2 * 16384 + 2 * 16384 + 2 * 32768;                  // 131072
    const int SM_FB   = 2 * 16384 + 2 * 16384 + 2 * 16384;                  // 98304
    cudaFuncSetAttribute(mma_gemm_kernel<128, 128, false, false, false, false, true>,
                         cudaFuncAttributeMaxDynamicSharedMemorySize, SM_LIN1);
    cudaFuncSetAttribute(fused2_kernel<128, 128, 128, false>,
                         cudaFuncAttributeMaxDynamicSharedMemorySize, SM_FA);
    cudaFuncSetAttribute(fused2_kernel<128, 64, 128, true>,
                         cudaFuncAttributeMaxDynamicSharedMemorySize, SM_FB);

    // prep
    dim3 tb(TAB, 2);
    build_table_kernel<<<tb, HH>>>(mlp_w1, mlp_b1, mlp_w2, mlp_b2);
    dim3 tg(64, 8);
    transpose_all_kernel<<<tg, 256>>>(lin1_w, lin2_w, lin_w, out1_w, out2_w, p_wh, p_wl);
    prep_kernel<<<(NN * 32 + 255) / 256, 256>>>(z, emb);
    hist_kernel<<<(EE + 255) / 256, 256>>>(ei);
    scan1_kernel<<<NBLK, SCAN_B>>>();
    scan3_kernel<<<NBLK, SCAN_B>>>();
    fill_kernel<<<(EE + 255) / 256, 256>>>(ei, pos);

    int gblocks = (NN + 127) / 128;
    for (int i = 0; i < 2; i++) {
        // xj = h @ lin1 -> bf16
        mma_gemm_kernel<128, 128, false, false, false, false, true><<<gblocks, 256, SM_LIN1>>>(
            p_h, p_wh + WT_LIN1(i), p_wl + WT_LIN1(i), nullptr, p_xjb, nullptr);
        // agg[n] = gather-sum over incident edges
        edge_conv_csr_kernel<<<smCount, 1024, TAB_SMEM>>>(i);
        // h += ssp(agg @ lin2 + b2) @ lin + b    (fused two-GEMM chain)
        fused2_kernel<128, 128, 128, false><<<gblocks, 256, SM_FA>>>(
            p_agg,
            p_wh + WT_LIN2(i), p_wl + WT_LIN2(i), lin2_b + (size_t)i * HH,
            p_wh + WT_LIN(i),  p_wl + WT_LIN(i),  lin_b + (size_t)i * HH,
            p_h, nullptr);
    }

    // pooled[batch] += ssp(h @ out1 + b1) @ out2 + b2   (fused, pool epilogue)
    fused2_kernel<128, 64, 128, true><<<gblocks, 256, SM_FB>>>(
        p_h,
        p_wh + WT_OUT1, p_wl + WT_OUT1, out1_b,
        p_wh + WT_OUT2, p_wl + WT_OUT2, out2_b,
        nullptr, batch);
    final_kernel<<<1, 256>>>(pred_w, pred_b, out);
}

// round 8
// speedup vs baseline: 2.3108x; 1.0147x over previous
#include <cuda_runtime.h>
#include <cuda_bf16.h>
#include <cuda_fp16.h>
#include <stdint.h>
#include <math.h>

#define NN 50000
#define EE 1600000
#define HH 128
#define BB 64
#define TT 4
#define GG 10
#define TAB 384
#define D_MAX 8.6603f
#define SCAN_B 1024
#define NBLK ((NN + SCAN_B - 1) / SCAN_B)

// scratch (static device globals — no runtime allocation)
static __device__ float g_table[2 * TAB * HH];
static __device__ float g_h[NN * HH];
static __device__ __nv_bfloat16 g_xjb[NN * HH];
static __device__ float g_agg[NN * HH];
static __device__ float g_pooled[BB * HH];
static __device__ __nv_bfloat16 g_wt_hi[7 * 16384];
static __device__ __nv_bfloat16 g_wt_lo[7 * 16384];
// CSR (dst-major)
static __device__ int  g_deg[NN];
static __device__ int  g_ptr[NN + 1];
static __device__ int  g_work[NN];
static __device__ int  g_bsum[NBLK];
static __device__ int2 g_csr[EE];        // {src | i0<<16, f(bits)}

#define WT_LIN1(i)  ((size_t)(i) * 16384)
#define WT_LIN2(i)  ((size_t)(32768) + (size_t)(i) * 16384)
#define WT_LIN(i)   ((size_t)(65536) + (size_t)(i) * 16384)
#define WT_OUT1     ((size_t)98304)
#define WT_OUT2     ((size_t)106496)

__device__ __forceinline__ float sspf(float x) {
    float ax = fabsf(x);
    return fmaxf(x, 0.0f) + log1pf(__expf(-ax)) - 0.6931471805599453f;
}

#define SWZ(off) ((off) ^ (((off) >> 3) & 0x70))

__device__ __forceinline__ unsigned smem_u32(const void* p) {
    return (unsigned)__cvta_generic_to_shared(p);
}
__device__ __forceinline__ void ldsm_x4(unsigned* r, unsigned addr) {
    asm volatile("ldmatrix.sync.aligned.m8n8.x4.shared.b16 {%0,%1,%2,%3}, [%4];"
                 : "=r"(r[0]), "=r"(r[1]), "=r"(r[2]), "=r"(r[3]) : "r"(addr));
}
__device__ __forceinline__ void ldsm_x2(unsigned* r, unsigned addr) {
    asm volatile("ldmatrix.sync.aligned.m8n8.x2.shared.b16 {%0,%1}, [%2];"
                 : "=r"(r[0]), "=r"(r[1]) : "r"(addr));
}
__device__ __forceinline__ void mma_bf16(float* d, const unsigned* a, const unsigned* b) {
    asm volatile("mma.sync.aligned.m16n8k16.row.col.f32.bf16.bf16.f32 "
                 "{%0,%1,%2,%3}, {%4,%5,%6,%7}, {%8,%9}, {%0,%1,%2,%3};"
                 : "+f"(d[0]), "+f"(d[1]), "+f"(d[2]), "+f"(d[3])
                 : "r"(a[0]), "r"(a[1]), "r"(a[2]), "r"(a[3]), "r"(b[0]), "r"(b[1]));
}

__device__ __forceinline__ void split_bf16(float x, __nv_bfloat16& hi, __nv_bfloat16& lo) {
    hi = __float2bfloat16(x);
    lo = __float2bfloat16(x - __bfloat162float(hi));
}

// ---------------------------------------------------------------------------
// Build filter table
// ---------------------------------------------------------------------------
__global__ void build_table_kernel(const float* __restrict__ w1, const float* __restrict__ b1,
                                   const float* __restrict__ w2, const float* __restrict__ b2) {
    int row = blockIdx.x;
    int inter = blockIdx.y;
    int tid = threadIdx.x;
    float d = row * (D_MAX / (float)(TAB - 1));

    __shared__ float hid[HH];
    const float* w1i = w1 + (size_t)inter * GG * HH;
    const float* b1i = b1 + (size_t)inter * HH;
    const float* w2i = w2 + (size_t)inter * HH * HH;
    const float* b2i = b2 + (size_t)inter * HH;

    const float step = 10.0f / 9.0f;
    const float coeff = -0.5f / (step * step);

    float acc = b1i[tid];
    #pragma unroll
    for (int g = 0; g < GG; g++) {
        float diff = d - (float)g * step;
        float r = expf(coeff * diff * diff);
        acc += r * w1i[g * HH + tid];
    }
    hid[tid] = sspf(acc);
    __syncthreads();

    float acc2 = b2i[tid];
    for (int k = 0; k < HH; k++)
        acc2 = fmaf(hid[k], w2i[k * HH + tid], acc2);

    float C = 0.5f * (cosf(d * 3.14159265358979f / 10.0f) + 1.0f);
    g_table[((size_t)inter * TAB + row) * HH + tid] = acc2 * C;
}

// ---------------------------------------------------------------------------
// Merged weight transpose + split-bf16: 8 matrices in one launch (grid.y)
// ---------------------------------------------------------------------------
__global__ void transpose_all_kernel(const float* __restrict__ lin1_w,
                                     const float* __restrict__ lin2_w,
                                     const float* __restrict__ lin_w,
                                     const float* __restrict__ out1_w,
                                     const float* __restrict__ out2_w,
                                     __nv_bfloat16* __restrict__ wh,
                                     __nv_bfloat16* __restrict__ wl) {
    int m = blockIdx.y;
    const float* src;
    size_t off;
    int K, N;
    switch (m) {
        case 0: src = lin1_w;          off = WT_LIN1(0); K = 128; N = 128; break;
        case 1: src = lin1_w + 16384;  off = WT_LIN1(1); K = 128; N = 128; break;
        case 2: src = lin2_w;          off = WT_LIN2(0); K = 128; N = 128; break;
        case 3: src = lin2_w + 16384;  off = WT_LIN2(1); K = 128; N = 128; break;
        case 4: src = lin_w;           off = WT_LIN(0);  K = 128; N = 128; break;
        case 5: src = lin_w + 16384;   off = WT_LIN(1);  K = 128; N = 128; break;
        case 6: src = out1_w;          off = WT_OUT1;    K = 128; N = 64;  break;
        default: src = out2_w;         off = WT_OUT2;    K = 64;  N = 128; break;
    }
    int i = blockIdx.x * blockDim.x + threadIdx.x;
    if (i >= K * N) return;
    int k = i / N, n = i % N;
    __nv_bfloat16 hi, lo;
    split_bf16(src[i], hi, lo);
    wh[off + (size_t)n * K + k] = hi;
    wl[off + (size_t)n * K + k] = lo;
}

// ---------------------------------------------------------------------------
// Fused prep: embedding gather + zero deg + zero pooled
// ---------------------------------------------------------------------------
__global__ void prep_kernel(const int* __restrict__ z, const float* __restrict__ emb) {
    int idx = blockIdx.x * blockDim.x + threadIdx.x;
    if (idx < NN * (HH / 4)) {
        int n = idx >> 5;
        int c = idx & 31;
        ((float4*)g_h)[idx] = ((const float4*)emb)[(size_t)z[n] * (HH / 4) + c];
    }
    if (idx < NN) g_deg[idx] = 0;
    if (idx < BB * HH) g_pooled[idx] = 0.f;
}

// ---------------------------------------------------------------------------
// CSR construction (vectorized histogram: 4 edges/thread)
// ---------------------------------------------------------------------------
__global__ void hist_kernel(const int* __restrict__ ei) {
    int i = blockIdx.x * blockDim.x + threadIdx.x;
    if (i >= EE / 4) return;
    int4 d4 = ((const int4*)(ei + EE))[i];
    atomicAdd(&g_deg[d4.x], 1);
    atomicAdd(&g_deg[d4.y], 1);
    atomicAdd(&g_deg[d4.z], 1);
    atomicAdd(&g_deg[d4.w], 1);
}

__global__ void scan1_kernel() {
    __shared__ int sm[SCAN_B];
    int idx = blockIdx.x * SCAN_B + threadIdx.x;
    int v = (idx < NN) ? g_deg[idx] : 0;
    sm[threadIdx.x] = v;
    __syncthreads();
    for (int off = SCAN_B / 2; off > 0; off >>= 1) {
        if (threadIdx.x < off) sm[threadIdx.x] += sm[threadIdx.x + off];
        __syncthreads();
    }
    if (threadIdx.x == 0) g_bsum[blockIdx.x] = sm[0];
}

__global__ void scan3_kernel() {   // intra-block scan + inline cross-block offset
    __shared__ int sm[SCAN_B];
    __shared__ int blockoff;
    int idx = blockIdx.x * SCAN_B + threadIdx.x;
    int v = (idx < NN) ? g_deg[idx] : 0;
    sm[threadIdx.x] = v;
    if (threadIdx.x == 0) {
        int run = 0;
        for (int b = 0; b < blockIdx.x; b++) run += g_bsum[b];
        blockoff = run;
    }
    __syncthreads();
    for (int off = 1; off < SCAN_B; off <<= 1) {
        int add = (threadIdx.x >= off) ? sm[threadIdx.x - off] : 0;
        __syncthreads();
        sm[threadIdx.x] += add;
        __syncthreads();
    }
    if (idx < NN) {
        int excl = blockoff + sm[threadIdx.x] - v;
        g_ptr[idx] = excl;
        g_work[idx] = excl;
        if (idx == NN - 1) g_ptr[NN] = blockoff + sm[threadIdx.x];
    }
}

// vectorized fill: 4 edges/thread
__global__ void fill_kernel(const int* __restrict__ ei, const float* __restrict__ pos) {
    int i = blockIdx.x * blockDim.x + threadIdx.x;
    if (i >= EE / 4) return;
    int4 s4 = ((const int4*)ei)[i];
    int4 d4 = ((const int4*)(ei + EE))[i];
    const float INV_STEP = (float)(TAB - 1) / D_MAX;
    #pragma unroll
    for (int q = 0; q < 4; q++) {
        int s = (&s4.x)[q];
        int d = (&d4.x)[q];
        float dx = pos[s * 3 + 0] - pos[d * 3 + 0];
        float dy = pos[s * 3 + 1] - pos[d * 3 + 1];
        float dz = pos[s * 3 + 2] - pos[d * 3 + 2];
        float dist = sqrtf(dx * dx + dy * dy + dz * dz);
        float t = dist * INV_STEP;
        int i0 = min((int)t, TAB - 2);
        float f = t - (float)i0;
        int slot = atomicAdd(&g_work[d], 1);
        g_csr[slot] = make_int2(s | (i0 << 16), __float_as_int(f));
    }
}

// ---------------------------------------------------------------------------
// CSR edge aggregation (gather-only), fp16 table in smem (98KB)
// ---------------------------------------------------------------------------
#define EDGE_BODY(J) {                                                              \
    int cx  = __shfl_sync(0xffffffffu, c.x, (J));                                   \
    int cyi = __shfl_sync(0xffffffffu, c.y, (J));                                   \
    int s  = cx & 0xffff;                                                           \
    int i0 = cx >> 16;                                                              \
    float f = __int_as_float(cyi);                                                  \
    uint2 xw = *(const uint2*)(g_xjb + (size_t)s * HH + lane * 4);                  \
    __nv_bfloat162 x01 = *reinterpret_cast<__nv_bfloat162*>(&xw.x);                 \
    __nv_bfloat162 x23 = *reinterpret_cast<__nv_bfloat162*>(&xw.y);                 \
    const __half* t0 = tab + i0 * HH + lane * 4;                                    \
    uint2 w0w = *(const uint2*)t0;                                                  \
    uint2 w1w = *(const uint2*)(t0 + HH);                                           \
    float2 w0a = __half22float2(*reinterpret_cast<__half2*>(&w0w.x));               \
    float2 w0b = __half22float2(*reinterpret_cast<__half2*>(&w0w.y));               \
    float2 w1a = __half22float2(*reinterpret_cast<__half2*>(&w1w.x));               \
    float2 w1b = __half22float2(*reinterpret_cast<__half2*>(&w1w.y));               \
    acc.x = fmaf(__bfloat162float(x01.x), fmaf(w1a.x - w0a.x, f, w0a.x), acc.x);    \
    acc.y = fmaf(__bfloat162float(x01.y), fmaf(w1a.y - w0a.y, f, w0a.y), acc.y);    \
    acc.z = fmaf(__bfloat162float(x23.x), fmaf(w1b.x - w0b.x, f, w0b.x), acc.z);    \
    acc.w = fmaf(__bfloat162float(x23.y), fmaf(w1b.y - w0b.y, f, w0b.y), acc.w);    \
}

__global__ void __launch_bounds__(1024) edge_conv_csr_kernel(int inter) {
    extern __shared__ __half tab[];
    const float4* src_tab = (const float4*)(g_table + (size_t)inter * TAB * HH);
    for (int i = threadIdx.x; i < TAB * HH / 8; i += 1024) {
        float4 f0 = src_tab[i * 2];
        float4 f1 = src_tab[i * 2 + 1];
        __half2 hh[4];
        hh[0] = __floats2half2_rn(f0.x, f0.y);
        hh[1] = __floats2half2_rn(f0.z, f0.w);
        hh[2] = __floats2half2_rn(f1.x, f1.y);
        hh[3] = __floats2half2_rn(f1.z, f1.w);
        ((uint4*)tab)[i] = *(uint4*)hh;
    }
    __syncthreads();

    int lane = threadIdx.x & 31;
    int gwarp = blockIdx.x * 32 + (threadIdx.x >> 5);
    int nwarp = gridDim.x * 32;

    for (int node = gwarp; node < NN; node += nwarp) {
        int beg = __ldg(&g_ptr[node]);
        int end = __ldg(&g_ptr[node + 1]);

        float4 acc = make_float4(0.f, 0.f, 0.f, 0.f);
        int base = beg;
        for (; base + 32 <= end; base += 32) {
            int2 c = __ldg(&g_csr[base + lane]);
            #pragma unroll 8
            for (int j = 0; j < 32; j++) EDGE_BODY(j);
        }
        if (base < end) {
            int k = base + lane;
            int2 c = (k < end) ? __ldg(&g_csr[k]) : make_int2(0, 0);
            int cnt = end - base;
            for (int j = 0; j < cnt; j++) EDGE_BODY(j);
        }
        *(float4*)(g_agg + (size_t)node * HH + lane * 4) = acc;
    }
}

// ---------------------------------------------------------------------------
// Pair epilogue
// ---------------------------------------------------------------------------
template <int NCOL, bool BIAS, bool ACT, bool RESID, bool POOL, bool OBF16>
__device__ __forceinline__ void epi2(int row, int col, float v0, float v1,
                                     const float* __restrict__ bias, void* outv,
                                     const int* __restrict__ batch) {
    if (row >= NN) return;
    if (BIAS) { v0 += bias[col]; v1 += bias[col + 1]; }
    if (ACT)  { v0 = sspf(v0); v1 = sspf(v1); }
    if (POOL) {
        int b = batch[row];
        float* p = g_pooled + (size_t)b * NCOL + col;
        asm volatile("red.global.add.v2.f32 [%0], {%1,%2};" :: "l"(p), "f"(v0), "f"(v1) : "memory");
    } else if (OBF16) {
        __nv_bfloat162 pk = __floats2bfloat162_rn(v0, v1);
        *(unsigned*)((__nv_bfloat16*)outv + (size_t)row * NCOL + col) = *(unsigned*)&pk;
    } else {
        float* o = (float*)outv + (size_t)row * NCOL + col;
        if (RESID) {
            float2 h = *(float2*)o;
            v0 += h.x; v1 += h.y;
        }
        *(float2*)o = make_float2(v0, v1);
    }
}

// ---------------------------------------------------------------------------
// Split-bf16 tensor-core GEMM (3-term emulation) — standalone (for lin1 -> xjb)
// ---------------------------------------------------------------------------
template <int KDIM, int NCOL, bool BIAS, bool ACT, bool RESID, bool POOL, bool OBF16>
__global__ void __launch_bounds__(256)
mma_gemm_kernel(const float* __restrict__ A,
                const __nv_bfloat16* __restrict__ Wt_hi,
                const __nv_bfloat16* __restrict__ Wt_lo,
                const float* __restrict__ bias, void* outv, const int* __restrict__ batch) {
    constexpr int KC = 64;
    constexpr int WN = NCOL / 2;
    constexpr int NT = WN / 8;
    constexpr int A_BYTES = 128 * KC * 2;
    constexpr int B_BYTES = NCOL * KC * 2;

    extern __shared__ char dynsm[];
    char* As_hi = dynsm;
    char* As_lo = dynsm + A_BYTES;
    char* Bs_hi = dynsm + 2 * A_BYTES;
    char* Bs_lo = dynsm + 2 * A_BYTES + B_BYTES;

    int tid = threadIdx.x;
    int warp = tid >> 5, lane = tid & 31;
    int wm = warp & 3, wn = warp >> 2;
    int row0 = blockIdx.x * 128;

    float acc[2][NT][4];
    #pragma unroll
    for (int mt = 0; mt < 2; mt++)
        #pragma unroll
        for (int nt = 0; nt < NT; nt++)
            #pragma unroll
            for (int q = 0; q < 4; q++) acc[mt][nt][q] = 0.f;

    unsigned ah_base = smem_u32(As_hi);
    unsigned al_base = smem_u32(As_lo);
    unsigned bh_base = smem_u32(Bs_hi);
    unsigned bl_base = smem_u32(Bs_lo);

    for (int k0 = 0; k0 < KDIM; k0 += KC) {
        #pragma unroll
        for (int i = tid; i < 128 * 8; i += 256) {
            int r = i >> 3, ch = i & 7;
            int grow = row0 + r;
            float v[8] = {0.f, 0.f, 0.f, 0.f, 0.f, 0.f, 0.f, 0.f};
            if (grow < NN) {
                const float* gp = A + (size_t)grow * KDIM + k0 + ch * 8;
                float4 f0 = *(const float4*)gp;
                float4 f1 = *(const float4*)(gp + 4);
                v[0] = f0.x; v[1] = f0.y; v[2] = f0.z; v[3] = f0.w;
                v[4] = f1.x; v[5] = f1.y; v[6] = f1.z; v[7] = f1.w;
            }
            __nv_bfloat16 hi[8], lo[8];
            #pragma unroll
            for (int q = 0; q < 8; q++) split_bf16(v[q], hi[q], lo[q]);
            int off = SWZ(r * 128 + ch * 16);
            *(uint4*)(As_hi + off) = *(uint4*)hi;
            *(uint4*)(As_lo + off) = *(uint4*)lo;
        }
        #pragma unroll
        for (int i = tid; i < NCOL * 8; i += 256) {
            int r = i >> 3, ch = i & 7;
            size_t gidx = (size_t)r * KDIM + k0 + ch * 8;
            int off = SWZ(r * 128 + ch * 16);
            *(uint4*)(Bs_hi + off) = *(const uint4*)(Wt_hi + gidx);
            *(uint4*)(Bs_lo + off) = *(const uint4*)(Wt_lo + gidx);
        }
        __syncthreads();

        #pragma unroll
        for (int ks = 0; ks < KC / 16; ks++) {
            unsigned ah[2][4], al[2][4];
            #pragma unroll
            for (int mt = 0; mt < 2; mt++) {
                int r = wm * 32 + mt * 16 + (lane & 15);
                int off = SWZ(r * 128 + ks * 32 + (lane >> 4) * 16);
                ldsm_x4(ah[mt], ah_base + off);
                ldsm_x4(al[mt], al_base + off);
            }
            #pragma unroll
            for (int nt = 0; nt < NT; nt++) {
                unsigned bh[2], bl[2];
                int l = lane & 15;
                int r = wn * WN + nt * 8 + (l & 7);
                int off = SWZ(r * 128 + ks * 32 + ((l >> 3) & 1) * 16);
                ldsm_x2(bh, bh_base + off);
                ldsm_x2(bl, bl_base + off);
                #pragma unroll
                for (int mt = 0; mt < 2; mt++) {
                    mma_bf16(acc[mt][nt], ah[mt], bh);
                    mma_bf16(acc[mt][nt], al[mt], bh);
                    mma_bf16(acc[mt][nt], ah[mt], bl);
                }
            }
        }
        __syncthreads();
    }

    #pragma unroll
    for (int mt = 0; mt < 2; mt++) {
        #pragma unroll
        for (int nt = 0; nt < NT; nt++) {
            int r = row0 + wm * 32 + mt * 16 + (lane >> 2);
            int c = wn * WN + nt * 8 + (lane & 3) * 2;
            epi2<NCOL, BIAS, ACT, RESID, POOL, OBF16>(r, c, acc[mt][nt][0], acc[mt][nt][1], bias, outv, batch);
            epi2<NCOL, BIAS, ACT, RESID, POOL, OBF16>(r + 8, c, acc[mt][nt][2], acc[mt][nt][3], bias, outv, batch);
        }
    }
}

// ---------------------------------------------------------------------------
// Fused two-GEMM chain (row-local): T = ssp(A@W1 + b1); out2 = T@W2 + b2
// ---------------------------------------------------------------------------
template <int K1, int N1, int N2, bool POOL2>
__global__ void __launch_bounds__(256)
fused2_kernel(const float* __restrict__ A,
              const __nv_bfloat16* __restrict__ W1h, const __nv_bfloat16* __restrict__ W1l,
              const float* __restrict__ b1,
              const __nv_bfloat16* __restrict__ W2h, const __nv_bfloat16* __restrict__ W2l,
              const float* __restrict__ b2,
              float* __restrict__ outh, const int* __restrict__ batch) {
    constexpr int WN1 = N1 / 2, NT1 = WN1 / 8;
    constexpr int WN2 = N2 / 2, NT2 = WN2 / 8;
    constexpr int A_B = 128 * 64 * 2;
    constexpr int B_B = (N1 > N2 ? N1 : N2) * 64 * 2;
    constexpr int T_B = 128 * N1 * 2;
    constexpr int PANEL = 128 * 64 * 2;

    extern __shared__ char dynsm[];
    char* As_hi = dynsm;
    char* As_lo = dynsm + A_B;
    char* Bs_hi = dynsm + 2 * A_B;
    char* Bs_lo = dynsm + 2 * A_B + B_B;
    char* Ts_hi = dynsm + 2 * A_B + 2 * B_B;
    char* Ts_lo = dynsm + 2 * A_B + 2 * B_B + T_B;

    int tid = threadIdx.x;
    int warp = tid >> 5, lane = tid & 31;
    int wm = warp & 3, wn = warp >> 2;
    int row0 = blockIdx.x * 128;

    unsigned ah_base = smem_u32(As_hi);
    unsigned al_base = smem_u32(As_lo);
    unsigned bh_base = smem_u32(Bs_hi);
    unsigned bl_base = smem_u32(Bs_lo);
    unsigned th_base = smem_u32(Ts_hi);
    unsigned tl_base = smem_u32(Ts_lo);

    float acc1[2][NT1][4];
    #pragma unroll
    for (int mt = 0; mt < 2; mt++)
        #pragma unroll
        for (int nt = 0; nt < NT1; nt++)
            #pragma unroll
            for (int q = 0; q < 4; q++) acc1[mt][nt][q] = 0.f;

    for (int k0 = 0; k0 < K1; k0 += 64) {
        #pragma unroll
        for (int i = tid; i < 128 * 8; i += 256) {
            int r = i >> 3, ch = i & 7;
            int grow = row0 + r;
            float v[8] = {0.f, 0.f, 0.f, 0.f, 0.f, 0.f, 0.f, 0.f};
            if (grow < NN) {
                const float* gp = A + (size_t)grow * K1 + k0 + ch * 8;
                float4 f0 = *(const float4*)gp;
                float4 f1 = *(const float4*)(gp + 4);
                v[0] = f0.x; v[1] = f0.y; v[2] = f0.z; v[3] = f0.w;
                v[4] = f1.x; v[5] = f1.y; v[6] = f1.z; v[7] = f1.w;
            }
            __nv_bfloat16 hi[8], lo[8];
            #pragma unroll
            for (int q = 0; q < 8; q++) split_bf16(v[q], hi[q], lo[q]);
            int off = SWZ(r * 128 + ch * 16);
            *(uint4*)(As_hi + off) = *(uint4*)hi;
            *(uint4*)(As_lo + off) = *(uint4*)lo;
        }
        #pragma unroll
        for (int i = tid; i < N1 * 8; i += 256) {
            int r = i >> 3, ch = i & 7;
            size_t gidx = (size_t)r * K1 + k0 + ch * 8;
            int off = SWZ(r * 128 + ch * 16);
            *(uint4*)(Bs_hi + off) = *(const uint4*)(W1h + gidx);
            *(uint4*)(Bs_lo + off) = *(const uint4*)(W1l + gidx);
        }
        __syncthreads();

        #pragma unroll
        for (int ks = 0; ks < 4; ks++) {
            unsigned ah[2][4], al[2][4];
            #pragma unroll
            for (int mt = 0; mt < 2; mt++) {
                int r = wm * 32 + mt * 16 + (lane & 15);
                int off = SWZ(r * 128 + ks * 32 + (lane >> 4) * 16);
                ldsm_x4(ah[mt], ah_base + off);
                ldsm_x4(al[mt], al_base + off);
            }
            #pragma unroll
            for (int nt = 0; nt < NT1; nt++) {
                unsigned bh[2], bl[2];
                int l = lane & 15;
                int r = wn * WN1 + nt * 8 + (l & 7);
                int off = SWZ(r * 128 + ks * 32 + ((l >> 3) & 1) * 16);
                ldsm_x2(bh, bh_base + off);
                ldsm_x2(bl, bl_base + off);
                #pragma unroll
                for (int mt = 0; mt < 2; mt++) {
                    mma_bf16(acc1[mt][nt], ah[mt], bh);
                    mma_bf16(acc1[mt][nt], al[mt], bh);
                    mma_bf16(acc1[mt][nt], ah[mt], bl);
                }
            }
        }
        __syncthreads();
    }

    #pragma unroll
    for (int mt = 0; mt < 2; mt++) {
        #pragma unroll
        for (int nt = 0; nt < NT1; nt++) {
            int c = wn * WN1 + nt * 8 + (lane & 3) * 2;
            int panel_off = (c >> 6) * PANEL;
            int kk2 = (c & 63) * 2;
            #pragma unroll
            for (int half = 0; half < 2; half++) {
                int rl = wm * 32 + mt * 16 + (lane >> 2) + half * 8;
                float v0 = sspf(acc1[mt][nt][half * 2 + 0] + b1[c]);
                float v1 = sspf(acc1[mt][nt][half * 2 + 1] + b1[c + 1]);
                __nv_bfloat16 h0, l0, h1, l1;
                split_bf16(v0, h0, l0);
                split_bf16(v1, h1, l1);
                __nv_bfloat16 hp[2] = {h0, h1}, lp[2] = {l0, l1};
                int off = panel_off + SWZ(rl * 128 + kk2);
                *(unsigned*)(Ts_hi + off) = *(unsigned*)hp;
                *(unsigned*)(Ts_lo + off) = *(unsigned*)lp;
            }
        }
    }
    __syncthreads();

    float acc2[2][NT2][4];
    #pragma unroll
    for (int mt = 0; mt < 2; mt++)
        #pragma unroll
        for (int nt = 0; nt < NT2; nt++)
            #pragma unroll
            for (int q = 0; q < 4; q++) acc2[mt][nt][q] = 0.f;

    for (int k0 = 0; k0 < N1; k0 += 64) {
        #pragma unroll
        for (int i = tid; i < N2 * 8; i += 256) {
            int r = i >> 3, ch = i & 7;
            size_t gidx = (size_t)r * N1 + k0 + ch * 8;
            int off = SWZ(r * 128 + ch * 16);
            *(uint4*)(Bs_hi + off) = *(const uint4*)(W2h + gidx);
            *(uint4*)(Bs_lo + off) = *(const uint4*)(W2l + gidx);
        }
        __syncthreads();

        int panel_off = (k0 >> 6) * PANEL;
        #pragma unroll
        for (int ks = 0; ks < 4; ks++) {
            unsigned ah[2][4], al[2][4];
            #pragma unroll
            for (int mt = 0; mt < 2; mt++) {
                int r = wm * 32 + mt * 16 + (lane & 15);
                int off = panel_off + SWZ(r * 128 + ks * 32 + (lane >> 4) * 16);
                ldsm_x4(ah[mt], th_base + off);
                ldsm_x4(al[mt], tl_base + off);
            }
            #pragma unroll
            for (int nt = 0; nt < NT2; nt++) {
                unsigned bh[2], bl[2];
                int l = lane & 15;
                int r = wn * WN2 + nt * 8 + (l & 7);
                int off = SWZ(r * 128 + ks * 32 + ((l >> 3) & 1) * 16);
                ldsm_x2(bh, bh_base + off);
                ldsm_x2(bl, bl_base + off);
                #pragma unroll
                for (int mt = 0; mt < 2; mt++) {
                    mma_bf16(acc2[mt][nt], ah[mt], bh);
                    mma_bf16(acc2[mt][nt], al[mt], bh);
                    mma_bf16(acc2[mt][nt], ah[mt], bl);
                }
            }
        }
        __syncthreads();
    }

    #pragma unroll
    for (int mt = 0; mt < 2; mt++) {
        #pragma unroll
        for (int nt = 0; nt < NT2; nt++) {
            int r = row0 + wm * 32 + mt * 16 + (lane >> 2);
            int c = wn * WN2 + nt * 8 + (lane & 3) * 2;
            epi2<N2, true, false, !POOL2, POOL2, false>(r, c, acc2[mt][nt][0], acc2[mt][nt][1], b2, outh, batch);
            epi2<N2, true, false, !POOL2, POOL2, false>(r + 8, c, acc2[mt][nt][2], acc2[mt][nt][3], b2, outh, batch);
        }
    }
}

// ---------------------------------------------------------------------------
// Final tiny GEMM
// ---------------------------------------------------------------------------
__global__ void final_kernel(const float* __restrict__ pw, const float* __restrict__ pb,
                             float* __restrict__ out) {
    int tid = threadIdx.x;
    int b = tid >> 2;
    int t = tid & 3;
    float acc = pb[t];
    for (int k = 0; k < HH; k++)
        acc = fmaf(g_pooled[b * HH + k], pw[k * TT + t], acc);
    out[b * TT + t] = acc;
}

// ---------------------------------------------------------------------------
extern "C" void kernel_launch(void* const* d_in, const int* in_sizes, int n_in,
                              void* d_out, int out_size) {
    const int*   z       = (const int*)d_in[0];
    const float* pos     = (const float*)d_in[1];
    const int*   batch   = (const int*)d_in[2];
    const int*   ei      = (const int*)d_in[3];
    const float* emb     = (const float*)d_in[4];
    const float* mlp_w1  = (const float*)d_in[5];
    const float* mlp_b1  = (const float*)d_in[6];
    const float* mlp_w2  = (const float*)d_in[7];
    const float* mlp_b2  = (const float*)d_in[8];
    const float* lin1_w  = (const float*)d_in[9];
    const float* lin2_w  = (const float*)d_in[10];
    const float* lin2_b  = (const float*)d_in[11];
    const float* lin_w   = (const float*)d_in[12];
    const float* lin_b   = (const float*)d_in[13];
    const float* out1_w  = (const float*)d_in[14];
    const float* out1_b  = (const float*)d_in[15];
    const float* out2_w  = (const float*)d_in[16];
    const float* out2_b  = (const float*)d_in[17];
    const float* pred_w  = (const float*)d_in[18];
    const float* pred_b  = (const float*)d_in[19];
    float* out = (float*)d_out;

    float *p_h, *p_agg;
    void* p_xjb;
    __nv_bfloat16 *p_wh, *p_wl;
    cudaGetSymbolAddress((void**)&p_h, g_h);
    cudaGetSymbolAddress(&p_xjb, g_xjb);
    cudaGetSymbolAddress((void**)&p_agg, g_agg);
    cudaGetSymbolAddress((void**)&p_wh, g_wt_hi);
    cudaGetSymbolAddress((void**)&p_wl, g_wt_lo);

    int dev = 0, smCount = 148;
    cudaGetDevice(&dev);
    cudaDeviceGetAttribute(&smCount, cudaDevAttrMultiProcessorCount, dev);

    const int TAB_SMEM = TAB * HH * (int)sizeof(__half);   // 98304
    cudaFuncSetAttribute(edge_conv_csr_kernel, cudaFuncAttributeMaxDynamicSharedMemorySize, TAB_SMEM);

    const int SM_LIN1 = (2 * 128 * 64 + 2 * 128 * 64) * 2;                  // 65536
    const int SM_FA   = 2 * 16384 + 2 * 16384 + 2 * 32768;                  // 131072
    const int SM_FB   = 2 * 16384 + 2 * 16384 + 2 * 16384;                  // 98304
    cudaFuncSetAttribute(mma_gemm_kernel<128, 128, false, false, false, false, true>,
                         cudaFuncAttributeMaxDynamicSharedMemorySize, SM_LIN1);
    cudaFuncSetAttribute(fused2_kernel<128, 128, 128, false>,
                         cudaFuncAttributeMaxDynamicSharedMemorySize, SM_FA);
    cudaFuncSetAttribute(fused2_kernel<128, 64, 128, true>,
                         cudaFuncAttributeMaxDynamicSharedMemorySize, SM_FB);

    // prep
    dim3 tb(TAB, 2);
    build_table_kernel<<<tb, HH>>>(mlp_w1, mlp_b1, mlp_w2, mlp_b2);
    dim3 tg(64, 8);
    transpose_all_kernel<<<tg, 256>>>(lin1_w, lin2_w, lin_w, out1_w, out2_w, p_wh, p_wl);
    prep_kernel<<<(NN * 32 + 255) / 256, 256>>>(z, emb);
    hist_kernel<<<(EE / 4 + 255) / 256, 256>>>(ei);
    scan1_kernel<<<NBLK, SCAN_B>>>();
    scan3_kernel<<<NBLK, SCAN_B>>>();
    fill_kernel<<<(EE / 4 + 255) / 256, 256>>>(ei, pos);

    int gblocks = (NN + 127) / 128;
    for (int i = 0; i < 2; i++) {
        mma_gemm_kernel<128, 128, false, false, false, false, true><<<gblocks, 256, SM_LIN1>>>(
            p_h, p_wh + WT_LIN1(i), p_wl + WT_LIN1(i), nullptr, p_xjb, nullptr);
        edge_conv_csr_kernel<<<smCount, 1024, TAB_SMEM>>>(i);
        fused2_kernel<128, 128, 128, false><<<gblocks, 256, SM_FA>>>(
            p_agg,
            p_wh + WT_LIN2(i), p_wl + WT_LIN2(i), lin2_b + (size_t)i * HH,
            p_wh + WT_LIN(i),  p_wl + WT_LIN(i),  lin_b + (size_t)i * HH,
            p_h, nullptr);
    }

    fused2_kernel<128, 64, 128, true><<<gblocks, 256, SM_FB>>>(
        p_h,
        p_wh + WT_OUT1, p_wl + WT_OUT1, out1_b,
        p_wh + WT_OUT2, p_wl + WT_OUT2, out2_b,
        nullptr, batch);
    final_kernel<<<1, 256>>>(pred_w, pred_b, out);
}

// round 9
// speedup vs baseline: 2.5771x; 1.1153x over previous
#include <cuda_runtime.h>
#include <cuda_bf16.h>
#include <cuda_fp16.h>
#include <stdint.h>
#include <math.h>

#define NN 50000
#define EE 1600000
#define HH 128
#define BB 64
#define TT 4
#define GG 10
#define TAB 384
#define D_MAX 8.6603f
#define SCAN_B 1024
#define NBLK ((NN + SCAN_B - 1) / SCAN_B)

// scratch (static device globals — no runtime allocation)
static __device__ float g_table[2 * TAB * HH];
static __device__ float g_h[NN * HH];
static __device__ __half g_xjh[NN * HH];
static __device__ float g_agg[NN * HH];
static __device__ float g_pooled[BB * HH];
static __device__ __half g_wt[7 * 16384];   // transposed fp16 weights
// CSR (dst-major)
static __device__ int  g_deg[NN];
static __device__ int  g_ptr[NN + 1];
static __device__ int  g_work[NN];
static __device__ int  g_bsum[NBLK];
static __device__ int2 g_csr[EE];        // {src | i0<<16, f(bits)}

#define WT_LIN1(i)  ((size_t)(i) * 16384)
#define WT_LIN2(i)  ((size_t)(32768) + (size_t)(i) * 16384)
#define WT_LIN(i)   ((size_t)(65536) + (size_t)(i) * 16384)
#define WT_OUT1     ((size_t)98304)
#define WT_OUT2     ((size_t)106496)

__device__ __forceinline__ float sspf(float x) {
    float ax = fabsf(x);
    return fmaxf(x, 0.0f) + log1pf(__expf(-ax)) - 0.6931471805599453f;
}

#define SWZ(off) ((off) ^ (((off) >> 3) & 0x70))

__device__ __forceinline__ unsigned smem_u32(const void* p) {
    return (unsigned)__cvta_generic_to_shared(p);
}
__device__ __forceinline__ void ldsm_x4(unsigned* r, unsigned addr) {
    asm volatile("ldmatrix.sync.aligned.m8n8.x4.shared.b16 {%0,%1,%2,%3}, [%4];"
                 : "=r"(r[0]), "=r"(r[1]), "=r"(r[2]), "=r"(r[3]) : "r"(addr));
}
__device__ __forceinline__ void ldsm_x2(unsigned* r, unsigned addr) {
    asm volatile("ldmatrix.sync.aligned.m8n8.x2.shared.b16 {%0,%1}, [%2];"
                 : "=r"(r[0]), "=r"(r[1]) : "r"(addr));
}
__device__ __forceinline__ void mma_fp16(float* d, const unsigned* a, const unsigned* b) {
    asm volatile("mma.sync.aligned.m16n8k16.row.col.f32.f16.f16.f32 "
                 "{%0,%1,%2,%3}, {%4,%5,%6,%7}, {%8,%9}, {%0,%1,%2,%3};"
                 : "+f"(d[0]), "+f"(d[1]), "+f"(d[2]), "+f"(d[3])
                 : "r"(a[0]), "r"(a[1]), "r"(a[2]), "r"(a[3]), "r"(b[0]), "r"(b[1]));
}

// ---------------------------------------------------------------------------
// Build filter table
// ---------------------------------------------------------------------------
__global__ void build_table_kernel(const float* __restrict__ w1, const float* __restrict__ b1,
                                   const float* __restrict__ w2, const float* __restrict__ b2) {
    int row = blockIdx.x;
    int inter = blockIdx.y;
    int tid = threadIdx.x;
    float d = row * (D_MAX / (float)(TAB - 1));

    __shared__ float hid[HH];
    const float* w1i = w1 + (size_t)inter * GG * HH;
    const float* b1i = b1 + (size_t)inter * HH;
    const float* w2i = w2 + (size_t)inter * HH * HH;
    const float* b2i = b2 + (size_t)inter * HH;

    const float step = 10.0f / 9.0f;
    const float coeff = -0.5f / (step * step);

    float acc = b1i[tid];
    #pragma unroll
    for (int g = 0; g < GG; g++) {
        float diff = d - (float)g * step;
        float r = expf(coeff * diff * diff);
        acc += r * w1i[g * HH + tid];
    }
    hid[tid] = sspf(acc);
    __syncthreads();

    float acc2 = b2i[tid];
    for (int k = 0; k < HH; k++)
        acc2 = fmaf(hid[k], w2i[k * HH + tid], acc2);

    float C = 0.5f * (cosf(d * 3.14159265358979f / 10.0f) + 1.0f);
    g_table[((size_t)inter * TAB + row) * HH + tid] = acc2 * C;
}

// ---------------------------------------------------------------------------
// Merged weight transpose + fp16 convert: 8 matrices in one launch (grid.y)
// ---------------------------------------------------------------------------
__global__ void transpose_all_kernel(const float* __restrict__ lin1_w,
                                     const float* __restrict__ lin2_w,
                                     const float* __restrict__ lin_w,
                                     const float* __restrict__ out1_w,
                                     const float* __restrict__ out2_w,
                                     __half* __restrict__ wt) {
    int m = blockIdx.y;
    const float* src;
    size_t off;
    int K, N;
    switch (m) {
        case 0: src = lin1_w;          off = WT_LIN1(0); K = 128; N = 128; break;
        case 1: src = lin1_w + 16384;  off = WT_LIN1(1); K = 128; N = 128; break;
        case 2: src = lin2_w;          off = WT_LIN2(0); K = 128; N = 128; break;
        case 3: src = lin2_w + 16384;  off = WT_LIN2(1); K = 128; N = 128; break;
        case 4: src = lin_w;           off = WT_LIN(0);  K = 128; N = 128; break;
        case 5: src = lin_w + 16384;   off = WT_LIN(1);  K = 128; N = 128; break;
        case 6: src = out1_w;          off = WT_OUT1;    K = 128; N = 64;  break;
        default: src = out2_w;         off = WT_OUT2;    K = 64;  N = 128; break;
    }
    int i = blockIdx.x * blockDim.x + threadIdx.x;
    if (i >= K * N) return;
    int k = i / N, n = i % N;
    wt[off + (size_t)n * K + k] = __float2half_rn(src[i]);
}

// ---------------------------------------------------------------------------
// Fused prep: embedding gather + zero deg + zero pooled
// ---------------------------------------------------------------------------
__global__ void prep_kernel(const int* __restrict__ z, const float* __restrict__ emb) {
    int idx = blockIdx.x * blockDim.x + threadIdx.x;
    if (idx < NN * (HH / 4)) {
        int n = idx >> 5;
        int c = idx & 31;
        ((float4*)g_h)[idx] = ((const float4*)emb)[(size_t)z[n] * (HH / 4) + c];
    }
    if (idx < NN) g_deg[idx] = 0;
    if (idx < BB * HH) g_pooled[idx] = 0.f;
}

// ---------------------------------------------------------------------------
// CSR construction
// ---------------------------------------------------------------------------
__global__ void hist_kernel(const int* __restrict__ ei) {
    int i = blockIdx.x * blockDim.x + threadIdx.x;
    if (i >= EE / 4) return;
    int4 d4 = ((const int4*)(ei + EE))[i];
    atomicAdd(&g_deg[d4.x], 1);
    atomicAdd(&g_deg[d4.y], 1);
    atomicAdd(&g_deg[d4.z], 1);
    atomicAdd(&g_deg[d4.w], 1);
}

__global__ void scan1_kernel() {
    __shared__ int sm[SCAN_B];
    int idx = blockIdx.x * SCAN_B + threadIdx.x;
    int v = (idx < NN) ? g_deg[idx] : 0;
    sm[threadIdx.x] = v;
    __syncthreads();
    for (int off = SCAN_B / 2; off > 0; off >>= 1) {
        if (threadIdx.x < off) sm[threadIdx.x] += sm[threadIdx.x + off];
        __syncthreads();
    }
    if (threadIdx.x == 0) g_bsum[blockIdx.x] = sm[0];
}

__global__ void scan3_kernel() {
    __shared__ int sm[SCAN_B];
    __shared__ int blockoff;
    int idx = blockIdx.x * SCAN_B + threadIdx.x;
    int v = (idx < NN) ? g_deg[idx] : 0;
    sm[threadIdx.x] = v;
    if (threadIdx.x == 0) {
        int run = 0;
        for (int b = 0; b < blockIdx.x; b++) run += g_bsum[b];
        blockoff = run;
    }
    __syncthreads();
    for (int off = 1; off < SCAN_B; off <<= 1) {
        int add = (threadIdx.x >= off) ? sm[threadIdx.x - off] : 0;
        __syncthreads();
        sm[threadIdx.x] += add;
        __syncthreads();
    }
    if (idx < NN) {
        int excl = blockoff + sm[threadIdx.x] - v;
        g_ptr[idx] = excl;
        g_work[idx] = excl;
        if (idx == NN - 1) g_ptr[NN] = blockoff + sm[threadIdx.x];
    }
}

__global__ void fill_kernel(const int* __restrict__ ei, const float* __restrict__ pos) {
    int i = blockIdx.x * blockDim.x + threadIdx.x;
    if (i >= EE / 4) return;
    int4 s4 = ((const int4*)ei)[i];
    int4 d4 = ((const int4*)(ei + EE))[i];
    const float INV_STEP = (float)(TAB - 1) / D_MAX;
    #pragma unroll
    for (int q = 0; q < 4; q++) {
        int s = (&s4.x)[q];
        int d = (&d4.x)[q];
        float dx = pos[s * 3 + 0] - pos[d * 3 + 0];
        float dy = pos[s * 3 + 1] - pos[d * 3 + 1];
        float dz = pos[s * 3 + 2] - pos[d * 3 + 2];
        float dist = sqrtf(dx * dx + dy * dy + dz * dz);
        float t = dist * INV_STEP;
        int i0 = min((int)t, TAB - 2);
        float f = t - (float)i0;
        int slot = atomicAdd(&g_work[d], 1);
        g_csr[slot] = make_int2(s | (i0 << 16), __float_as_int(f));
    }
}

// ---------------------------------------------------------------------------
// CSR edge aggregation (gather-only), fp16 table in smem (98KB), fp16 xj
// ---------------------------------------------------------------------------
#define EDGE_BODY(J) {                                                              \
    int cx  = __shfl_sync(0xffffffffu, c.x, (J));                                   \
    int cyi = __shfl_sync(0xffffffffu, c.y, (J));                                   \
    int s  = cx & 0xffff;                                                           \
    int i0 = cx >> 16;                                                              \
    float f = __int_as_float(cyi);                                                  \
    uint2 xw = *(const uint2*)(g_xjh + (size_t)s * HH + lane * 4);                  \
    float2 xa = __half22float2(*reinterpret_cast<__half2*>(&xw.x));                 \
    float2 xb = __half22float2(*reinterpret_cast<__half2*>(&xw.y));                 \
    const __half* t0 = tab + i0 * HH + lane * 4;                                    \
    uint2 w0w = *(const uint2*)t0;                                                  \
    uint2 w1w = *(const uint2*)(t0 + HH);                                           \
    float2 w0a = __half22float2(*reinterpret_cast<__half2*>(&w0w.x));               \
    float2 w0b = __half22float2(*reinterpret_cast<__half2*>(&w0w.y));               \
    float2 w1a = __half22float2(*reinterpret_cast<__half2*>(&w1w.x));               \
    float2 w1b = __half22float2(*reinterpret_cast<__half2*>(&w1w.y));               \
    acc.x = fmaf(xa.x, fmaf(w1a.x - w0a.x, f, w0a.x), acc.x);                       \
    acc.y = fmaf(xa.y, fmaf(w1a.y - w0a.y, f, w0a.y), acc.y);                       \
    acc.z = fmaf(xb.x, fmaf(w1b.x - w0b.x, f, w0b.x), acc.z);                       \
    acc.w = fmaf(xb.y, fmaf(w1b.y - w0b.y, f, w0b.y), acc.w);                       \
}

__global__ void __launch_bounds__(1024) edge_conv_csr_kernel(int inter) {
    extern __shared__ __half tab[];
    const float4* src_tab = (const float4*)(g_table + (size_t)inter * TAB * HH);
    for (int i = threadIdx.x; i < TAB * HH / 8; i += 1024) {
        float4 f0 = src_tab[i * 2];
        float4 f1 = src_tab[i * 2 + 1];
        __half2 hh[4];
        hh[0] = __floats2half2_rn(f0.x, f0.y);
        hh[1] = __floats2half2_rn(f0.z, f0.w);
        hh[2] = __floats2half2_rn(f1.x, f1.y);
        hh[3] = __floats2half2_rn(f1.z, f1.w);
        ((uint4*)tab)[i] = *(uint4*)hh;
    }
    __syncthreads();

    int lane = threadIdx.x & 31;
    int gwarp = blockIdx.x * 32 + (threadIdx.x >> 5);
    int nwarp = gridDim.x * 32;

    for (int node = gwarp; node < NN; node += nwarp) {
        int beg = __ldg(&g_ptr[node]);
        int end = __ldg(&g_ptr[node + 1]);

        float4 acc = make_float4(0.f, 0.f, 0.f, 0.f);
        int base = beg;
        for (; base + 32 <= end; base += 32) {
            int2 c = __ldg(&g_csr[base + lane]);
            #pragma unroll 8
            for (int j = 0; j < 32; j++) EDGE_BODY(j);
        }
        if (base < end) {
            int k = base + lane;
            int2 c = (k < end) ? __ldg(&g_csr[k]) : make_int2(0, 0);
            int cnt = end - base;
            for (int j = 0; j < cnt; j++) EDGE_BODY(j);
        }
        *(float4*)(g_agg + (size_t)node * HH + lane * 4) = acc;
    }
}

// ---------------------------------------------------------------------------
// Pair epilogue
// ---------------------------------------------------------------------------
template <int NCOL, bool BIAS, bool ACT, bool RESID, bool POOL, bool OFP16>
__device__ __forceinline__ void epi2(int row, int col, float v0, float v1,
                                     const float* __restrict__ bias, void* outv,
                                     const int* __restrict__ batch) {
    if (row >= NN) return;
    if (BIAS) { v0 += bias[col]; v1 += bias[col + 1]; }
    if (ACT)  { v0 = sspf(v0); v1 = sspf(v1); }
    if (POOL) {
        int b = batch[row];
        float* p = g_pooled + (size_t)b * NCOL + col;
        asm volatile("red.global.add.v2.f32 [%0], {%1,%2};" :: "l"(p), "f"(v0), "f"(v1) : "memory");
    } else if (OFP16) {
        __half2 pk = __floats2half2_rn(v0, v1);
        *(unsigned*)((__half*)outv + (size_t)row * NCOL + col) = *(unsigned*)&pk;
    } else {
        float* o = (float*)outv + (size_t)row * NCOL + col;
        if (RESID) {
            float2 h = *(float2*)o;
            v0 += h.x; v1 += h.y;
        }
        *(float2*)o = make_float2(v0, v1);
    }
}

// ---------------------------------------------------------------------------
// fp16 tensor-core GEMM (single-pass) — standalone (for lin1 -> xjh)
// ---------------------------------------------------------------------------
template <int KDIM, int NCOL, bool BIAS, bool ACT, bool RESID, bool POOL, bool OFP16>
__global__ void __launch_bounds__(256)
mma_gemm_kernel(const float* __restrict__ A,
                const __half* __restrict__ Wt,
                const float* __restrict__ bias, void* outv, const int* __restrict__ batch) {
    constexpr int KC = 64;
    constexpr int WN = NCOL / 2;
    constexpr int NT = WN / 8;
    constexpr int A_BYTES = 128 * KC * 2;

    extern __shared__ char dynsm[];
    char* As = dynsm;
    char* Bs = dynsm + A_BYTES;

    int tid = threadIdx.x;
    int warp = tid >> 5, lane = tid & 31;
    int wm = warp & 3, wn = warp >> 2;
    int row0 = blockIdx.x * 128;

    float acc[2][NT][4];
    #pragma unroll
    for (int mt = 0; mt < 2; mt++)
        #pragma unroll
        for (int nt = 0; nt < NT; nt++)
            #pragma unroll
            for (int q = 0; q < 4; q++) acc[mt][nt][q] = 0.f;

    unsigned as_base = smem_u32(As);
    unsigned bs_base = smem_u32(Bs);

    for (int k0 = 0; k0 < KDIM; k0 += KC) {
        #pragma unroll
        for (int i = tid; i < 128 * 8; i += 256) {
            int r = i >> 3, ch = i & 7;
            int grow = row0 + r;
            float v[8] = {0.f, 0.f, 0.f, 0.f, 0.f, 0.f, 0.f, 0.f};
            if (grow < NN) {
                const float* gp = A + (size_t)grow * KDIM + k0 + ch * 8;
                float4 f0 = *(const float4*)gp;
                float4 f1 = *(const float4*)(gp + 4);
                v[0] = f0.x; v[1] = f0.y; v[2] = f0.z; v[3] = f0.w;
                v[4] = f1.x; v[5] = f1.y; v[6] = f1.z; v[7] = f1.w;
            }
            __half2 hh[4];
            #pragma unroll
            for (int q = 0; q < 4; q++) hh[q] = __floats2half2_rn(v[2 * q], v[2 * q + 1]);
            *(uint4*)(As + SWZ(r * 128 + ch * 16)) = *(uint4*)hh;
        }
        #pragma unroll
        for (int i = tid; i < NCOL * 8; i += 256) {
            int r = i >> 3, ch = i & 7;
            uint4 w = *(const uint4*)(Wt + (size_t)r * KDIM + k0 + ch * 8);
            *(uint4*)(Bs + SWZ(r * 128 + ch * 16)) = w;
        }
        __syncthreads();

        #pragma unroll
        for (int ks = 0; ks < KC / 16; ks++) {
            unsigned a[2][4];
            #pragma unroll
            for (int mt = 0; mt < 2; mt++) {
                int r = wm * 32 + mt * 16 + (lane & 15);
                ldsm_x4(a[mt], as_base + SWZ(r * 128 + ks * 32 + (lane >> 4) * 16));
            }
            #pragma unroll
            for (int nt = 0; nt < NT; nt++) {
                unsigned b[2];
                int l = lane & 15;
                int r = wn * WN + nt * 8 + (l & 7);
                ldsm_x2(b, bs_base + SWZ(r * 128 + ks * 32 + ((l >> 3) & 1) * 16));
                mma_fp16(acc[0][nt], a[0], b);
                mma_fp16(acc[1][nt], a[1], b);
            }
        }
        __syncthreads();
    }

    #pragma unroll
    for (int mt = 0; mt < 2; mt++) {
        #pragma unroll
        for (int nt = 0; nt < NT; nt++) {
            int r = row0 + wm * 32 + mt * 16 + (lane >> 2);
            int c = wn * WN + nt * 8 + (lane & 3) * 2;
            epi2<NCOL, BIAS, ACT, RESID, POOL, OFP16>(r, c, acc[mt][nt][0], acc[mt][nt][1], bias, outv, batch);
            epi2<NCOL, BIAS, ACT, RESID, POOL, OFP16>(r + 8, c, acc[mt][nt][2], acc[mt][nt][3], bias, outv, batch);
        }
    }
}

// ---------------------------------------------------------------------------
// Fused two-GEMM chain (row-local): T = ssp(A@W1 + b1); out2 = T@W2 + b2
// T in smem fp16, 128B-row swizzled panels of 64 K each.
// ---------------------------------------------------------------------------
template <int K1, int N1, int N2, bool POOL2>
__global__ void __launch_bounds__(256)
fused2_kernel(const float* __restrict__ A,
              const __half* __restrict__ W1, const float* __restrict__ b1,
              const __half* __restrict__ W2, const float* __restrict__ b2,
              float* __restrict__ outh, const int* __restrict__ batch) {
    constexpr int WN1 = N1 / 2, NT1 = WN1 / 8;
    constexpr int WN2 = N2 / 2, NT2 = WN2 / 8;
    constexpr int A_B = 128 * 64 * 2;   // 16384
    constexpr int B_B = 16384;          // one 64-K panel of up to 128 rows
    constexpr int T_B = 128 * N1 * 2;
    constexpr int PANEL = 128 * 64 * 2; // 16384

    extern __shared__ char dynsm[];
    char* As = dynsm;
    char* Bs = dynsm + A_B;
    char* Ts = dynsm + A_B + B_B;

    int tid = threadIdx.x;
    int warp = tid >> 5, lane = tid & 31;
    int wm = warp & 3, wn = warp >> 2;
    int row0 = blockIdx.x * 128;

    unsigned as_base = smem_u32(As);
    unsigned bs_base = smem_u32(Bs);
    unsigned ts_base = smem_u32(Ts);

    // ---------------- stage 1: acc1 = A @ W1 ----------------
    float acc1[2][NT1][4];
    #pragma unroll
    for (int mt = 0; mt < 2; mt++)
        #pragma unroll
        for (int nt = 0; nt < NT1; nt++)
            #pragma unroll
            for (int q = 0; q < 4; q++) acc1[mt][nt][q] = 0.f;

    for (int k0 = 0; k0 < K1; k0 += 64) {
        #pragma unroll
        for (int i = tid; i < 128 * 8; i += 256) {
            int r = i >> 3, ch = i & 7;
            int grow = row0 + r;
            float v[8] = {0.f, 0.f, 0.f, 0.f, 0.f, 0.f, 0.f, 0.f};
            if (grow < NN) {
                const float* gp = A + (size_t)grow * K1 + k0 + ch * 8;
                float4 f0 = *(const float4*)gp;
                float4 f1 = *(const float4*)(gp + 4);
                v[0] = f0.x; v[1] = f0.y; v[2] = f0.z; v[3] = f0.w;
                v[4] = f1.x; v[5] = f1.y; v[6] = f1.z; v[7] = f1.w;
            }
            __half2 hh[4];
            #pragma unroll
            for (int q = 0; q < 4; q++) hh[q] = __floats2half2_rn(v[2 * q], v[2 * q + 1]);
            *(uint4*)(As + SWZ(r * 128 + ch * 16)) = *(uint4*)hh;
        }
        #pragma unroll
        for (int i = tid; i < N1 * 8; i += 256) {
            int r = i >> 3, ch = i & 7;
            uint4 w = *(const uint4*)(W1 + (size_t)r * K1 + k0 + ch * 8);
            *(uint4*)(Bs + SWZ(r * 128 + ch * 16)) = w;
        }
        __syncthreads();

        #pragma unroll
        for (int ks = 0; ks < 4; ks++) {
            unsigned a[2][4];
            #pragma unroll
            for (int mt = 0; mt < 2; mt++) {
                int r = wm * 32 + mt * 16 + (lane & 15);
                ldsm_x4(a[mt], as_base + SWZ(r * 128 + ks * 32 + (lane >> 4) * 16));
            }
            #pragma unroll
            for (int nt = 0; nt < NT1; nt++) {
                unsigned b[2];
                int l = lane & 15;
                int r = wn * WN1 + nt * 8 + (l & 7);
                ldsm_x2(b, bs_base + SWZ(r * 128 + ks * 32 + ((l >> 3) & 1) * 16));
                mma_fp16(acc1[0][nt], a[0], b);
                mma_fp16(acc1[1][nt], a[1], b);
            }
        }
        __syncthreads();
    }

    // epilogue 1: T = ssp(acc1 + b1) -> fp16 into Ts panels
    #pragma unroll
    for (int mt = 0; mt < 2; mt++) {
        #pragma unroll
        for (int nt = 0; nt < NT1; nt++) {
            int c = wn * WN1 + nt * 8 + (lane & 3) * 2;
            int panel_off = (c >> 6) * PANEL;
            int kk2 = (c & 63) * 2;
            #pragma unroll
            for (int half = 0; half < 2; half++) {
                int rl = wm * 32 + mt * 16 + (lane >> 2) + half * 8;
                float v0 = sspf(acc1[mt][nt][half * 2 + 0] + b1[c]);
                float v1 = sspf(acc1[mt][nt][half * 2 + 1] + b1[c + 1]);
                __half2 pk = __floats2half2_rn(v0, v1);
                *(unsigned*)(Ts + panel_off + SWZ(rl * 128 + kk2)) = *(unsigned*)&pk;
            }
        }
    }
    __syncthreads();

    // ---------------- stage 2: out = T @ W2 ----------------
    float acc2[2][NT2][4];
    #pragma unroll
    for (int mt = 0; mt < 2; mt++)
        #pragma unroll
        for (int nt = 0; nt < NT2; nt++)
            #pragma unroll
            for (int q = 0; q < 4; q++) acc2[mt][nt][q] = 0.f;

    for (int k0 = 0; k0 < N1; k0 += 64) {
        #pragma unroll
        for (int i = tid; i < N2 * 8; i += 256) {
            int r = i >> 3, ch = i & 7;
            uint4 w = *(const uint4*)(W2 + (size_t)r * N1 + k0 + ch * 8);
            *(uint4*)(Bs + SWZ(r * 128 + ch * 16)) = w;
        }
        __syncthreads();

        int panel_off = (k0 >> 6) * PANEL;
        #pragma unroll
        for (int ks = 0; ks < 4; ks++) {
            unsigned a[2][4];
            #pragma unroll
            for (int mt = 0; mt < 2; mt++) {
                int r = wm * 32 + mt * 16 + (lane & 15);
                ldsm_x4(a[mt], ts_base + panel_off + SWZ(r * 128 + ks * 32 + (lane >> 4) * 16));
            }
            #pragma unroll
            for (int nt = 0; nt < NT2; nt++) {
                unsigned b[2];
                int l = lane & 15;
                int r = wn * WN2 + nt * 8 + (l & 7);
                ldsm_x2(b, bs_base + SWZ(r * 128 + ks * 32 + ((l >> 3) & 1) * 16));
                mma_fp16(acc2[0][nt], a[0], b);
                mma_fp16(acc2[1][nt], a[1], b);
            }
        }
        __syncthreads();
    }

    #pragma unroll
    for (int mt = 0; mt < 2; mt++) {
        #pragma unroll
        for (int nt = 0; nt < NT2; nt++) {
            int r = row0 + wm * 32 + mt * 16 + (lane >> 2);
            int c = wn * WN2 + nt * 8 + (lane & 3) * 2;
            epi2<N2, true, false, !POOL2, POOL2, false>(r, c, acc2[mt][nt][0], acc2[mt][nt][1], b2, outh, batch);
            epi2<N2, true, false, !POOL2, POOL2, false>(r + 8, c, acc2[mt][nt][2], acc2[mt][nt][3], b2, outh, batch);
        }
    }
}

// ---------------------------------------------------------------------------
// Final tiny GEMM
// ---------------------------------------------------------------------------
__global__ void final_kernel(const float* __restrict__ pw, const float* __restrict__ pb,
                             float* __restrict__ out) {
    int tid = threadIdx.x;
    int b = tid >> 2;
    int t = tid & 3;
    float acc = pb[t];
    for (int k = 0; k < HH; k++)
        acc = fmaf(g_pooled[b * HH + k], pw[k * TT + t], acc);
    out[b * TT + t] = acc;
}

// ---------------------------------------------------------------------------
extern "C" void kernel_launch(void* const* d_in, const int* in_sizes, int n_in,
                              void* d_out, int out_size) {
    const int*   z       = (const int*)d_in[0];
    const float* pos     = (const float*)d_in[1];
    const int*   batch   = (const int*)d_in[2];
    const int*   ei      = (const int*)d_in[3];
    const float* emb     = (const float*)d_in[4];
    const float* mlp_w1  = (const float*)d_in[5];
    const float* mlp_b1  = (const float*)d_in[6];
    const float* mlp_w2  = (const float*)d_in[7];
    const float* mlp_b2  = (const float*)d_in[8];
    const float* lin1_w  = (const float*)d_in[9];
    const float* lin2_w  = (const float*)d_in[10];
    const float* lin2_b  = (const float*)d_in[11];
    const float* lin_w   = (const float*)d_in[12];
    const float* lin_b   = (const float*)d_in[13];
    const float* out1_w  = (const float*)d_in[14];
    const float* out1_b  = (const float*)d_in[15];
    const float* out2_w  = (const float*)d_in[16];
    const float* out2_b  = (const float*)d_in[17];
    const float* pred_w  = (const float*)d_in[18];
    const float* pred_b  = (const float*)d_in[19];
    float* out = (float*)d_out;

    float *p_h, *p_agg;
    void* p_xjh;
    __half* p_wt;
    cudaGetSymbolAddress((void**)&p_h, g_h);
    cudaGetSymbolAddress(&p_xjh, g_xjh);
    cudaGetSymbolAddress((void**)&p_agg, g_agg);
    cudaGetSymbolAddress((void**)&p_wt, g_wt);

    int dev = 0, smCount = 148;
    cudaGetDevice(&dev);
    cudaDeviceGetAttribute(&smCount, cudaDevAttrMultiProcessorCount, dev);

    const int TAB_SMEM = TAB * HH * (int)sizeof(__half);   // 98304
    cudaFuncSetAttribute(edge_conv_csr_kernel, cudaFuncAttributeMaxDynamicSharedMemorySize, TAB_SMEM);

    const int SM_LIN1 = 16384 + 16384;              // 32768
    const int SM_FA   = 16384 + 16384 + 32768;      // 65536 (N1=128)
    const int SM_FB   = 16384 + 16384 + 16384;      // 49152 (N1=64)
    cudaFuncSetAttribute(mma_gemm_kernel<128, 128, false, false, false, false, true>,
                         cudaFuncAttributeMaxDynamicSharedMemorySize, SM_LIN1);
    cudaFuncSetAttribute(fused2_kernel<128, 128, 128, false>,
                         cudaFuncAttributeMaxDynamicSharedMemorySize, SM_FA);
    cudaFuncSetAttribute(fused2_kernel<128, 64, 128, true>,
                         cudaFuncAttributeMaxDynamicSharedMemorySize, SM_FB);

    int gblocks = (NN + 127) / 128;

    // prep (ordered so launch index 3 is the first mma GEMM — ncu samples it)
    dim3 tg(64, 8);
    transpose_all_kernel<<<tg, 256>>>(lin1_w, lin2_w, lin_w, out1_w, out2_w, p_wt);       // 0
    prep_kernel<<<(NN * 32 + 255) / 256, 256>>>(z, emb);                                   // 1
    dim3 tb(TAB, 2);
    build_table_kernel<<<tb, HH>>>(mlp_w1, mlp_b1, mlp_w2, mlp_b2);                        // 2
    mma_gemm_kernel<128, 128, false, false, false, false, true><<<gblocks, 256, SM_LIN1>>>(
        p_h, p_wt + WT_LIN1(0), nullptr, p_xjh, nullptr);                                  // 3
    hist_kernel<<<(EE / 4 + 255) / 256, 256>>>(ei);                                        // 4
    scan1_kernel<<<NBLK, SCAN_B>>>();                                                      // 5
    scan3_kernel<<<NBLK, SCAN_B>>>();                                                      // 6
    fill_kernel<<<(EE / 4 + 255) / 256, 256>>>(ei, pos);                                   // 7

    for (int i = 0; i < 2; i++) {
        if (i > 0) {
            mma_gemm_kernel<128, 128, false, false, false, false, true><<<gblocks, 256, SM_LIN1>>>(
                p_h, p_wt + WT_LIN1(i), nullptr, p_xjh, nullptr);
        }
        edge_conv_csr_kernel<<<smCount, 1024, TAB_SMEM>>>(i);
        fused2_kernel<128, 128, 128, false><<<gblocks, 256, SM_FA>>>(
            p_agg,
            p_wt + WT_LIN2(i), lin2_b + (size_t)i * HH,
            p_wt + WT_LIN(i),  lin_b + (size_t)i * HH,
            p_h, nullptr);
    }

    fused2_kernel<128, 64, 128, true><<<gblocks, 256, SM_FB>>>(
        p_h,
        p_wt + WT_OUT1, out1_b,
        p_wt + WT_OUT2, out2_b,
        nullptr, batch);
    final_kernel<<<1, 256>>>(pred_w, pred_b, out);
}

// round 10
// speedup vs baseline: 2.8224x; 1.0952x over previous
#include <cuda_runtime.h>
#include <cuda_bf16.h>
#include <cuda_fp16.h>
#include <stdint.h>
#include <math.h>

#define NN 50000
#define EE 1600000
#define HH 128
#define BB 64
#define TT 4
#define GG 10
#define TAB 384
#define D_MAX 8.6603f
#define SCAN_B 1024
#define NBLK ((NN + SCAN_B - 1) / SCAN_B)

// scratch (static device globals — no runtime allocation)
static __device__ float g_table[2 * TAB * HH];
static __device__ float g_h[NN * HH];
static __device__ __half g_xjh[NN * HH];
static __device__ float g_agg[NN * HH];
static __device__ float g_pooled[BB * HH];
static __device__ __half g_wt[7 * 16384];   // transposed fp16 weights
// CSR (dst-major)
static __device__ int  g_deg[NN];
static __device__ int  g_ptr[NN + 1];
static __device__ int  g_work[NN];
static __device__ int  g_bsum[NBLK];
static __device__ int2 g_csr[EE];        // {src | i0<<16, half2(f,f) bits}

#define WT_LIN1(i)  ((size_t)(i) * 16384)
#define WT_LIN2(i)  ((size_t)(32768) + (size_t)(i) * 16384)
#define WT_LIN(i)   ((size_t)(65536) + (size_t)(i) * 16384)
#define WT_OUT1     ((size_t)98304)
#define WT_OUT2     ((size_t)106496)

__device__ __forceinline__ float sspf(float x) {
    float ax = fabsf(x);
    return fmaxf(x, 0.0f) + log1pf(__expf(-ax)) - 0.6931471805599453f;
}

#define SWZ(off) ((off) ^ (((off) >> 3) & 0x70))

__device__ __forceinline__ unsigned smem_u32(const void* p) {
    return (unsigned)__cvta_generic_to_shared(p);
}
__device__ __forceinline__ void ldsm_x4(unsigned* r, unsigned addr) {
    asm volatile("ldmatrix.sync.aligned.m8n8.x4.shared.b16 {%0,%1,%2,%3}, [%4];"
                 : "=r"(r[0]), "=r"(r[1]), "=r"(r[2]), "=r"(r[3]) : "r"(addr));
}
__device__ __forceinline__ void ldsm_x2(unsigned* r, unsigned addr) {
    asm volatile("ldmatrix.sync.aligned.m8n8.x2.shared.b16 {%0,%1}, [%2];"
                 : "=r"(r[0]), "=r"(r[1]) : "r"(addr));
}
__device__ __forceinline__ void mma_fp16(float* d, const unsigned* a, const unsigned* b) {
    asm volatile("mma.sync.aligned.m16n8k16.row.col.f32.f16.f16.f32 "
                 "{%0,%1,%2,%3}, {%4,%5,%6,%7}, {%8,%9}, {%0,%1,%2,%3};"
                 : "+f"(d[0]), "+f"(d[1]), "+f"(d[2]), "+f"(d[3])
                 : "r"(a[0]), "r"(a[1]), "r"(a[2]), "r"(a[3]), "r"(b[0]), "r"(b[1]));
}

// ---------------------------------------------------------------------------
// Build filter table
// ---------------------------------------------------------------------------
__global__ void build_table_kernel(const float* __restrict__ w1, const float* __restrict__ b1,
                                   const float* __restrict__ w2, const float* __restrict__ b2) {
    int row = blockIdx.x;
    int inter = blockIdx.y;
    int tid = threadIdx.x;
    float d = row * (D_MAX / (float)(TAB - 1));

    __shared__ float hid[HH];
    const float* w1i = w1 + (size_t)inter * GG * HH;
    const float* b1i = b1 + (size_t)inter * HH;
    const float* w2i = w2 + (size_t)inter * HH * HH;
    const float* b2i = b2 + (size_t)inter * HH;

    const float step = 10.0f / 9.0f;
    const float coeff = -0.5f / (step * step);

    float acc = b1i[tid];
    #pragma unroll
    for (int g = 0; g < GG; g++) {
        float diff = d - (float)g * step;
        float r = expf(coeff * diff * diff);
        acc += r * w1i[g * HH + tid];
    }
    hid[tid] = sspf(acc);
    __syncthreads();

    float acc2 = b2i[tid];
    for (int k = 0; k < HH; k++)
        acc2 = fmaf(hid[k], w2i[k * HH + tid], acc2);

    float C = 0.5f * (cosf(d * 3.14159265358979f / 10.0f) + 1.0f);
    g_table[((size_t)inter * TAB + row) * HH + tid] = acc2 * C;
}

// ---------------------------------------------------------------------------
// Merged weight transpose + fp16 convert: 8 matrices in one launch (grid.y)
// ---------------------------------------------------------------------------
__global__ void transpose_all_kernel(const float* __restrict__ lin1_w,
                                     const float* __restrict__ lin2_w,
                                     const float* __restrict__ lin_w,
                                     const float* __restrict__ out1_w,
                                     const float* __restrict__ out2_w,
                                     __half* __restrict__ wt) {
    int m = blockIdx.y;
    const float* src;
    size_t off;
    int K, N;
    switch (m) {
        case 0: src = lin1_w;          off = WT_LIN1(0); K = 128; N = 128; break;
        case 1: src = lin1_w + 16384;  off = WT_LIN1(1); K = 128; N = 128; break;
        case 2: src = lin2_w;          off = WT_LIN2(0); K = 128; N = 128; break;
        case 3: src = lin2_w + 16384;  off = WT_LIN2(1); K = 128; N = 128; break;
        case 4: src = lin_w;           off = WT_LIN(0);  K = 128; N = 128; break;
        case 5: src = lin_w + 16384;   off = WT_LIN(1);  K = 128; N = 128; break;
        case 6: src = out1_w;          off = WT_OUT1;    K = 128; N = 64;  break;
        default: src = out2_w;         off = WT_OUT2;    K = 64;  N = 128; break;
    }
    int i = blockIdx.x * blockDim.x + threadIdx.x;
    if (i >= K * N) return;
    int k = i / N, n = i % N;
    wt[off + (size_t)n * K + k] = __float2half_rn(src[i]);
}

// ---------------------------------------------------------------------------
// Fused prep: embedding gather + zero deg + zero pooled
// ---------------------------------------------------------------------------
__global__ void prep_kernel(const int* __restrict__ z, const float* __restrict__ emb) {
    int idx = blockIdx.x * blockDim.x + threadIdx.x;
    if (idx < NN * (HH / 4)) {
        int n = idx >> 5;
        int c = idx & 31;
        ((float4*)g_h)[idx] = ((const float4*)emb)[(size_t)z[n] * (HH / 4) + c];
    }
    if (idx < NN) g_deg[idx] = 0;
    if (idx < BB * HH) g_pooled[idx] = 0.f;
}

// ---------------------------------------------------------------------------
// CSR construction
// ---------------------------------------------------------------------------
__global__ void hist_kernel(const int* __restrict__ ei) {
    int i = blockIdx.x * blockDim.x + threadIdx.x;
    if (i >= EE / 4) return;
    int4 d4 = ((const int4*)(ei + EE))[i];
    atomicAdd(&g_deg[d4.x], 1);
    atomicAdd(&g_deg[d4.y], 1);
    atomicAdd(&g_deg[d4.z], 1);
    atomicAdd(&g_deg[d4.w], 1);
}

__global__ void scan1_kernel() {
    __shared__ int sm[SCAN_B];
    int idx = blockIdx.x * SCAN_B + threadIdx.x;
    int v = (idx < NN) ? g_deg[idx] : 0;
    sm[threadIdx.x] = v;
    __syncthreads();
    for (int off = SCAN_B / 2; off > 0; off >>= 1) {
        if (threadIdx.x < off) sm[threadIdx.x] += sm[threadIdx.x + off];
        __syncthreads();
    }
    if (threadIdx.x == 0) g_bsum[blockIdx.x] = sm[0];
}

__global__ void scan3_kernel() {
    __shared__ int sm[SCAN_B];
    __shared__ int blockoff;
    int idx = blockIdx.x * SCAN_B + threadIdx.x;
    int v = (idx < NN) ? g_deg[idx] : 0;
    sm[threadIdx.x] = v;
    if (threadIdx.x == 0) {
        int run = 0;
        for (int b = 0; b < blockIdx.x; b++) run += g_bsum[b];
        blockoff = run;
    }
    __syncthreads();
    for (int off = 1; off < SCAN_B; off <<= 1) {
        int add = (threadIdx.x >= off) ? sm[threadIdx.x - off] : 0;
        __syncthreads();
        sm[threadIdx.x] += add;
        __syncthreads();
    }
    if (idx < NN) {
        int excl = blockoff + sm[threadIdx.x] - v;
        g_ptr[idx] = excl;
        g_work[idx] = excl;
        if (idx == NN - 1) g_ptr[NN] = blockoff + sm[threadIdx.x];
    }
}

__global__ void fill_kernel(const int* __restrict__ ei, const float* __restrict__ pos) {
    int i = blockIdx.x * blockDim.x + threadIdx.x;
    if (i >= EE / 4) return;
    int4 s4 = ((const int4*)ei)[i];
    int4 d4 = ((const int4*)(ei + EE))[i];
    const float INV_STEP = (float)(TAB - 1) / D_MAX;
    #pragma unroll
    for (int q = 0; q < 4; q++) {
        int s = (&s4.x)[q];
        int d = (&d4.x)[q];
        float dx = pos[s * 3 + 0] - pos[d * 3 + 0];
        float dy = pos[s * 3 + 1] - pos[d * 3 + 1];
        float dz = pos[s * 3 + 2] - pos[d * 3 + 2];
        float dist = sqrtf(dx * dx + dy * dy + dz * dz);
        float t = dist * INV_STEP;
        int i0 = min((int)t, TAB - 2);
        float f = t - (float)i0;
        __half2 f2 = __float2half2_rn(f);     // pre-packed lerp weight
        int slot = atomicAdd(&g_work[d], 1);
        g_csr[slot] = make_int2(s | (i0 << 16), *(int*)&f2);
    }
}

// ---------------------------------------------------------------------------
// CSR edge aggregation (gather-only), fp16 table in smem, half2 arithmetic,
// fp32 accumulation.
// ---------------------------------------------------------------------------
#define EDGE_BODY(J) {                                                              \
    int cx  = __shfl_sync(0xffffffffu, c.x, (J));                                   \
    int cyi = __shfl_sync(0xffffffffu, c.y, (J));                                   \
    int s  = cx & 0xffff;                                                           \
    int i0 = cx >> 16;                                                              \
    __half2 f2 = *reinterpret_cast<__half2*>(&cyi);                                 \
    uint2 xw = *(const uint2*)(g_xjh + (size_t)s * HH + lane * 4);                  \
    __half2 x0 = *reinterpret_cast<__half2*>(&xw.x);                                \
    __half2 x1 = *reinterpret_cast<__half2*>(&xw.y);                                \
    const __half* t0 = tab + i0 * HH + lane * 4;                                    \
    uint2 w0w = *(const uint2*)t0;                                                  \
    uint2 w1w = *(const uint2*)(t0 + HH);                                           \
    __half2 w0a = *reinterpret_cast<__half2*>(&w0w.x);                              \
    __half2 w0b = *reinterpret_cast<__half2*>(&w0w.y);                              \
    __half2 w1a = *reinterpret_cast<__half2*>(&w1w.x);                              \
    __half2 w1b = *reinterpret_cast<__half2*>(&w1w.y);                              \
    __half2 p0 = __hmul2(__hfma2(__hsub2(w1a, w0a), f2, w0a), x0);                  \
    __half2 p1 = __hmul2(__hfma2(__hsub2(w1b, w0b), f2, w0b), x1);                  \
    float2 pf0 = __half22float2(p0);                                                \
    float2 pf1 = __half22float2(p1);                                                \
    acc.x += pf0.x; acc.y += pf0.y; acc.z += pf1.x; acc.w += pf1.y;                 \
}

__global__ void __launch_bounds__(1024) edge_conv_csr_kernel(int inter) {
    extern __shared__ __half tab[];
    const float4* src_tab = (const float4*)(g_table + (size_t)inter * TAB * HH);
    for (int i = threadIdx.x; i < TAB * HH / 8; i += 1024) {
        float4 f0 = src_tab[i * 2];
        float4 f1 = src_tab[i * 2 + 1];
        __half2 hh[4];
        hh[0] = __floats2half2_rn(f0.x, f0.y);
        hh[1] = __floats2half2_rn(f0.z, f0.w);
        hh[2] = __floats2half2_rn(f1.x, f1.y);
        hh[3] = __floats2half2_rn(f1.z, f1.w);
        ((uint4*)tab)[i] = *(uint4*)hh;
    }
    __syncthreads();

    int lane = threadIdx.x & 31;
    int gwarp = blockIdx.x * 32 + (threadIdx.x >> 5);
    int nwarp = gridDim.x * 32;

    for (int node = gwarp; node < NN; node += nwarp) {
        int beg = __ldg(&g_ptr[node]);
        int end = __ldg(&g_ptr[node + 1]);

        float4 acc = make_float4(0.f, 0.f, 0.f, 0.f);
        int base = beg;
        for (; base + 32 <= end; base += 32) {
            int2 c = __ldg(&g_csr[base + lane]);
            #pragma unroll 8
            for (int j = 0; j < 32; j++) EDGE_BODY(j);
        }
        if (base < end) {
            int k = base + lane;
            int2 c = (k < end) ? __ldg(&g_csr[k]) : make_int2(0, 0);
            int cnt = end - base;
            for (int j = 0; j < cnt; j++) EDGE_BODY(j);
        }
        *(float4*)(g_agg + (size_t)node * HH + lane * 4) = acc;
    }
}

// ---------------------------------------------------------------------------
// Pair epilogue
// ---------------------------------------------------------------------------
template <int NCOL, bool BIAS, bool ACT, bool RESID, bool POOL, bool OFP16>
__device__ __forceinline__ void epi2(int row, int col, float v0, float v1,
                                     const float* __restrict__ bias, void* outv,
                                     const int* __restrict__ batch) {
    if (row >= NN) return;
    if (BIAS) { v0 += bias[col]; v1 += bias[col + 1]; }
    if (ACT)  { v0 = sspf(v0); v1 = sspf(v1); }
    if (POOL) {
        int b = batch[row];
        float* p = g_pooled + (size_t)b * NCOL + col;
        asm volatile("red.global.add.v2.f32 [%0], {%1,%2};" :: "l"(p), "f"(v0), "f"(v1) : "memory");
    } else if (OFP16) {
        __half2 pk = __floats2half2_rn(v0, v1);
        *(unsigned*)((__half*)outv + (size_t)row * NCOL + col) = *(unsigned*)&pk;
    } else {
        float* o = (float*)outv + (size_t)row * NCOL + col;
        if (RESID) {
            float2 h = *(float2*)o;
            v0 += h.x; v1 += h.y;
        }
        *(float2*)o = make_float2(v0, v1);
    }
}

// ---------------------------------------------------------------------------
// fp16 tensor-core GEMM (single-pass) — standalone (for lin1 -> xjh)
// ---------------------------------------------------------------------------
template <int KDIM, int NCOL, bool BIAS, bool ACT, bool RESID, bool POOL, bool OFP16>
__global__ void __launch_bounds__(256, 2)
mma_gemm_kernel(const float* __restrict__ A,
                const __half* __restrict__ Wt,
                const float* __restrict__ bias, void* outv, const int* __restrict__ batch) {
    constexpr int KC = 64;
    constexpr int WN = NCOL / 2;
    constexpr int NT = WN / 8;
    constexpr int A_BYTES = 128 * KC * 2;

    extern __shared__ char dynsm[];
    char* As = dynsm;
    char* Bs = dynsm + A_BYTES;

    int tid = threadIdx.x;
    int warp = tid >> 5, lane = tid & 31;
    int wm = warp & 3, wn = warp >> 2;
    int row0 = blockIdx.x * 128;

    float acc[2][NT][4];
    #pragma unroll
    for (int mt = 0; mt < 2; mt++)
        #pragma unroll
        for (int nt = 0; nt < NT; nt++)
            #pragma unroll
            for (int q = 0; q < 4; q++) acc[mt][nt][q] = 0.f;

    unsigned as_base = smem_u32(As);
    unsigned bs_base = smem_u32(Bs);

    for (int k0 = 0; k0 < KDIM; k0 += KC) {
        #pragma unroll
        for (int i = tid; i < 128 * 8; i += 256) {
            int r = i >> 3, ch = i & 7;
            int grow = row0 + r;
            float v[8] = {0.f, 0.f, 0.f, 0.f, 0.f, 0.f, 0.f, 0.f};
            if (grow < NN) {
                const float* gp = A + (size_t)grow * KDIM + k0 + ch * 8;
                float4 f0 = *(const float4*)gp;
                float4 f1 = *(const float4*)(gp + 4);
                v[0] = f0.x; v[1] = f0.y; v[2] = f0.z; v[3] = f0.w;
                v[4] = f1.x; v[5] = f1.y; v[6] = f1.z; v[7] = f1.w;
            }
            __half2 hh[4];
            #pragma unroll
            for (int q = 0; q < 4; q++) hh[q] = __floats2half2_rn(v[2 * q], v[2 * q + 1]);
            *(uint4*)(As + SWZ(r * 128 + ch * 16)) = *(uint4*)hh;
        }
        #pragma unroll
        for (int i = tid; i < NCOL * 8; i += 256) {
            int r = i >> 3, ch = i & 7;
            uint4 w = *(const uint4*)(Wt + (size_t)r * KDIM + k0 + ch * 8);
            *(uint4*)(Bs + SWZ(r * 128 + ch * 16)) = w;
        }
        __syncthreads();

        #pragma unroll
        for (int ks = 0; ks < KC / 16; ks++) {
            unsigned a[2][4];
            #pragma unroll
            for (int mt = 0; mt < 2; mt++) {
                int r = wm * 32 + mt * 16 + (lane & 15);
                ldsm_x4(a[mt], as_base + SWZ(r * 128 + ks * 32 + (lane >> 4) * 16));
            }
            #pragma unroll
            for (int nt = 0; nt < NT; nt++) {
                unsigned b[2];
                int l = lane & 15;
                int r = wn * WN + nt * 8 + (l & 7);
                ldsm_x2(b, bs_base + SWZ(r * 128 + ks * 32 + ((l >> 3) & 1) * 16));
                mma_fp16(acc[0][nt], a[0], b);
                mma_fp16(acc[1][nt], a[1], b);
            }
        }
        __syncthreads();
    }

    #pragma unroll
    for (int mt = 0; mt < 2; mt++) {
        #pragma unroll
        for (int nt = 0; nt < NT; nt++) {
            int r = row0 + wm * 32 + mt * 16 + (lane >> 2);
            int c = wn * WN + nt * 8 + (lane & 3) * 2;
            epi2<NCOL, BIAS, ACT, RESID, POOL, OFP16>(r, c, acc[mt][nt][0], acc[mt][nt][1], bias, outv, batch);
            epi2<NCOL, BIAS, ACT, RESID, POOL, OFP16>(r + 8, c, acc[mt][nt][2], acc[mt][nt][3], bias, outv, batch);
        }
    }
}

// ---------------------------------------------------------------------------
// Fused two-GEMM chain (row-local): T = ssp(A@W1 + b1); out2 = T@W2 + b2
// ---------------------------------------------------------------------------
template <int K1, int N1, int N2, bool POOL2>
__global__ void __launch_bounds__(256, 2)
fused2_kernel(const float* __restrict__ A,
              const __half* __restrict__ W1, const float* __restrict__ b1,
              const __half* __restrict__ W2, const float* __restrict__ b2,
              float* __restrict__ outh, const int* __restrict__ batch) {
    constexpr int WN1 = N1 / 2, NT1 = WN1 / 8;
    constexpr int WN2 = N2 / 2, NT2 = WN2 / 8;
    constexpr int A_B = 128 * 64 * 2;   // 16384
    constexpr int B_B = 16384;
    constexpr int PANEL = 128 * 64 * 2; // 16384

    extern __shared__ char dynsm[];
    char* As = dynsm;
    char* Bs = dynsm + A_B;
    char* Ts = dynsm + A_B + B_B;

    int tid = threadIdx.x;
    int warp = tid >> 5, lane = tid & 31;
    int wm = warp & 3, wn = warp >> 2;
    int row0 = blockIdx.x * 128;

    unsigned as_base = smem_u32(As);
    unsigned bs_base = smem_u32(Bs);
    unsigned ts_base = smem_u32(Ts);

    // ---------------- stage 1: acc1 = A @ W1 ----------------
    float acc1[2][NT1][4];
    #pragma unroll
    for (int mt = 0; mt < 2; mt++)
        #pragma unroll
        for (int nt = 0; nt < NT1; nt++)
            #pragma unroll
            for (int q = 0; q < 4; q++) acc1[mt][nt][q] = 0.f;

    for (int k0 = 0; k0 < K1; k0 += 64) {
        #pragma unroll
        for (int i = tid; i < 128 * 8; i += 256) {
            int r = i >> 3, ch = i & 7;
            int grow = row0 + r;
            float v[8] = {0.f, 0.f, 0.f, 0.f, 0.f, 0.f, 0.f, 0.f};
            if (grow < NN) {
                const float* gp = A + (size_t)grow * K1 + k0 + ch * 8;
                float4 f0 = *(const float4*)gp;
                float4 f1 = *(const float4*)(gp + 4);
                v[0] = f0.x; v[1] = f0.y; v[2] = f0.z; v[3] = f0.w;
                v[4] = f1.x; v[5] = f1.y; v[6] = f1.z; v[7] = f1.w;
            }
            __half2 hh[4];
            #pragma unroll
            for (int q = 0; q < 4; q++) hh[q] = __floats2half2_rn(v[2 * q], v[2 * q + 1]);
            *(uint4*)(As + SWZ(r * 128 + ch * 16)) = *(uint4*)hh;
        }
        #pragma unroll
        for (int i = tid; i < N1 * 8; i += 256) {
            int r = i >> 3, ch = i & 7;
            uint4 w = *(const uint4*)(W1 + (size_t)r * K1 + k0 + ch * 8);
            *(uint4*)(Bs + SWZ(r * 128 + ch * 16)) = w;
        }
        __syncthreads();

        #pragma unroll
        for (int ks = 0; ks < 4; ks++) {
            unsigned a[2][4];
            #pragma unroll
            for (int mt = 0; mt < 2; mt++) {
                int r = wm * 32 + mt * 16 + (lane & 15);
                ldsm_x4(a[mt], as_base + SWZ(r * 128 + ks * 32 + (lane >> 4) * 16));
            }
            #pragma unroll
            for (int nt = 0; nt < NT1; nt++) {
                unsigned b[2];
                int l = lane & 15;
                int r = wn * WN1 + nt * 8 + (l & 7);
                ldsm_x2(b, bs_base + SWZ(r * 128 + ks * 32 + ((l >> 3) & 1) * 16));
                mma_fp16(acc1[0][nt], a[0], b);
                mma_fp16(acc1[1][nt], a[1], b);
            }
        }
        __syncthreads();
    }

    // epilogue 1: T = ssp(acc1 + b1) -> fp16 into Ts panels
    #pragma unroll
    for (int mt = 0; mt < 2; mt++) {
        #pragma unroll
        for (int nt = 0; nt < NT1; nt++) {
            int c = wn * WN1 + nt * 8 + (lane & 3) * 2;
            int panel_off = (c >> 6) * PANEL;
            int kk2 = (c & 63) * 2;
            #pragma unroll
            for (int half = 0; half < 2; half++) {
                int rl = wm * 32 + mt * 16 + (lane >> 2) + half * 8;
                float v0 = sspf(acc1[mt][nt][half * 2 + 0] + b1[c]);
                float v1 = sspf(acc1[mt][nt][half * 2 + 1] + b1[c + 1]);
                __half2 pk = __floats2half2_rn(v0, v1);
                *(unsigned*)(Ts + panel_off + SWZ(rl * 128 + kk2)) = *(unsigned*)&pk;
            }
        }
    }
    __syncthreads();

    // ---------------- stage 2: out = T @ W2 ----------------
    float acc2[2][NT2][4];
    #pragma unroll
    for (int mt = 0; mt < 2; mt++)
        #pragma unroll
        for (int nt = 0; nt < NT2; nt++)
            #pragma unroll
            for (int q = 0; q < 4; q++) acc2[mt][nt][q] = 0.f;

    for (int k0 = 0; k0 < N1; k0 += 64) {
        #pragma unroll
        for (int i = tid; i < N2 * 8; i += 256) {
            int r = i >> 3, ch = i & 7;
            uint4 w = *(const uint4*)(W2 + (size_t)r * N1 + k0 + ch * 8);
            *(uint4*)(Bs + SWZ(r * 128 + ch * 16)) = w;
        }
        __syncthreads();

        int panel_off = (k0 >> 6) * PANEL;
        #pragma unroll
        for (int ks = 0; ks < 4; ks++) {
            unsigned a[2][4];
            #pragma unroll
            for (int mt = 0; mt < 2; mt++) {
                int r = wm * 32 + mt * 16 + (lane & 15);
                ldsm_x4(a[mt], ts_base + panel_off + SWZ(r * 128 + ks * 32 + (lane >> 4) * 16));
            }
            #pragma unroll
            for (int nt = 0; nt < NT2; nt++) {
                unsigned b[2];
                int l = lane & 15;
                int r = wn * WN2 + nt * 8 + (l & 7);
                ldsm_x2(b, bs_base + SWZ(r * 128 + ks * 32 + ((l >> 3) & 1) * 16));
                mma_fp16(acc2[0][nt], a[0], b);
                mma_fp16(acc2[1][nt], a[1], b);
            }
        }
        __syncthreads();
    }

    #pragma unroll
    for (int mt = 0; mt < 2; mt++) {
        #pragma unroll
        for (int nt = 0; nt < NT2; nt++) {
            int r = row0 + wm * 32 + mt * 16 + (lane >> 2);
            int c = wn * WN2 + nt * 8 + (lane & 3) * 2;
            epi2<N2, true, false, !POOL2, POOL2, false>(r, c, acc2[mt][nt][0], acc2[mt][nt][1], b2, outh, batch);
            epi2<N2, true, false, !POOL2, POOL2, false>(r + 8, c, acc2[mt][nt][2], acc2[mt][nt][3], b2, outh, batch);
        }
    }
}

// ---------------------------------------------------------------------------
// Final tiny GEMM
// ---------------------------------------------------------------------------
__global__ void final_kernel(const float* __restrict__ pw, const float* __restrict__ pb,
                             float* __restrict__ out) {
    int tid = threadIdx.x;
    int b = tid >> 2;
    int t = tid & 3;
    float acc = pb[t];
    for (int k = 0; k < HH; k++)
        acc = fmaf(g_pooled[b * HH + k], pw[k * TT + t], acc);
    out[b * TT + t] = acc;
}

// ---------------------------------------------------------------------------
extern "C" void kernel_launch(void* const* d_in, const int* in_sizes, int n_in,
                              void* d_out, int out_size) {
    const int*   z       = (const int*)d_in[0];
    const float* pos     = (const float*)d_in[1];
    const int*   batch   = (const int*)d_in[2];
    const int*   ei      = (const int*)d_in[3];
    const float* emb     = (const float*)d_in[4];
    const float* mlp_w1  = (const float*)d_in[5];
    const float* mlp_b1  = (const float*)d_in[6];
    const float* mlp_w2  = (const float*)d_in[7];
    const float* mlp_b2  = (const float*)d_in[8];
    const float* lin1_w  = (const float*)d_in[9];
    const float* lin2_w  = (const float*)d_in[10];
    const float* lin2_b  = (const float*)d_in[11];
    const float* lin_w   = (const float*)d_in[12];
    const float* lin_b   = (const float*)d_in[13];
    const float* out1_w  = (const float*)d_in[14];
    const float* out1_b  = (const float*)d_in[15];
    const float* out2_w  = (const float*)d_in[16];
    const float* out2_b  = (const float*)d_in[17];
    const float* pred_w  = (const float*)d_in[18];
    const float* pred_b  = (const float*)d_in[19];
    float* out = (float*)d_out;

    float *p_h, *p_agg;
    void* p_xjh;
    __half* p_wt;
    cudaGetSymbolAddress((void**)&p_h, g_h);
    cudaGetSymbolAddress(&p_xjh, g_xjh);
    cudaGetSymbolAddress((void**)&p_agg, g_agg);
    cudaGetSymbolAddress((void**)&p_wt, g_wt);

    int dev = 0, smCount = 148;
    cudaGetDevice(&dev);
    cudaDeviceGetAttribute(&smCount, cudaDevAttrMultiProcessorCount, dev);

    const int TAB_SMEM = TAB * HH * (int)sizeof(__half);   // 98304
    cudaFuncSetAttribute(edge_conv_csr_kernel, cudaFuncAttributeMaxDynamicSharedMemorySize, TAB_SMEM);

    const int SM_LIN1 = 16384 + 16384;              // 32768
    const int SM_FA   = 16384 + 16384 + 32768;      // 65536 (N1=128)
    const int SM_FB   = 16384 + 16384 + 16384;      // 49152 (N1=64)
    cudaFuncSetAttribute(mma_gemm_kernel<128, 128, false, false, false, false, true>,
                         cudaFuncAttributeMaxDynamicSharedMemorySize, SM_LIN1);
    cudaFuncSetAttribute(fused2_kernel<128, 128, 128, false>,
                         cudaFuncAttributeMaxDynamicSharedMemorySize, SM_FA);
    cudaFuncSetAttribute(fused2_kernel<128, 64, 128, true>,
                         cudaFuncAttributeMaxDynamicSharedMemorySize, SM_FB);

    int gblocks = (NN + 127) / 128;

    // prep
    dim3 tg(64, 8);
    transpose_all_kernel<<<tg, 256>>>(lin1_w, lin2_w, lin_w, out1_w, out2_w, p_wt);
    prep_kernel<<<(NN * 32 + 255) / 256, 256>>>(z, emb);
    dim3 tb(TAB, 2);
    build_table_kernel<<<tb, HH>>>(mlp_w1, mlp_b1, mlp_w2, mlp_b2);
    mma_gemm_kernel<128, 128, false, false, false, false, true><<<gblocks, 256, SM_LIN1>>>(
        p_h, p_wt + WT_LIN1(0), nullptr, p_xjh, nullptr);
    hist_kernel<<<(EE / 4 + 255) / 256, 256>>>(ei);
    scan1_kernel<<<NBLK, SCAN_B>>>();
    scan3_kernel<<<NBLK, SCAN_B>>>();
    fill_kernel<<<(EE / 4 + 255) / 256, 256>>>(ei, pos);

    for (int i = 0; i < 2; i++) {
        if (i > 0) {
            mma_gemm_kernel<128, 128, false, false, false, false, true><<<gblocks, 256, SM_LIN1>>>(
                p_h, p_wt + WT_LIN1(i), nullptr, p_xjh, nullptr);
        }
        edge_conv_csr_kernel<<<smCount, 1024, TAB_SMEM>>>(i);
        fused2_kernel<128, 128, 128, false><<<gblocks, 256, SM_FA>>>(
            p_agg,
            p_wt + WT_LIN2(i), lin2_b + (size_t)i * HH,
            p_wt + WT_LIN(i),  lin_b + (size_t)i * HH,
            p_h, nullptr);
    }

    fused2_kernel<128, 64, 128, true><<<gblocks, 256, SM_FB>>>(
        p_h,
        p_wt + WT_OUT1, out1_b,
        p_wt + WT_OUT2, out2_b,
        nullptr, batch);
    final_kernel<<<1, 256>>>(pred_w, pred_b, out);
}